// round 11
// baseline (speedup 1.0000x reference)
#include <cuda_runtime.h>
#include <math.h>

#define Nn 10000
#define Ee 320000
#define K1H 216          // per-head K for layer-1 GEMM
#define LDA1 (4 * K1H)   // 864
#define K2P 1376

// ---------------- static scratch ----------------
__device__ int   d_src[Ee], d_dst[Ee], d_et[Ee], d_nt[Nn];
__device__ int   d_deg[Nn], d_off[Nn + 1], d_cur[Nn];
__device__ int   d_eid[Ee], d_srcS[Ee], d_etS[Ee];
__device__ float d_se1[Ee * 4], d_se2[Ee * 4];
__device__ float d_ssrc[Nn * 4], d_sdst[Nn * 4];
__device__ float d_u1[Nn * 64], d_u2[Nn * 256], d_h1[Nn * 256];
__device__ float d_v1[(size_t)Nn * LDA1], d_v2[(size_t)Nn * K2P];
__device__ float d_wsrc1[256], d_wdst1[256], d_wae1[256], d_etd1[22 * 4];
__device__ float d_wsrc2[1024], d_wdst2[1024], d_wae2[256], d_etd2[22 * 4];
__device__ float d_W1h[4 * K1H * 64], d_W2cat[K2P * 256];

typedef unsigned long long ull;

__device__ __forceinline__ float lrelu(float v) { return v > 0.f ? v : 0.2f * v; }
__device__ __forceinline__ int ldidx(const void* p, long long i, int is64) {
    return is64 ? (int)((const long long*)p)[i] : ((const int*)p)[i];
}
__device__ __forceinline__ ull dup2(float x) {
    ull r;
    asm("mov.b64 %0, {%1, %1};" : "=l"(r) : "r"(__float_as_uint(x)));
    return r;
}
__device__ __forceinline__ void fma2(ull& d, ull a, ull b) {
    asm("fma.rn.f32x2 %0, %1, %2, %0;" : "+l"(d) : "l"(a), "l"(b));
}
__device__ __forceinline__ float4 logit4(float4 ss, float4 sd, float4 se) {
    float4 l;
    l.x = lrelu(ss.x + sd.x + se.x); l.y = lrelu(ss.y + sd.y + se.y);
    l.z = lrelu(ss.z + sd.z + se.z); l.w = lrelu(ss.w + sd.w + se.w);
    return l;
}
__device__ __forceinline__ float4 warpMax4(float4 v) {
#pragma unroll
    for (int o = 16; o > 0; o >>= 1) {
        v.x = fmaxf(v.x, __shfl_xor_sync(0xffffffffu, v.x, o));
        v.y = fmaxf(v.y, __shfl_xor_sync(0xffffffffu, v.y, o));
        v.z = fmaxf(v.z, __shfl_xor_sync(0xffffffffu, v.z, o));
        v.w = fmaxf(v.w, __shfl_xor_sync(0xffffffffu, v.w, o));
    }
    return v;
}
__device__ __forceinline__ float4 warpSum4(float4 v) {
#pragma unroll
    for (int o = 16; o > 0; o >>= 1) {
        v.x += __shfl_xor_sync(0xffffffffu, v.x, o);
        v.y += __shfl_xor_sync(0xffffffffu, v.y, o);
        v.z += __shfl_xor_sync(0xffffffffu, v.z, o);
        v.w += __shfl_xor_sync(0xffffffffu, v.w, o);
    }
    return v;
}
__device__ __forceinline__ int block_is64(const unsigned int* w) {
    int t = threadIdx.x;
    int bad = 0;
    if (t < 128) bad = (w[2 * (t * 39) + 1] != 0u);
    return __syncthreads_or(bad) ? 0 : 1;
}

// ---------------- K1: fused preprocessing ----------------
#define PRE_CONV 1250
#define PRE_PW1  (PRE_CONV + 216)
#define PRE_PW2  (PRE_PW1 + 1376)
#define PRE_TOT  (PRE_PW2 + 13)

__global__ void k_pre(const void* ei, const void* ntp, const void* etp,
                      const float* W1, const float* as1, const float* ad1,
                      const float* We1, const float* ag1, const float* etb1,
                      const float* W2, const float* as2, const float* ad2,
                      const float* We2, const float* ag2, const float* etb2,
                      const float* res1) {
    int b = blockIdx.x, t = threadIdx.x;
    if (b < PRE_CONV) {
        int is64 = block_is64((const unsigned int*)ntp);
        int e = b * 256 + t;
        if (e < Ee) {
            int s = ldidx(ei, e, is64);
            int d2 = ldidx(ei, (long long)Ee + e, is64);
            d_src[e] = s; d_dst[e] = d2; d_et[e] = ldidx(etp, e, is64);
            atomicAdd(&d_deg[d2], 1);
        }
        if (b < 40) { int i = b * 256 + t; if (i < Nn) d_nt[i] = ldidx(ntp, i, is64); }
    } else if (b < PRE_PW1) {
        int j = (b - PRE_CONV) * 256 + t;
        int c = j & 63, hk = j >> 6, h = hk / K1H, k = hk - h * K1H;
        float v = 0.f;
        if (k < 64) v = W1[k * 256 + h * 64 + c];
        else if (k < 128) v = We1[(k - 64) * 256 + h * 64 + c];
        else if (k < 150) v = etb1[(k - 128) * 256 + h * 64 + c];
        else if (k < 214) v = res1[(k - 150) * 256 + h * 64 + c];
        d_W1h[j] = v;
    } else if (b < PRE_PW2) {
        int j = (b - PRE_PW1) * 256 + t;
        int col = j & 255, r = j >> 8;
        float v = 0.f;
        if (r < 1024) { int h = r >> 8, k = r & 255; v = W2[k * 1024 + h * 256 + col] * 0.25f; }
        else if (r < 1280) { int rr = r - 1024, h = rr >> 6, k = rr & 63; v = We2[k * 1024 + h * 256 + col] * 0.25f; }
        else if (r < 1368) { int rr = r - 1280, h = rr / 22, tt = rr % 22; v = etb2[tt * 1024 + h * 256 + col] * 0.25f; }
        d_W2cat[j] = v;
    } else {
        int j = (b - PRE_PW2) * 256 + t;
        if (j < 256) {
            int h = j >> 6, k = j & 63; float s = 0.f;
            for (int c = 0; c < 64; c++) s += W1[k * 256 + h * 64 + c] * as1[h * 64 + c];
            d_wsrc1[j] = s;
        } else if (j < 512) {
            int jj = j - 256, h = jj >> 6, k = jj & 63; float s = 0.f;
            for (int c = 0; c < 64; c++) s += W1[k * 256 + h * 64 + c] * ad1[h * 64 + c];
            d_wdst1[jj] = s;
        } else if (j < 768) {
            int jj = j - 512, h = jj >> 6, k = jj & 63; float s = 0.f;
            for (int c = 0; c < 64; c++) s += We1[k * 256 + h * 64 + c] * ag1[h * 64 + c];
            d_wae1[jj] = s;
        } else if (j < 856) {
            int jj = j - 768, tt = jj >> 2, h = jj & 3; float s = 0.f;
            for (int c = 0; c < 64; c++) s += etb1[tt * 256 + h * 64 + c] * ag1[h * 64 + c];
            d_etd1[jj] = s;
        } else if (j < 1880) {
            int jj = j - 856, h = jj >> 8, k = jj & 255; float s = 0.f;
            for (int c = 0; c < 256; c++) s += W2[k * 1024 + h * 256 + c] * as2[h * 256 + c];
            d_wsrc2[jj] = s;
        } else if (j < 2904) {
            int jj = j - 1880, h = jj >> 8, k = jj & 255; float s = 0.f;
            for (int c = 0; c < 256; c++) s += W2[k * 1024 + h * 256 + c] * ad2[h * 256 + c];
            d_wdst2[jj] = s;
        } else if (j < 3160) {
            int jj = j - 2904, h = jj >> 6, k = jj & 63; float s = 0.f;
            for (int c = 0; c < 256; c++) s += We2[k * 1024 + h * 256 + c] * ag2[h * 256 + c];
            d_wae2[jj] = s;
        } else if (j < 3248) {
            int jj = j - 3160, tt = jj >> 2, h = jj & 3; float s = 0.f;
            for (int c = 0; c < 256; c++) s += etb2[tt * 1024 + h * 256 + c] * ag2[h * 256 + c];
            d_etd2[jj] = s;
        }
    }
}

// ---------------- K2: scan (+ zero d_deg for replay) ----------------
__global__ void k_scan() {
    __shared__ int wsum[32];
    int t = threadIdx.x, base = t * 10, loc[10], sum = 0;
#pragma unroll
    for (int ii = 0; ii < 10; ii++) {
        int i = base + ii;
        int d = (i < Nn) ? d_deg[i] : 0;
        loc[ii] = d; sum += d;
    }
    int lane = t & 31, w = t >> 5;
    int v = sum;
#pragma unroll
    for (int o = 1; o < 32; o <<= 1) {
        int u = __shfl_up_sync(0xffffffffu, v, o);
        if (lane >= o) v += u;
    }
    if (lane == 31) wsum[w] = v;
    __syncthreads();
    if (w == 0) {
        int s = wsum[lane];
#pragma unroll
        for (int o = 1; o < 32; o <<= 1) {
            int u = __shfl_up_sync(0xffffffffu, s, o);
            if (lane >= o) s += u;
        }
        wsum[lane] = s;
    }
    __syncthreads();
    int run = v - sum + (w ? wsum[w - 1] : 0);
#pragma unroll
    for (int ii = 0; ii < 10; ii++) {
        int i = base + ii;
        if (i < Nn) { d_off[i] = run; d_cur[i] = run; d_deg[i] = 0; run += loc[ii]; }
        else if (i == Nn) d_off[Nn] = run;
    }
}

// ---------------- nscore body ----------------
__device__ __forceinline__ void nscore_one(int gw, int lane, const float* xin,
                                           const float* ntemb, int K,
                                           const float* ws, const float* wd, float* u) {
    int nt = d_nt[gw];
    float ps[4] = {0, 0, 0, 0}, pd[4] = {0, 0, 0, 0};
    for (int k = lane; k < K; k += 32) {
        float v = xin[gw * K + k] + ntemb[nt * K + k];
        u[gw * K + k] = v;
#pragma unroll
        for (int h = 0; h < 4; h++) { ps[h] += v * ws[h * K + k]; pd[h] += v * wd[h * K + k]; }
    }
#pragma unroll
    for (int h = 0; h < 4; h++)
        for (int o = 16; o > 0; o >>= 1) {
            ps[h] += __shfl_xor_sync(0xffffffffu, ps[h], o);
            pd[h] += __shfl_xor_sync(0xffffffffu, pd[h], o);
        }
    if (lane == 0)
#pragma unroll
        for (int h = 0; h < 4; h++) { d_ssrc[gw * 4 + h] = ps[h]; d_sdst[gw * 4 + h] = pd[h]; }
}

// ---------------- K3: fused scatter + nscore1 + edgescore ----------------
#define MID_SCAT 1250
#define MID_NS   (MID_SCAT + 1250)
#define MID_TOT  (MID_NS + 40000)

__global__ void k_mid(const float* __restrict__ ea, const float* __restrict__ x,
                      const float* __restrict__ nte1) {
    int b = blockIdx.x, t = threadIdx.x;
    if (b < MID_SCAT) {
        int e = b * 256 + t;
        if (e < Ee) {
            int p = atomicAdd(&d_cur[d_dst[e]], 1);
            d_eid[p] = e; d_srcS[p] = d_src[e]; d_etS[p] = d_et[e];
        }
    } else if (b < MID_NS) {
        int gw = (b - MID_SCAT) * 8 + (t >> 5);
        if (gw < Nn) nscore_one(gw, t & 31, x, nte1, 64, d_wsrc1, d_wdst1, d_u1);
    } else {
        int e = (b - MID_NS) * 8 + (t >> 5);
        int lane = t & 31;
        float a0 = ea[(size_t)e * 64 + lane];
        float a1 = ea[(size_t)e * 64 + 32 + lane];
        float dd1[4], dd2[4];
#pragma unroll
        for (int h = 0; h < 4; h++) {
            dd1[h] = a0 * d_wae1[h * 64 + lane] + a1 * d_wae1[h * 64 + 32 + lane];
            dd2[h] = a0 * d_wae2[h * 64 + lane] + a1 * d_wae2[h * 64 + 32 + lane];
            for (int o = 16; o > 0; o >>= 1) {
                dd1[h] += __shfl_xor_sync(0xffffffffu, dd1[h], o);
                dd2[h] += __shfl_xor_sync(0xffffffffu, dd2[h], o);
            }
        }
        if (lane == 0) {
            int et = d_et[e];
#pragma unroll
            for (int h = 0; h < 4; h++) {
                d_se1[e * 4 + h] = dd1[h] + d_etd1[et * 4 + h];
                d_se2[e * 4 + h] = dd2[h] + d_etd2[et * 4 + h];
            }
        }
    }
}

// ---- warp softmax stats ----
__device__ __forceinline__ void warp_softmax(const float4* se4, int beg, int end,
                                             int lane, float4 sd, float4& m, float4& rdn) {
    const float4* ssrc4 = (const float4*)d_ssrc;
    float4 mx = make_float4(-1e30f, -1e30f, -1e30f, -1e30f);
    for (int i = beg + lane; i < end; i += 32) {
        float4 l = logit4(ssrc4[d_srcS[i]], sd, se4[d_eid[i]]);
        mx.x = fmaxf(mx.x, l.x); mx.y = fmaxf(mx.y, l.y);
        mx.z = fmaxf(mx.z, l.z); mx.w = fmaxf(mx.w, l.w);
    }
    m = warpMax4(mx);
    float4 sm = make_float4(0, 0, 0, 0);
    for (int i = beg + lane; i < end; i += 32) {
        float4 l = logit4(ssrc4[d_srcS[i]], sd, se4[d_eid[i]]);
        sm.x += __expf(l.x - m.x); sm.y += __expf(l.y - m.y);
        sm.z += __expf(l.z - m.z); sm.w += __expf(l.w - m.w);
    }
    float4 den = warpSum4(sm);
    rdn.x = 1.f / (den.x + 1e-16f); rdn.y = 1.f / (den.y + 1e-16f);
    rdn.z = 1.f / (den.z + 1e-16f); rdn.w = 1.f / (den.w + 1e-16f);
}

// ---------------- K4: warp-per-node layer-1 attention (R6) ----------------
__global__ void k_attn1(const float* __restrict__ ea, const float* __restrict__ x) {
    int wid = threadIdx.x >> 5, lane = threadIdx.x & 31;
    int n = blockIdx.x * 8 + wid;
    __shared__ ull  aSh[8][32][4];
    __shared__ int2 iSh[8][32];
    __shared__ float acctSh[8][88];
    for (int i = lane; i < 88; i += 32) acctSh[wid][i] = 0.f;
    __syncwarp();
    int beg = d_off[n], end = d_off[n + 1], nE = end - beg;
    ull ax[4] = {0, 0, 0, 0}, av[4] = {0, 0, 0, 0};
    if (nE > 0) {
        const float4* ssrc4 = (const float4*)d_ssrc;
        const float4* se4 = (const float4*)d_se1;
        float4 sd = ((const float4*)d_sdst)[n];
        float4 m, rdn;
        warp_softmax(se4, beg, end, lane, sd, m, rdn);
        for (int c0 = beg; c0 < end; c0 += 32) {
            int nc = min(32, end - c0);
            if (lane < nc) {
                int i = c0 + lane;
                int s = d_srcS[i], e = d_eid[i], et = d_etS[i];
                float4 l = logit4(ssrc4[s], sd, se4[e]);
                float a0 = __expf(l.x - m.x) * rdn.x, a1 = __expf(l.y - m.y) * rdn.y;
                float a2 = __expf(l.z - m.z) * rdn.z, a3 = __expf(l.w - m.w) * rdn.w;
                aSh[wid][lane][0] = dup2(a0); aSh[wid][lane][1] = dup2(a1);
                aSh[wid][lane][2] = dup2(a2); aSh[wid][lane][3] = dup2(a3);
                iSh[wid][lane] = make_int2(s, e);
                atomicAdd(&acctSh[wid][et], a0);
                atomicAdd(&acctSh[wid][22 + et], a1);
                atomicAdd(&acctSh[wid][44 + et], a2);
                atomicAdd(&acctSh[wid][66 + et], a3);
            }
            __syncwarp();
#pragma unroll 4
            for (int j = 0; j < nc; j++) {
                ull b0 = aSh[wid][j][0], b1 = aSh[wid][j][1];
                ull b2 = aSh[wid][j][2], b3 = aSh[wid][j][3];
                int2 se = iSh[wid][j];
                ull u = *(const ull*)&d_u1[se.x * 64 + lane * 2];
                ull a = *(const ull*)&ea[(size_t)se.y * 64 + lane * 2];
                fma2(ax[0], u, b0); fma2(ax[1], u, b1);
                fma2(ax[2], u, b2); fma2(ax[3], u, b3);
                fma2(av[0], a, b0); fma2(av[1], a, b1);
                fma2(av[2], a, b2); fma2(av[3], a, b3);
            }
            __syncwarp();
        }
    }
    __syncwarp();
    float* v = &d_v1[(size_t)n * LDA1];
    int c = lane * 2;
#pragma unroll
    for (int h = 0; h < 4; h++) {
        *(ull*)&v[h * K1H + c] = ax[h];
        *(ull*)&v[h * K1H + 64 + c] = av[h];
        *(ull*)&v[h * K1H + 150 + c] = *(const ull*)&x[n * 64 + c];
    }
    for (int i = lane; i < 88; i += 32) {
        int hh = i / 22, t2 = i % 22;
        v[hh * K1H + 128 + t2] = acctSh[wid][hh * 22 + t2];
    }
    if (lane < 8) v[(lane >> 1) * K1H + 214 + (lane & 1)] = 0.f;
}

// ---------------- K6: nscore layer 2 ----------------
__global__ void k_ns2(const float* __restrict__ nte2) {
    int gw = (blockIdx.x * blockDim.x + threadIdx.x) >> 5;
    if (gw < Nn) nscore_one(gw, threadIdx.x & 31, d_h1, nte2, 256, d_wsrc2, d_wdst2, d_u2);
}

// ---------------- K7: warp-per-node layer-2 attention (R6) ----------------
__global__ void k_attn2(const float* __restrict__ ea) {
    int wid = threadIdx.x >> 5, lane = threadIdx.x & 31;
    int n = blockIdx.x * 8 + wid;
    __shared__ ull  aSh[8][32][4];
    __shared__ int2 iSh[8][32];
    __shared__ float acctSh[8][88];
    for (int i = lane; i < 88; i += 32) acctSh[wid][i] = 0.f;
    __syncwarp();
    int beg = d_off[n], end = d_off[n + 1], nE = end - beg;
    ull axu[4][4];
#pragma unroll
    for (int h = 0; h < 4; h++)
#pragma unroll
        for (int q = 0; q < 4; q++) axu[h][q] = 0ull;
    ull av[4] = {0, 0, 0, 0};
    if (nE > 0) {
        const float4* ssrc4 = (const float4*)d_ssrc;
        const float4* se4 = (const float4*)d_se2;
        float4 sd = ((const float4*)d_sdst)[n];
        float4 m, rdn;
        warp_softmax(se4, beg, end, lane, sd, m, rdn);
        for (int c0 = beg; c0 < end; c0 += 32) {
            int nc = min(32, end - c0);
            if (lane < nc) {
                int i = c0 + lane;
                int s = d_srcS[i], e = d_eid[i], et = d_etS[i];
                float4 l = logit4(ssrc4[s], sd, se4[e]);
                float a0 = __expf(l.x - m.x) * rdn.x, a1 = __expf(l.y - m.y) * rdn.y;
                float a2 = __expf(l.z - m.z) * rdn.z, a3 = __expf(l.w - m.w) * rdn.w;
                aSh[wid][lane][0] = dup2(a0); aSh[wid][lane][1] = dup2(a1);
                aSh[wid][lane][2] = dup2(a2); aSh[wid][lane][3] = dup2(a3);
                iSh[wid][lane] = make_int2(s, e);
                atomicAdd(&acctSh[wid][et], a0);
                atomicAdd(&acctSh[wid][22 + et], a1);
                atomicAdd(&acctSh[wid][44 + et], a2);
                atomicAdd(&acctSh[wid][66 + et], a3);
            }
            __syncwarp();
#pragma unroll 2
            for (int j = 0; j < nc; j++) {
                ull b0 = aSh[wid][j][0], b1 = aSh[wid][j][1];
                ull b2 = aSh[wid][j][2], b3 = aSh[wid][j][3];
                int2 se = iSh[wid][j];
                const float4* up = (const float4*)&d_u2[se.x * 256 + lane * 8];
                float4 u0 = up[0], u1 = up[1];
                ull p0 = *(ull*)&u0.x, p1 = *(ull*)&u0.z;
                ull p2 = *(ull*)&u1.x, p3 = *(ull*)&u1.z;
                fma2(axu[0][0], p0, b0); fma2(axu[0][1], p1, b0);
                fma2(axu[0][2], p2, b0); fma2(axu[0][3], p3, b0);
                fma2(axu[1][0], p0, b1); fma2(axu[1][1], p1, b1);
                fma2(axu[1][2], p2, b1); fma2(axu[1][3], p3, b1);
                fma2(axu[2][0], p0, b2); fma2(axu[2][1], p1, b2);
                fma2(axu[2][2], p2, b2); fma2(axu[2][3], p3, b2);
                fma2(axu[3][0], p0, b3); fma2(axu[3][1], p1, b3);
                fma2(axu[3][2], p2, b3); fma2(axu[3][3], p3, b3);
                ull a = *(const ull*)&ea[(size_t)se.y * 64 + lane * 2];
                fma2(av[0], a, b0); fma2(av[1], a, b1);
                fma2(av[2], a, b2); fma2(av[3], a, b3);
            }
            __syncwarp();
        }
    }
    __syncwarp();
    float* v = &d_v2[(size_t)n * K2P];
#pragma unroll
    for (int h = 0; h < 4; h++) {
#pragma unroll
        for (int q = 0; q < 4; q++)
            *(ull*)&v[h * 256 + lane * 8 + q * 2] = axu[h][q];
        *(ull*)&v[1024 + h * 64 + lane * 2] = av[h];
    }
    for (int i = lane; i < 96; i += 32)
        v[1280 + i] = (i < 88) ? acctSh[wid][i] : 0.f;
}

// ---------------- f32x2 packed SGEMM: double-buffered + pre-dup B ------------
template <int K, int MODE>
__global__ void k_gemmT(const float* __restrict__ A, const float* __restrict__ B,
                        const float* __restrict__ bias, const float* __restrict__ add,
                        float* __restrict__ C) {
    constexpr int LDA = (MODE == 1) ? LDA1 : K2P;
    constexpr int NSTEP = K / 8;
    __shared__ float As[2][8][132];
    __shared__ ull  Bsd[2][8][64];
    int y = blockIdx.y;
    int bm = blockIdx.x * 128;
    int colbase = y * 64;
    const float* Ab = A + ((MODE == 1) ? y * K1H : 0);
    const float* Bb = (MODE == 1) ? (B + y * K1H * 64) : (B + colbase);
    const int ldb = (MODE == 1) ? 64 : 256;
    int tid = threadIdx.x;
    int tx = tid & 15, ty = tid >> 4;
    int lrow = tid >> 1, lk = (tid & 1) * 4;
    int brow = tid >> 4, bcol = (tid & 15) * 4;
    int row = bm + lrow;
    ull acc[4][4];
#pragma unroll
    for (int p = 0; p < 4; p++)
#pragma unroll
        for (int j = 0; j < 4; j++) acc[p][j] = 0ull;

    // prologue: load step 0 into buffer 0
    {
        float4 avv = make_float4(0, 0, 0, 0);
        if (row < Nn) avv = *(const float4*)&Ab[(size_t)row * LDA + lk];
        As[0][lk + 0][lrow] = avv.x; As[0][lk + 1][lrow] = avv.y;
        As[0][lk + 2][lrow] = avv.z; As[0][lk + 3][lrow] = avv.w;
        if (tid < 128) {
            float4 bv = *(const float4*)&Bb[(size_t)brow * ldb + bcol];
            Bsd[0][brow][bcol + 0] = dup2(bv.x); Bsd[0][brow][bcol + 1] = dup2(bv.y);
            Bsd[0][brow][bcol + 2] = dup2(bv.z); Bsd[0][brow][bcol + 3] = dup2(bv.w);
        }
    }
    __syncthreads();

    for (int st = 0; st < NSTEP; st++) {
        int cur = st & 1, nxt = cur ^ 1;
        // issue next step's global loads into registers
        float4 avv = make_float4(0, 0, 0, 0);
        float4 bv = make_float4(0, 0, 0, 0);
        if (st + 1 < NSTEP) {
            int k0 = (st + 1) * 8;
            if (row < Nn) avv = *(const float4*)&Ab[(size_t)row * LDA + k0 + lk];
            if (tid < 128) bv = *(const float4*)&Bb[(size_t)(k0 + brow) * ldb + bcol];
        }
        // compute current step
#pragma unroll
        for (int kk = 0; kk < 8; kk++) {
            ulonglong2 a01 = *(const ulonglong2*)&As[cur][kk][ty * 8];
            ulonglong2 a23 = *(const ulonglong2*)&As[cur][kk][ty * 8 + 4];
            ulonglong2 b01 = *(const ulonglong2*)&Bsd[cur][kk][tx * 4];
            ulonglong2 b23 = *(const ulonglong2*)&Bsd[cur][kk][tx * 4 + 2];
            ull ap[4] = {a01.x, a01.y, a23.x, a23.y};
            ull bd[4] = {b01.x, b01.y, b23.x, b23.y};
#pragma unroll
            for (int p = 0; p < 4; p++)
#pragma unroll
                for (int j = 0; j < 4; j++) fma2(acc[p][j], ap[p], bd[j]);
        }
        // store next step into the other buffer
        if (st + 1 < NSTEP) {
            As[nxt][lk + 0][lrow] = avv.x; As[nxt][lk + 1][lrow] = avv.y;
            As[nxt][lk + 2][lrow] = avv.z; As[nxt][lk + 3][lrow] = avv.w;
            if (tid < 128) {
                Bsd[nxt][brow][bcol + 0] = dup2(bv.x); Bsd[nxt][brow][bcol + 1] = dup2(bv.y);
                Bsd[nxt][brow][bcol + 2] = dup2(bv.z); Bsd[nxt][brow][bcol + 3] = dup2(bv.w);
            }
        }
        __syncthreads();
    }

#pragma unroll
    for (int p = 0; p < 4; p++) {
        int r0 = bm + ty * 8 + 2 * p;
#pragma unroll
        for (int j = 0; j < 4; j++) {
            int col = colbase + tx * 4 + j;
            float lo = __uint_as_float((unsigned)(acc[p][j] & 0xffffffffull));
            float hi = __uint_as_float((unsigned)(acc[p][j] >> 32));
            float bsv = bias[col];
            if (r0 < Nn) {
                float v = lo + bsv;
                if (MODE == 1) v = fmaxf(v, 0.f);
                else v += add[r0 * 256 + col];
                C[r0 * 256 + col] = v;
            }
            if (r0 + 1 < Nn) {
                float v = hi + bsv;
                if (MODE == 1) v = fmaxf(v, 0.f);
                else v += add[(r0 + 1) * 256 + col];
                C[(r0 + 1) * 256 + col] = v;
            }
        }
    }
}

// ---------------- launch ----------------
extern "C" void kernel_launch(void* const* d_in, const int* in_sizes, int n_in,
                              void* d_out, int out_size) {
    const float* x    = (const float*)d_in[0];
    const void*  ei   = d_in[1];
    const void*  ntp  = d_in[2];
    const float* ea   = (const float*)d_in[3];
    const void*  etp  = d_in[4];
    const float* W1   = (const float*)d_in[5];
    const float* b1   = (const float*)d_in[6];
    const float* We1  = (const float*)d_in[7];
    const float* nte1 = (const float*)d_in[8];
    const float* ete1 = (const float*)d_in[9];
    const float* as1  = (const float*)d_in[10];
    const float* ad1  = (const float*)d_in[11];
    const float* ag1  = (const float*)d_in[12];
    const float* res1 = (const float*)d_in[13];
    const float* W2   = (const float*)d_in[14];
    const float* b2   = (const float*)d_in[15];
    const float* We2  = (const float*)d_in[16];
    const float* nte2 = (const float*)d_in[17];
    const float* ete2 = (const float*)d_in[18];
    const float* as2  = (const float*)d_in[19];
    const float* ad2  = (const float*)d_in[20];
    const float* ag2  = (const float*)d_in[21];
    float* out = (float*)d_out;

    k_pre<<<PRE_TOT, 256>>>(ei, ntp, etp, W1, as1, ad1, We1, ag1, ete1,
                            W2, as2, ad2, We2, ag2, ete2, res1);
    k_scan<<<1, 1024>>>();
    k_mid<<<MID_TOT, 256>>>(ea, x, nte1);
    k_attn1<<<Nn / 8, 256>>>(ea, x);

    float* h1;  cudaGetSymbolAddress((void**)&h1, d_h1);
    float* v1;  cudaGetSymbolAddress((void**)&v1, d_v1);
    float* w1h; cudaGetSymbolAddress((void**)&w1h, d_W1h);
    float* v2;  cudaGetSymbolAddress((void**)&v2, d_v2);
    float* w2c; cudaGetSymbolAddress((void**)&w2c, d_W2cat);
    dim3 g((Nn + 127) / 128, 4);
    k_gemmT<K1H, 1><<<g, 256>>>(v1, w1h, b1, nullptr, h1);
    k_ns2<<<(Nn * 32 + 255) / 256, 256>>>(nte2);
    k_attn2<<<Nn / 8, 256>>>(ea);
    k_gemmT<K2P, 2><<<g, 256>>>(v2, w2c, b2, h1, out);
}

// round 12
// speedup vs baseline: 1.4804x; 1.4804x over previous
#include <cuda_runtime.h>
#include <math.h>

#define Nn 10000
#define Ee 320000
#define K1H 216          // per-head K for layer-1 GEMM
#define LDA1 (4 * K1H)   // 864
#define K2P 1376

// ---------------- static scratch ----------------
__device__ int   d_src[Ee], d_dst[Ee], d_et[Ee], d_nt[Nn];
__device__ int   d_deg[Nn], d_off[Nn + 1], d_cur[Nn];
__device__ int   d_eid[Ee], d_srcS[Ee], d_etS[Ee];
__device__ float d_se1[Ee * 4], d_se2[Ee * 4];
__device__ float d_ssrc[Nn * 4], d_sdst[Nn * 4];
__device__ float d_u1[Nn * 64], d_u2[Nn * 256], d_h1[Nn * 256];
__device__ float d_v1[(size_t)Nn * LDA1], d_v2[(size_t)Nn * K2P];
__device__ float d_wsrc1[256], d_wdst1[256], d_wae1[256], d_etd1[22 * 4];
__device__ float d_wsrc2[1024], d_wdst2[1024], d_wae2[256], d_etd2[22 * 4];
__device__ float d_W1h[4 * K1H * 64], d_W2cat[K2P * 256];

typedef unsigned long long ull;

__device__ __forceinline__ float lrelu(float v) { return v > 0.f ? v : 0.2f * v; }
__device__ __forceinline__ int ldidx(const void* p, long long i, int is64) {
    return is64 ? (int)((const long long*)p)[i] : ((const int*)p)[i];
}
__device__ __forceinline__ ull dup2(float x) {
    ull r;
    asm("mov.b64 %0, {%1, %1};" : "=l"(r) : "r"(__float_as_uint(x)));
    return r;
}
__device__ __forceinline__ void fma2(ull& d, ull a, ull b) {
    asm("fma.rn.f32x2 %0, %1, %2, %0;" : "+l"(d) : "l"(a), "l"(b));
}
__device__ __forceinline__ unsigned to_tf32(float x) {
    unsigned r;
    asm("cvt.rna.tf32.f32 %0, %1;" : "=r"(r) : "f"(x));
    return r;
}
__device__ __forceinline__ float4 logit4(float4 ss, float4 sd, float4 se) {
    float4 l;
    l.x = lrelu(ss.x + sd.x + se.x); l.y = lrelu(ss.y + sd.y + se.y);
    l.z = lrelu(ss.z + sd.z + se.z); l.w = lrelu(ss.w + sd.w + se.w);
    return l;
}
__device__ __forceinline__ float4 warpMax4(float4 v) {
#pragma unroll
    for (int o = 16; o > 0; o >>= 1) {
        v.x = fmaxf(v.x, __shfl_xor_sync(0xffffffffu, v.x, o));
        v.y = fmaxf(v.y, __shfl_xor_sync(0xffffffffu, v.y, o));
        v.z = fmaxf(v.z, __shfl_xor_sync(0xffffffffu, v.z, o));
        v.w = fmaxf(v.w, __shfl_xor_sync(0xffffffffu, v.w, o));
    }
    return v;
}
__device__ __forceinline__ float4 warpSum4(float4 v) {
#pragma unroll
    for (int o = 16; o > 0; o >>= 1) {
        v.x += __shfl_xor_sync(0xffffffffu, v.x, o);
        v.y += __shfl_xor_sync(0xffffffffu, v.y, o);
        v.z += __shfl_xor_sync(0xffffffffu, v.z, o);
        v.w += __shfl_xor_sync(0xffffffffu, v.w, o);
    }
    return v;
}
__device__ __forceinline__ int block_is64(const unsigned int* w) {
    int t = threadIdx.x;
    int bad = 0;
    if (t < 128) bad = (w[2 * (t * 39) + 1] != 0u);
    return __syncthreads_or(bad) ? 0 : 1;
}

// ---------------- K1: fused preprocessing ----------------
#define PRE_CONV 1250
#define PRE_PW1  (PRE_CONV + 216)
#define PRE_PW2  (PRE_PW1 + 1376)
#define PRE_TOT  (PRE_PW2 + 13)

__global__ void k_pre(const void* ei, const void* ntp, const void* etp,
                      const float* W1, const float* as1, const float* ad1,
                      const float* We1, const float* ag1, const float* etb1,
                      const float* W2, const float* as2, const float* ad2,
                      const float* We2, const float* ag2, const float* etb2,
                      const float* res1) {
    int b = blockIdx.x, t = threadIdx.x;
    if (b < PRE_CONV) {
        int is64 = block_is64((const unsigned int*)ntp);
        int e = b * 256 + t;
        if (e < Ee) {
            int s = ldidx(ei, e, is64);
            int d2 = ldidx(ei, (long long)Ee + e, is64);
            d_src[e] = s; d_dst[e] = d2; d_et[e] = ldidx(etp, e, is64);
            atomicAdd(&d_deg[d2], 1);
        }
        if (b < 40) { int i = b * 256 + t; if (i < Nn) d_nt[i] = ldidx(ntp, i, is64); }
    } else if (b < PRE_PW1) {
        int j = (b - PRE_CONV) * 256 + t;
        int c = j & 63, hk = j >> 6, h = hk / K1H, k = hk - h * K1H;
        float v = 0.f;
        if (k < 64) v = W1[k * 256 + h * 64 + c];
        else if (k < 128) v = We1[(k - 64) * 256 + h * 64 + c];
        else if (k < 150) v = etb1[(k - 128) * 256 + h * 64 + c];
        else if (k < 214) v = res1[(k - 150) * 256 + h * 64 + c];
        d_W1h[j] = v;
    } else if (b < PRE_PW2) {
        int j = (b - PRE_PW1) * 256 + t;
        int col = j & 255, r = j >> 8;
        float v = 0.f;
        if (r < 1024) { int h = r >> 8, k = r & 255; v = W2[k * 1024 + h * 256 + col] * 0.25f; }
        else if (r < 1280) { int rr = r - 1024, h = rr >> 6, k = rr & 63; v = We2[k * 1024 + h * 256 + col] * 0.25f; }
        else if (r < 1368) { int rr = r - 1280, h = rr / 22, tt = rr % 22; v = etb2[tt * 1024 + h * 256 + col] * 0.25f; }
        d_W2cat[j] = v;
    } else {
        int j = (b - PRE_PW2) * 256 + t;
        if (j < 256) {
            int h = j >> 6, k = j & 63; float s = 0.f;
            for (int c = 0; c < 64; c++) s += W1[k * 256 + h * 64 + c] * as1[h * 64 + c];
            d_wsrc1[j] = s;
        } else if (j < 512) {
            int jj = j - 256, h = jj >> 6, k = jj & 63; float s = 0.f;
            for (int c = 0; c < 64; c++) s += W1[k * 256 + h * 64 + c] * ad1[h * 64 + c];
            d_wdst1[jj] = s;
        } else if (j < 768) {
            int jj = j - 512, h = jj >> 6, k = jj & 63; float s = 0.f;
            for (int c = 0; c < 64; c++) s += We1[k * 256 + h * 64 + c] * ag1[h * 64 + c];
            d_wae1[jj] = s;
        } else if (j < 856) {
            int jj = j - 768, tt = jj >> 2, h = jj & 3; float s = 0.f;
            for (int c = 0; c < 64; c++) s += etb1[tt * 256 + h * 64 + c] * ag1[h * 64 + c];
            d_etd1[jj] = s;
        } else if (j < 1880) {
            int jj = j - 856, h = jj >> 8, k = jj & 255; float s = 0.f;
            for (int c = 0; c < 256; c++) s += W2[k * 1024 + h * 256 + c] * as2[h * 256 + c];
            d_wsrc2[jj] = s;
        } else if (j < 2904) {
            int jj = j - 1880, h = jj >> 8, k = jj & 255; float s = 0.f;
            for (int c = 0; c < 256; c++) s += W2[k * 1024 + h * 256 + c] * ad2[h * 256 + c];
            d_wdst2[jj] = s;
        } else if (j < 3160) {
            int jj = j - 2904, h = jj >> 6, k = jj & 63; float s = 0.f;
            for (int c = 0; c < 256; c++) s += We2[k * 1024 + h * 256 + c] * ag2[h * 256 + c];
            d_wae2[jj] = s;
        } else if (j < 3248) {
            int jj = j - 3160, tt = jj >> 2, h = jj & 3; float s = 0.f;
            for (int c = 0; c < 256; c++) s += etb2[tt * 1024 + h * 256 + c] * ag2[h * 256 + c];
            d_etd2[jj] = s;
        }
    }
}

// ---------------- K2: scan (+ zero d_deg for replay) ----------------
__global__ void k_scan() {
    __shared__ int wsum[32];
    int t = threadIdx.x, base = t * 10, loc[10], sum = 0;
#pragma unroll
    for (int ii = 0; ii < 10; ii++) {
        int i = base + ii;
        int d = (i < Nn) ? d_deg[i] : 0;
        loc[ii] = d; sum += d;
    }
    int lane = t & 31, w = t >> 5;
    int v = sum;
#pragma unroll
    for (int o = 1; o < 32; o <<= 1) {
        int u = __shfl_up_sync(0xffffffffu, v, o);
        if (lane >= o) v += u;
    }
    if (lane == 31) wsum[w] = v;
    __syncthreads();
    if (w == 0) {
        int s = wsum[lane];
#pragma unroll
        for (int o = 1; o < 32; o <<= 1) {
            int u = __shfl_up_sync(0xffffffffu, s, o);
            if (lane >= o) s += u;
        }
        wsum[lane] = s;
    }
    __syncthreads();
    int run = v - sum + (w ? wsum[w - 1] : 0);
#pragma unroll
    for (int ii = 0; ii < 10; ii++) {
        int i = base + ii;
        if (i < Nn) { d_off[i] = run; d_cur[i] = run; d_deg[i] = 0; run += loc[ii]; }
        else if (i == Nn) d_off[Nn] = run;
    }
}

// ---------------- nscore body ----------------
__device__ __forceinline__ void nscore_one(int gw, int lane, const float* xin,
                                           const float* ntemb, int K,
                                           const float* ws, const float* wd, float* u) {
    int nt = d_nt[gw];
    float ps[4] = {0, 0, 0, 0}, pd[4] = {0, 0, 0, 0};
    for (int k = lane; k < K; k += 32) {
        float v = xin[gw * K + k] + ntemb[nt * K + k];
        u[gw * K + k] = v;
#pragma unroll
        for (int h = 0; h < 4; h++) { ps[h] += v * ws[h * K + k]; pd[h] += v * wd[h * K + k]; }
    }
#pragma unroll
    for (int h = 0; h < 4; h++)
        for (int o = 16; o > 0; o >>= 1) {
            ps[h] += __shfl_xor_sync(0xffffffffu, ps[h], o);
            pd[h] += __shfl_xor_sync(0xffffffffu, pd[h], o);
        }
    if (lane == 0)
#pragma unroll
        for (int h = 0; h < 4; h++) { d_ssrc[gw * 4 + h] = ps[h]; d_sdst[gw * 4 + h] = pd[h]; }
}

// ---------------- K3: fused scatter + nscore1 + edgescore ----------------
#define MID_SCAT 1250
#define MID_NS   (MID_SCAT + 1250)
#define MID_TOT  (MID_NS + 40000)

__global__ void k_mid(const float* __restrict__ ea, const float* __restrict__ x,
                      const float* __restrict__ nte1) {
    int b = blockIdx.x, t = threadIdx.x;
    if (b < MID_SCAT) {
        int e = b * 256 + t;
        if (e < Ee) {
            int p = atomicAdd(&d_cur[d_dst[e]], 1);
            d_eid[p] = e; d_srcS[p] = d_src[e]; d_etS[p] = d_et[e];
        }
    } else if (b < MID_NS) {
        int gw = (b - MID_SCAT) * 8 + (t >> 5);
        if (gw < Nn) nscore_one(gw, t & 31, x, nte1, 64, d_wsrc1, d_wdst1, d_u1);
    } else {
        int e = (b - MID_NS) * 8 + (t >> 5);
        int lane = t & 31;
        float a0 = ea[(size_t)e * 64 + lane];
        float a1 = ea[(size_t)e * 64 + 32 + lane];
        float dd1[4], dd2[4];
#pragma unroll
        for (int h = 0; h < 4; h++) {
            dd1[h] = a0 * d_wae1[h * 64 + lane] + a1 * d_wae1[h * 64 + 32 + lane];
            dd2[h] = a0 * d_wae2[h * 64 + lane] + a1 * d_wae2[h * 64 + 32 + lane];
            for (int o = 16; o > 0; o >>= 1) {
                dd1[h] += __shfl_xor_sync(0xffffffffu, dd1[h], o);
                dd2[h] += __shfl_xor_sync(0xffffffffu, dd2[h], o);
            }
        }
        if (lane == 0) {
            int et = d_et[e];
#pragma unroll
            for (int h = 0; h < 4; h++) {
                d_se1[e * 4 + h] = dd1[h] + d_etd1[et * 4 + h];
                d_se2[e * 4 + h] = dd2[h] + d_etd2[et * 4 + h];
            }
        }
    }
}

// ---- warp softmax stats ----
__device__ __forceinline__ void warp_softmax(const float4* se4, int beg, int end,
                                             int lane, float4 sd, float4& m, float4& rdn) {
    const float4* ssrc4 = (const float4*)d_ssrc;
    float4 mx = make_float4(-1e30f, -1e30f, -1e30f, -1e30f);
    for (int i = beg + lane; i < end; i += 32) {
        float4 l = logit4(ssrc4[d_srcS[i]], sd, se4[d_eid[i]]);
        mx.x = fmaxf(mx.x, l.x); mx.y = fmaxf(mx.y, l.y);
        mx.z = fmaxf(mx.z, l.z); mx.w = fmaxf(mx.w, l.w);
    }
    m = warpMax4(mx);
    float4 sm = make_float4(0, 0, 0, 0);
    for (int i = beg + lane; i < end; i += 32) {
        float4 l = logit4(ssrc4[d_srcS[i]], sd, se4[d_eid[i]]);
        sm.x += __expf(l.x - m.x); sm.y += __expf(l.y - m.y);
        sm.z += __expf(l.z - m.z); sm.w += __expf(l.w - m.w);
    }
    float4 den = warpSum4(sm);
    rdn.x = 1.f / (den.x + 1e-16f); rdn.y = 1.f / (den.y + 1e-16f);
    rdn.z = 1.f / (den.z + 1e-16f); rdn.w = 1.f / (den.w + 1e-16f);
}

// ---------------- K4: warp-per-node layer-1 attention (R6) ----------------
__global__ void k_attn1(const float* __restrict__ ea, const float* __restrict__ x) {
    int wid = threadIdx.x >> 5, lane = threadIdx.x & 31;
    int n = blockIdx.x * 8 + wid;
    __shared__ ull  aSh[8][32][4];
    __shared__ int2 iSh[8][32];
    __shared__ float acctSh[8][88];
    for (int i = lane; i < 88; i += 32) acctSh[wid][i] = 0.f;
    __syncwarp();
    int beg = d_off[n], end = d_off[n + 1], nE = end - beg;
    ull ax[4] = {0, 0, 0, 0}, av[4] = {0, 0, 0, 0};
    if (nE > 0) {
        const float4* ssrc4 = (const float4*)d_ssrc;
        const float4* se4 = (const float4*)d_se1;
        float4 sd = ((const float4*)d_sdst)[n];
        float4 m, rdn;
        warp_softmax(se4, beg, end, lane, sd, m, rdn);
        for (int c0 = beg; c0 < end; c0 += 32) {
            int nc = min(32, end - c0);
            if (lane < nc) {
                int i = c0 + lane;
                int s = d_srcS[i], e = d_eid[i], et = d_etS[i];
                float4 l = logit4(ssrc4[s], sd, se4[e]);
                float a0 = __expf(l.x - m.x) * rdn.x, a1 = __expf(l.y - m.y) * rdn.y;
                float a2 = __expf(l.z - m.z) * rdn.z, a3 = __expf(l.w - m.w) * rdn.w;
                aSh[wid][lane][0] = dup2(a0); aSh[wid][lane][1] = dup2(a1);
                aSh[wid][lane][2] = dup2(a2); aSh[wid][lane][3] = dup2(a3);
                iSh[wid][lane] = make_int2(s, e);
                atomicAdd(&acctSh[wid][et], a0);
                atomicAdd(&acctSh[wid][22 + et], a1);
                atomicAdd(&acctSh[wid][44 + et], a2);
                atomicAdd(&acctSh[wid][66 + et], a3);
            }
            __syncwarp();
#pragma unroll 4
            for (int j = 0; j < nc; j++) {
                ull b0 = aSh[wid][j][0], b1 = aSh[wid][j][1];
                ull b2 = aSh[wid][j][2], b3 = aSh[wid][j][3];
                int2 se = iSh[wid][j];
                ull u = *(const ull*)&d_u1[se.x * 64 + lane * 2];
                ull a = *(const ull*)&ea[(size_t)se.y * 64 + lane * 2];
                fma2(ax[0], u, b0); fma2(ax[1], u, b1);
                fma2(ax[2], u, b2); fma2(ax[3], u, b3);
                fma2(av[0], a, b0); fma2(av[1], a, b1);
                fma2(av[2], a, b2); fma2(av[3], a, b3);
            }
            __syncwarp();
        }
    }
    __syncwarp();
    float* v = &d_v1[(size_t)n * LDA1];
    int c = lane * 2;
#pragma unroll
    for (int h = 0; h < 4; h++) {
        *(ull*)&v[h * K1H + c] = ax[h];
        *(ull*)&v[h * K1H + 64 + c] = av[h];
        *(ull*)&v[h * K1H + 150 + c] = *(const ull*)&x[n * 64 + c];
    }
    for (int i = lane; i < 88; i += 32) {
        int hh = i / 22, t2 = i % 22;
        v[hh * K1H + 128 + t2] = acctSh[wid][hh * 22 + t2];
    }
    if (lane < 8) v[(lane >> 1) * K1H + 214 + (lane & 1)] = 0.f;
}

// ---------------- K6: nscore layer 2 ----------------
__global__ void k_ns2(const float* __restrict__ nte2) {
    int gw = (blockIdx.x * blockDim.x + threadIdx.x) >> 5;
    if (gw < Nn) nscore_one(gw, threadIdx.x & 31, d_h1, nte2, 256, d_wsrc2, d_wdst2, d_u2);
}

// ---------------- K7: warp-per-node layer-2 attention (R6) ----------------
__global__ void k_attn2(const float* __restrict__ ea) {
    int wid = threadIdx.x >> 5, lane = threadIdx.x & 31;
    int n = blockIdx.x * 8 + wid;
    __shared__ ull  aSh[8][32][4];
    __shared__ int2 iSh[8][32];
    __shared__ float acctSh[8][88];
    for (int i = lane; i < 88; i += 32) acctSh[wid][i] = 0.f;
    __syncwarp();
    int beg = d_off[n], end = d_off[n + 1], nE = end - beg;
    ull axu[4][4];
#pragma unroll
    for (int h = 0; h < 4; h++)
#pragma unroll
        for (int q = 0; q < 4; q++) axu[h][q] = 0ull;
    ull av[4] = {0, 0, 0, 0};
    if (nE > 0) {
        const float4* ssrc4 = (const float4*)d_ssrc;
        const float4* se4 = (const float4*)d_se2;
        float4 sd = ((const float4*)d_sdst)[n];
        float4 m, rdn;
        warp_softmax(se4, beg, end, lane, sd, m, rdn);
        for (int c0 = beg; c0 < end; c0 += 32) {
            int nc = min(32, end - c0);
            if (lane < nc) {
                int i = c0 + lane;
                int s = d_srcS[i], e = d_eid[i], et = d_etS[i];
                float4 l = logit4(ssrc4[s], sd, se4[e]);
                float a0 = __expf(l.x - m.x) * rdn.x, a1 = __expf(l.y - m.y) * rdn.y;
                float a2 = __expf(l.z - m.z) * rdn.z, a3 = __expf(l.w - m.w) * rdn.w;
                aSh[wid][lane][0] = dup2(a0); aSh[wid][lane][1] = dup2(a1);
                aSh[wid][lane][2] = dup2(a2); aSh[wid][lane][3] = dup2(a3);
                iSh[wid][lane] = make_int2(s, e);
                atomicAdd(&acctSh[wid][et], a0);
                atomicAdd(&acctSh[wid][22 + et], a1);
                atomicAdd(&acctSh[wid][44 + et], a2);
                atomicAdd(&acctSh[wid][66 + et], a3);
            }
            __syncwarp();
#pragma unroll 2
            for (int j = 0; j < nc; j++) {
                ull b0 = aSh[wid][j][0], b1 = aSh[wid][j][1];
                ull b2 = aSh[wid][j][2], b3 = aSh[wid][j][3];
                int2 se = iSh[wid][j];
                const float4* up = (const float4*)&d_u2[se.x * 256 + lane * 8];
                float4 u0 = up[0], u1 = up[1];
                ull p0 = *(ull*)&u0.x, p1 = *(ull*)&u0.z;
                ull p2 = *(ull*)&u1.x, p3 = *(ull*)&u1.z;
                fma2(axu[0][0], p0, b0); fma2(axu[0][1], p1, b0);
                fma2(axu[0][2], p2, b0); fma2(axu[0][3], p3, b0);
                fma2(axu[1][0], p0, b1); fma2(axu[1][1], p1, b1);
                fma2(axu[1][2], p2, b1); fma2(axu[1][3], p3, b1);
                fma2(axu[2][0], p0, b2); fma2(axu[2][1], p1, b2);
                fma2(axu[2][2], p2, b2); fma2(axu[2][3], p3, b2);
                fma2(axu[3][0], p0, b3); fma2(axu[3][1], p1, b3);
                fma2(axu[3][2], p2, b3); fma2(axu[3][3], p3, b3);
                ull a = *(const ull*)&ea[(size_t)se.y * 64 + lane * 2];
                fma2(av[0], a, b0); fma2(av[1], a, b1);
                fma2(av[2], a, b2); fma2(av[3], a, b3);
            }
            __syncwarp();
        }
    }
    __syncwarp();
    float* v = &d_v2[(size_t)n * K2P];
#pragma unroll
    for (int h = 0; h < 4; h++) {
#pragma unroll
        for (int q = 0; q < 4; q++)
            *(ull*)&v[h * 256 + lane * 8 + q * 2] = axu[h][q];
        *(ull*)&v[1024 + h * 64 + lane * 2] = av[h];
    }
    for (int i = lane; i < 96; i += 32)
        v[1280 + i] = (i < 88) ? acctSh[wid][i] : 0.f;
}

// ---------------- gemm1: f32x2 SGEMM per-head (exact R6) ----------------
__global__ void k_gemm1(const float* __restrict__ A, const float* __restrict__ B,
                        const float* __restrict__ bias, float* __restrict__ C) {
    __shared__ float As[8][132];
    __shared__ float Bs[8][64];
    int y = blockIdx.y;
    int bm = blockIdx.x * 128;
    int colbase = y * 64;
    const float* Ab = A + y * K1H;
    const float* Bb = B + y * K1H * 64;
    int tid = threadIdx.x;
    int tx = tid & 15, ty = tid >> 4;
    int lrow = tid >> 1, lk = (tid & 1) * 4;
    int brow = tid >> 4, bcol = (tid & 15) * 4;
    ull acc[4][4];
#pragma unroll
    for (int p = 0; p < 4; p++)
#pragma unroll
        for (int j = 0; j < 4; j++) acc[p][j] = 0ull;
    for (int k0 = 0; k0 < K1H; k0 += 8) {
        float4 avv = make_float4(0, 0, 0, 0);
        int row = bm + lrow;
        if (row < Nn) avv = *(const float4*)&Ab[(size_t)row * LDA1 + k0 + lk];
        As[lk + 0][lrow] = avv.x; As[lk + 1][lrow] = avv.y;
        As[lk + 2][lrow] = avv.z; As[lk + 3][lrow] = avv.w;
        if (tid < 128) {
            float4 bv = *(const float4*)&Bb[(size_t)(k0 + brow) * 64 + bcol];
            *(float4*)&Bs[brow][bcol] = bv;
        }
        __syncthreads();
#pragma unroll
        for (int kk = 0; kk < 8; kk++) {
            ulonglong2 a01 = *(const ulonglong2*)&As[kk][ty * 8];
            ulonglong2 a23 = *(const ulonglong2*)&As[kk][ty * 8 + 4];
            float4 bv = *(const float4*)&Bs[kk][tx * 4];
            ull ap[4] = {a01.x, a01.y, a23.x, a23.y};
            ull bd[4] = {dup2(bv.x), dup2(bv.y), dup2(bv.z), dup2(bv.w)};
#pragma unroll
            for (int p = 0; p < 4; p++)
#pragma unroll
                for (int j = 0; j < 4; j++) fma2(acc[p][j], ap[p], bd[j]);
        }
        __syncthreads();
    }
#pragma unroll
    for (int p = 0; p < 4; p++) {
        int r0 = bm + ty * 8 + 2 * p;
#pragma unroll
        for (int j = 0; j < 4; j++) {
            int col = colbase + tx * 4 + j;
            float lo = __uint_as_float((unsigned)(acc[p][j] & 0xffffffffull));
            float hi = __uint_as_float((unsigned)(acc[p][j] >> 32));
            float bsv = bias[col];
            if (r0 < Nn) C[r0 * 256 + col] = fmaxf(lo + bsv, 0.f);
            if (r0 + 1 < Nn) C[(r0 + 1) * 256 + col] = fmaxf(hi + bsv, 0.f);
        }
    }
}

// ---------------- gemm2: tf32 mma.sync m16n8k8, 128x64 tile ----------------
__global__ void k_gemm2(const float* __restrict__ A, const float* __restrict__ B,
                        const float* __restrict__ bias, const float* __restrict__ add,
                        float* __restrict__ C) {
    __shared__ unsigned As[8][136];   // [k][row] tf32 bits (136: k-stride mod 32 == 8)
    __shared__ unsigned Bs[8][72];    // [k][n]  tf32 bits
    int bm = blockIdx.x * 128;
    int colbase = blockIdx.y * 64;
    const float* Bb = B + colbase;
    int tid = threadIdx.x;
    int warp = tid >> 5, lane = tid & 31;
    int g = lane >> 2, tig = lane & 3;
    int lrow = tid & 127, lk = (tid >> 7) * 4;   // A staging: conflict-free STS
    int brow = tid >> 4, bcol = (tid & 15) * 4;  // B staging (tid < 128)
    int row = bm + lrow;
    float acc[8][4];
#pragma unroll
    for (int nt = 0; nt < 8; nt++)
#pragma unroll
        for (int j = 0; j < 4; j++) acc[nt][j] = 0.f;

    for (int k0 = 0; k0 < K2P; k0 += 8) {
        float4 avv = make_float4(0, 0, 0, 0);
        if (row < Nn) avv = *(const float4*)&A[(size_t)row * K2P + k0 + lk];
        As[lk + 0][lrow] = to_tf32(avv.x);
        As[lk + 1][lrow] = to_tf32(avv.y);
        As[lk + 2][lrow] = to_tf32(avv.z);
        As[lk + 3][lrow] = to_tf32(avv.w);
        if (tid < 128) {
            float4 bv = *(const float4*)&Bb[(size_t)(k0 + brow) * 256 + bcol];
            Bs[brow][bcol + 0] = to_tf32(bv.x);
            Bs[brow][bcol + 1] = to_tf32(bv.y);
            Bs[brow][bcol + 2] = to_tf32(bv.z);
            Bs[brow][bcol + 3] = to_tf32(bv.w);
        }
        __syncthreads();
        unsigned a0 = As[tig][warp * 16 + g];
        unsigned a1 = As[tig][warp * 16 + g + 8];
        unsigned a2 = As[tig + 4][warp * 16 + g];
        unsigned a3 = As[tig + 4][warp * 16 + g + 8];
#pragma unroll
        for (int nt = 0; nt < 8; nt++) {
            unsigned b0 = Bs[tig][nt * 8 + g];
            unsigned b1 = Bs[tig + 4][nt * 8 + g];
            asm volatile(
                "mma.sync.aligned.m16n8k8.row.col.f32.tf32.tf32.f32 "
                "{%0,%1,%2,%3}, {%4,%5,%6,%7}, {%8,%9}, {%0,%1,%2,%3};"
                : "+f"(acc[nt][0]), "+f"(acc[nt][1]), "+f"(acc[nt][2]), "+f"(acc[nt][3])
                : "r"(a0), "r"(a1), "r"(a2), "r"(a3), "r"(b0), "r"(b1));
        }
        __syncthreads();
    }
    // epilogue: c0:(g,2tig) c1:(g,2tig+1) c2:(g+8,2tig) c3:(g+8,2tig+1)
#pragma unroll
    for (int nt = 0; nt < 8; nt++) {
        int r0 = bm + warp * 16 + g, r1 = r0 + 8;
        int cA = colbase + nt * 8 + 2 * tig, cB = cA + 1;
        if (r0 < Nn) {
            C[r0 * 256 + cA] = acc[nt][0] + bias[cA] + add[r0 * 256 + cA];
            C[r0 * 256 + cB] = acc[nt][1] + bias[cB] + add[r0 * 256 + cB];
        }
        if (r1 < Nn) {
            C[r1 * 256 + cA] = acc[nt][2] + bias[cA] + add[r1 * 256 + cA];
            C[r1 * 256 + cB] = acc[nt][3] + bias[cB] + add[r1 * 256 + cB];
        }
    }
}

// ---------------- launch ----------------
extern "C" void kernel_launch(void* const* d_in, const int* in_sizes, int n_in,
                              void* d_out, int out_size) {
    const float* x    = (const float*)d_in[0];
    const void*  ei   = d_in[1];
    const void*  ntp  = d_in[2];
    const float* ea   = (const float*)d_in[3];
    const void*  etp  = d_in[4];
    const float* W1   = (const float*)d_in[5];
    const float* b1   = (const float*)d_in[6];
    const float* We1  = (const float*)d_in[7];
    const float* nte1 = (const float*)d_in[8];
    const float* ete1 = (const float*)d_in[9];
    const float* as1  = (const float*)d_in[10];
    const float* ad1  = (const float*)d_in[11];
    const float* ag1  = (const float*)d_in[12];
    const float* res1 = (const float*)d_in[13];
    const float* W2   = (const float*)d_in[14];
    const float* b2   = (const float*)d_in[15];
    const float* We2  = (const float*)d_in[16];
    const float* nte2 = (const float*)d_in[17];
    const float* ete2 = (const float*)d_in[18];
    const float* as2  = (const float*)d_in[19];
    const float* ad2  = (const float*)d_in[20];
    const float* ag2  = (const float*)d_in[21];
    float* out = (float*)d_out;

    k_pre<<<PRE_TOT, 256>>>(ei, ntp, etp, W1, as1, ad1, We1, ag1, ete1,
                            W2, as2, ad2, We2, ag2, ete2, res1);
    k_scan<<<1, 1024>>>();
    k_mid<<<MID_TOT, 256>>>(ea, x, nte1);
    k_attn1<<<Nn / 8, 256>>>(ea, x);

    float* h1;  cudaGetSymbolAddress((void**)&h1, d_h1);
    float* v1;  cudaGetSymbolAddress((void**)&v1, d_v1);
    float* w1h; cudaGetSymbolAddress((void**)&w1h, d_W1h);
    float* v2;  cudaGetSymbolAddress((void**)&v2, d_v2);
    float* w2c; cudaGetSymbolAddress((void**)&w2c, d_W2cat);
    {
        dim3 g1((Nn + 127) / 128, 4);
        k_gemm1<<<g1, 256>>>(v1, w1h, b1, h1);
    }
    k_ns2<<<(Nn * 32 + 255) / 256, 256>>>(nte2);
    k_attn2<<<Nn / 8, 256>>>(ea);
    {
        dim3 g2((Nn + 127) / 128, 4);
        k_gemm2<<<g2, 256>>>(v2, w2c, b2, h1, out);
    }
}

// round 13
// speedup vs baseline: 1.4981x; 1.0119x over previous
#include <cuda_runtime.h>
#include <math.h>

#define Nn 10000
#define Ee 320000
#define K1H 216          // per-head K for layer-1 GEMM
#define LDA1 (4 * K1H)   // 864
#define K2P 1376

// ---------------- static scratch ----------------
__device__ int   d_src[Ee], d_dst[Ee], d_et[Ee], d_nt[Nn];
__device__ int   d_deg[Nn], d_off[Nn + 1], d_cur[Nn];
__device__ int   d_eid[Ee], d_srcS[Ee], d_etS[Ee];
__device__ float d_se1[Ee * 4], d_se2[Ee * 4];
__device__ float d_ssrc[Nn * 4], d_sdst[Nn * 4];
__device__ float d_u1[Nn * 64], d_u2[Nn * 256], d_h1[Nn * 256];
__device__ float d_v1[(size_t)Nn * LDA1], d_v2[(size_t)Nn * K2P];
__device__ float d_wsrc1[256], d_wdst1[256], d_wae1[256], d_etd1[22 * 4];
__device__ float d_wsrc2[1024], d_wdst2[1024], d_wae2[256], d_etd2[22 * 4];
__device__ float d_W1h[4 * K1H * 64], d_W2cat[K2P * 256];

typedef unsigned long long ull;

__device__ __forceinline__ float lrelu(float v) { return v > 0.f ? v : 0.2f * v; }
__device__ __forceinline__ int ldidx(const void* p, long long i, int is64) {
    return is64 ? (int)((const long long*)p)[i] : ((const int*)p)[i];
}
__device__ __forceinline__ ull dup2(float x) {
    ull r;
    asm("mov.b64 %0, {%1, %1};" : "=l"(r) : "r"(__float_as_uint(x)));
    return r;
}
__device__ __forceinline__ void fma2(ull& d, ull a, ull b) {
    asm("fma.rn.f32x2 %0, %1, %2, %0;" : "+l"(d) : "l"(a), "l"(b));
}
__device__ __forceinline__ unsigned to_tf32(float x) {
    unsigned r;
    asm("cvt.rna.tf32.f32 %0, %1;" : "=r"(r) : "f"(x));
    return r;
}
__device__ __forceinline__ float4 logit4(float4 ss, float4 sd, float4 se) {
    float4 l;
    l.x = lrelu(ss.x + sd.x + se.x); l.y = lrelu(ss.y + sd.y + se.y);
    l.z = lrelu(ss.z + sd.z + se.z); l.w = lrelu(ss.w + sd.w + se.w);
    return l;
}
__device__ __forceinline__ float4 warpMax4(float4 v) {
#pragma unroll
    for (int o = 16; o > 0; o >>= 1) {
        v.x = fmaxf(v.x, __shfl_xor_sync(0xffffffffu, v.x, o));
        v.y = fmaxf(v.y, __shfl_xor_sync(0xffffffffu, v.y, o));
        v.z = fmaxf(v.z, __shfl_xor_sync(0xffffffffu, v.z, o));
        v.w = fmaxf(v.w, __shfl_xor_sync(0xffffffffu, v.w, o));
    }
    return v;
}
__device__ __forceinline__ float4 warpSum4(float4 v) {
#pragma unroll
    for (int o = 16; o > 0; o >>= 1) {
        v.x += __shfl_xor_sync(0xffffffffu, v.x, o);
        v.y += __shfl_xor_sync(0xffffffffu, v.y, o);
        v.z += __shfl_xor_sync(0xffffffffu, v.z, o);
        v.w += __shfl_xor_sync(0xffffffffu, v.w, o);
    }
    return v;
}
__device__ __forceinline__ int block_is64(const unsigned int* w) {
    int t = threadIdx.x;
    int bad = 0;
    if (t < 128) bad = (w[2 * (t * 39) + 1] != 0u);
    return __syncthreads_or(bad) ? 0 : 1;
}

// ---------------- K1: fused preprocessing ----------------
#define PRE_CONV 1250
#define PRE_PW1  (PRE_CONV + 216)
#define PRE_PW2  (PRE_PW1 + 1376)
#define PRE_TOT  (PRE_PW2 + 13)

__global__ void k_pre(const void* ei, const void* ntp, const void* etp,
                      const float* W1, const float* as1, const float* ad1,
                      const float* We1, const float* ag1, const float* etb1,
                      const float* W2, const float* as2, const float* ad2,
                      const float* We2, const float* ag2, const float* etb2,
                      const float* res1) {
    int b = blockIdx.x, t = threadIdx.x;
    if (b < PRE_CONV) {
        int is64 = block_is64((const unsigned int*)ntp);
        int e = b * 256 + t;
        if (e < Ee) {
            int s = ldidx(ei, e, is64);
            int d2 = ldidx(ei, (long long)Ee + e, is64);
            d_src[e] = s; d_dst[e] = d2; d_et[e] = ldidx(etp, e, is64);
            atomicAdd(&d_deg[d2], 1);
        }
        if (b < 40) { int i = b * 256 + t; if (i < Nn) d_nt[i] = ldidx(ntp, i, is64); }
    } else if (b < PRE_PW1) {
        int j = (b - PRE_CONV) * 256 + t;
        int c = j & 63, hk = j >> 6, h = hk / K1H, k = hk - h * K1H;
        float v = 0.f;
        if (k < 64) v = W1[k * 256 + h * 64 + c];
        else if (k < 128) v = We1[(k - 64) * 256 + h * 64 + c];
        else if (k < 150) v = etb1[(k - 128) * 256 + h * 64 + c];
        else if (k < 214) v = res1[(k - 150) * 256 + h * 64 + c];
        d_W1h[j] = v;
    } else if (b < PRE_PW2) {
        int j = (b - PRE_PW1) * 256 + t;
        int col = j & 255, r = j >> 8;
        float v = 0.f;
        if (r < 1024) { int h = r >> 8, k = r & 255; v = W2[k * 1024 + h * 256 + col] * 0.25f; }
        else if (r < 1280) { int rr = r - 1024, h = rr >> 6, k = rr & 63; v = We2[k * 1024 + h * 256 + col] * 0.25f; }
        else if (r < 1368) { int rr = r - 1280, h = rr / 22, tt = rr % 22; v = etb2[tt * 1024 + h * 256 + col] * 0.25f; }
        d_W2cat[j] = v;
    } else {
        int j = (b - PRE_PW2) * 256 + t;
        if (j < 256) {
            int h = j >> 6, k = j & 63; float s = 0.f;
            for (int c = 0; c < 64; c++) s += W1[k * 256 + h * 64 + c] * as1[h * 64 + c];
            d_wsrc1[j] = s;
        } else if (j < 512) {
            int jj = j - 256, h = jj >> 6, k = jj & 63; float s = 0.f;
            for (int c = 0; c < 64; c++) s += W1[k * 256 + h * 64 + c] * ad1[h * 64 + c];
            d_wdst1[jj] = s;
        } else if (j < 768) {
            int jj = j - 512, h = jj >> 6, k = jj & 63; float s = 0.f;
            for (int c = 0; c < 64; c++) s += We1[k * 256 + h * 64 + c] * ag1[h * 64 + c];
            d_wae1[jj] = s;
        } else if (j < 856) {
            int jj = j - 768, tt = jj >> 2, h = jj & 3; float s = 0.f;
            for (int c = 0; c < 64; c++) s += etb1[tt * 256 + h * 64 + c] * ag1[h * 64 + c];
            d_etd1[jj] = s;
        } else if (j < 1880) {
            int jj = j - 856, h = jj >> 8, k = jj & 255; float s = 0.f;
            for (int c = 0; c < 256; c++) s += W2[k * 1024 + h * 256 + c] * as2[h * 256 + c];
            d_wsrc2[jj] = s;
        } else if (j < 2904) {
            int jj = j - 1880, h = jj >> 8, k = jj & 255; float s = 0.f;
            for (int c = 0; c < 256; c++) s += W2[k * 1024 + h * 256 + c] * ad2[h * 256 + c];
            d_wdst2[jj] = s;
        } else if (j < 3160) {
            int jj = j - 2904, h = jj >> 6, k = jj & 63; float s = 0.f;
            for (int c = 0; c < 256; c++) s += We2[k * 1024 + h * 256 + c] * ag2[h * 256 + c];
            d_wae2[jj] = s;
        } else if (j < 3248) {
            int jj = j - 3160, tt = jj >> 2, h = jj & 3; float s = 0.f;
            for (int c = 0; c < 256; c++) s += etb2[tt * 1024 + h * 256 + c] * ag2[h * 256 + c];
            d_etd2[jj] = s;
        }
    }
}

// ---------------- K2: scan (+ zero d_deg for replay) ----------------
__global__ void k_scan() {
    __shared__ int wsum[32];
    int t = threadIdx.x, base = t * 10, loc[10], sum = 0;
#pragma unroll
    for (int ii = 0; ii < 10; ii++) {
        int i = base + ii;
        int d = (i < Nn) ? d_deg[i] : 0;
        loc[ii] = d; sum += d;
    }
    int lane = t & 31, w = t >> 5;
    int v = sum;
#pragma unroll
    for (int o = 1; o < 32; o <<= 1) {
        int u = __shfl_up_sync(0xffffffffu, v, o);
        if (lane >= o) v += u;
    }
    if (lane == 31) wsum[w] = v;
    __syncthreads();
    if (w == 0) {
        int s = wsum[lane];
#pragma unroll
        for (int o = 1; o < 32; o <<= 1) {
            int u = __shfl_up_sync(0xffffffffu, s, o);
            if (lane >= o) s += u;
        }
        wsum[lane] = s;
    }
    __syncthreads();
    int run = v - sum + (w ? wsum[w - 1] : 0);
#pragma unroll
    for (int ii = 0; ii < 10; ii++) {
        int i = base + ii;
        if (i < Nn) { d_off[i] = run; d_cur[i] = run; d_deg[i] = 0; run += loc[ii]; }
        else if (i == Nn) d_off[Nn] = run;
    }
}

// ---------------- nscore body ----------------
__device__ __forceinline__ void nscore_one(int gw, int lane, const float* xin,
                                           const float* ntemb, int K,
                                           const float* ws, const float* wd, float* u) {
    int nt = d_nt[gw];
    float ps[4] = {0, 0, 0, 0}, pd[4] = {0, 0, 0, 0};
    for (int k = lane; k < K; k += 32) {
        float v = xin[gw * K + k] + ntemb[nt * K + k];
        u[gw * K + k] = v;
#pragma unroll
        for (int h = 0; h < 4; h++) { ps[h] += v * ws[h * K + k]; pd[h] += v * wd[h * K + k]; }
    }
#pragma unroll
    for (int h = 0; h < 4; h++)
        for (int o = 16; o > 0; o >>= 1) {
            ps[h] += __shfl_xor_sync(0xffffffffu, ps[h], o);
            pd[h] += __shfl_xor_sync(0xffffffffu, pd[h], o);
        }
    if (lane == 0)
#pragma unroll
        for (int h = 0; h < 4; h++) { d_ssrc[gw * 4 + h] = ps[h]; d_sdst[gw * 4 + h] = pd[h]; }
}

// ---------------- K3: fused scatter + nscore1 + edgescore ----------------
#define MID_SCAT 1250
#define MID_NS   (MID_SCAT + 1250)
#define MID_TOT  (MID_NS + 40000)

__global__ void k_mid(const float* __restrict__ ea, const float* __restrict__ x,
                      const float* __restrict__ nte1) {
    int b = blockIdx.x, t = threadIdx.x;
    if (b < MID_SCAT) {
        int e = b * 256 + t;
        if (e < Ee) {
            int p = atomicAdd(&d_cur[d_dst[e]], 1);
            d_eid[p] = e; d_srcS[p] = d_src[e]; d_etS[p] = d_et[e];
        }
    } else if (b < MID_NS) {
        int gw = (b - MID_SCAT) * 8 + (t >> 5);
        if (gw < Nn) nscore_one(gw, t & 31, x, nte1, 64, d_wsrc1, d_wdst1, d_u1);
    } else {
        int e = (b - MID_NS) * 8 + (t >> 5);
        int lane = t & 31;
        float a0 = ea[(size_t)e * 64 + lane];
        float a1 = ea[(size_t)e * 64 + 32 + lane];
        float dd1[4], dd2[4];
#pragma unroll
        for (int h = 0; h < 4; h++) {
            dd1[h] = a0 * d_wae1[h * 64 + lane] + a1 * d_wae1[h * 64 + 32 + lane];
            dd2[h] = a0 * d_wae2[h * 64 + lane] + a1 * d_wae2[h * 64 + 32 + lane];
            for (int o = 16; o > 0; o >>= 1) {
                dd1[h] += __shfl_xor_sync(0xffffffffu, dd1[h], o);
                dd2[h] += __shfl_xor_sync(0xffffffffu, dd2[h], o);
            }
        }
        if (lane == 0) {
            int et = d_et[e];
#pragma unroll
            for (int h = 0; h < 4; h++) {
                d_se1[e * 4 + h] = dd1[h] + d_etd1[et * 4 + h];
                d_se2[e * 4 + h] = dd2[h] + d_etd2[et * 4 + h];
            }
        }
    }
}

// ---- warp softmax stats ----
__device__ __forceinline__ void warp_softmax(const float4* se4, int beg, int end,
                                             int lane, float4 sd, float4& m, float4& rdn) {
    const float4* ssrc4 = (const float4*)d_ssrc;
    float4 mx = make_float4(-1e30f, -1e30f, -1e30f, -1e30f);
    for (int i = beg + lane; i < end; i += 32) {
        float4 l = logit4(ssrc4[d_srcS[i]], sd, se4[d_eid[i]]);
        mx.x = fmaxf(mx.x, l.x); mx.y = fmaxf(mx.y, l.y);
        mx.z = fmaxf(mx.z, l.z); mx.w = fmaxf(mx.w, l.w);
    }
    m = warpMax4(mx);
    float4 sm = make_float4(0, 0, 0, 0);
    for (int i = beg + lane; i < end; i += 32) {
        float4 l = logit4(ssrc4[d_srcS[i]], sd, se4[d_eid[i]]);
        sm.x += __expf(l.x - m.x); sm.y += __expf(l.y - m.y);
        sm.z += __expf(l.z - m.z); sm.w += __expf(l.w - m.w);
    }
    float4 den = warpSum4(sm);
    rdn.x = 1.f / (den.x + 1e-16f); rdn.y = 1.f / (den.y + 1e-16f);
    rdn.z = 1.f / (den.z + 1e-16f); rdn.w = 1.f / (den.w + 1e-16f);
}

// ---------------- K4: warp-per-node layer-1 attention (R6) ----------------
__global__ void k_attn1(const float* __restrict__ ea, const float* __restrict__ x) {
    int wid = threadIdx.x >> 5, lane = threadIdx.x & 31;
    int n = blockIdx.x * 8 + wid;
    __shared__ ull  aSh[8][32][4];
    __shared__ int2 iSh[8][32];
    __shared__ float acctSh[8][88];
    for (int i = lane; i < 88; i += 32) acctSh[wid][i] = 0.f;
    __syncwarp();
    int beg = d_off[n], end = d_off[n + 1], nE = end - beg;
    ull ax[4] = {0, 0, 0, 0}, av[4] = {0, 0, 0, 0};
    if (nE > 0) {
        const float4* ssrc4 = (const float4*)d_ssrc;
        const float4* se4 = (const float4*)d_se1;
        float4 sd = ((const float4*)d_sdst)[n];
        float4 m, rdn;
        warp_softmax(se4, beg, end, lane, sd, m, rdn);
        for (int c0 = beg; c0 < end; c0 += 32) {
            int nc = min(32, end - c0);
            if (lane < nc) {
                int i = c0 + lane;
                int s = d_srcS[i], e = d_eid[i], et = d_etS[i];
                float4 l = logit4(ssrc4[s], sd, se4[e]);
                float a0 = __expf(l.x - m.x) * rdn.x, a1 = __expf(l.y - m.y) * rdn.y;
                float a2 = __expf(l.z - m.z) * rdn.z, a3 = __expf(l.w - m.w) * rdn.w;
                aSh[wid][lane][0] = dup2(a0); aSh[wid][lane][1] = dup2(a1);
                aSh[wid][lane][2] = dup2(a2); aSh[wid][lane][3] = dup2(a3);
                iSh[wid][lane] = make_int2(s, e);
                atomicAdd(&acctSh[wid][et], a0);
                atomicAdd(&acctSh[wid][22 + et], a1);
                atomicAdd(&acctSh[wid][44 + et], a2);
                atomicAdd(&acctSh[wid][66 + et], a3);
            }
            __syncwarp();
#pragma unroll 4
            for (int j = 0; j < nc; j++) {
                ull b0 = aSh[wid][j][0], b1 = aSh[wid][j][1];
                ull b2 = aSh[wid][j][2], b3 = aSh[wid][j][3];
                int2 se = iSh[wid][j];
                ull u = *(const ull*)&d_u1[se.x * 64 + lane * 2];
                ull a = *(const ull*)&ea[(size_t)se.y * 64 + lane * 2];
                fma2(ax[0], u, b0); fma2(ax[1], u, b1);
                fma2(ax[2], u, b2); fma2(ax[3], u, b3);
                fma2(av[0], a, b0); fma2(av[1], a, b1);
                fma2(av[2], a, b2); fma2(av[3], a, b3);
            }
            __syncwarp();
        }
    }
    __syncwarp();
    float* v = &d_v1[(size_t)n * LDA1];
    int c = lane * 2;
#pragma unroll
    for (int h = 0; h < 4; h++) {
        *(ull*)&v[h * K1H + c] = ax[h];
        *(ull*)&v[h * K1H + 64 + c] = av[h];
        *(ull*)&v[h * K1H + 150 + c] = *(const ull*)&x[n * 64 + c];
    }
    for (int i = lane; i < 88; i += 32) {
        int hh = i / 22, t2 = i % 22;
        v[hh * K1H + 128 + t2] = acctSh[wid][hh * 22 + t2];
    }
    if (lane < 8) v[(lane >> 1) * K1H + 214 + (lane & 1)] = 0.f;
}

// ---------------- K6: nscore layer 2 ----------------
__global__ void k_ns2(const float* __restrict__ nte2) {
    int gw = (blockIdx.x * blockDim.x + threadIdx.x) >> 5;
    if (gw < Nn) nscore_one(gw, threadIdx.x & 31, d_h1, nte2, 256, d_wsrc2, d_wdst2, d_u2);
}

// ---------------- K7: warp-per-node layer-2 attention (R6) ----------------
__global__ void k_attn2(const float* __restrict__ ea) {
    int wid = threadIdx.x >> 5, lane = threadIdx.x & 31;
    int n = blockIdx.x * 8 + wid;
    __shared__ ull  aSh[8][32][4];
    __shared__ int2 iSh[8][32];
    __shared__ float acctSh[8][88];
    for (int i = lane; i < 88; i += 32) acctSh[wid][i] = 0.f;
    __syncwarp();
    int beg = d_off[n], end = d_off[n + 1], nE = end - beg;
    ull axu[4][4];
#pragma unroll
    for (int h = 0; h < 4; h++)
#pragma unroll
        for (int q = 0; q < 4; q++) axu[h][q] = 0ull;
    ull av[4] = {0, 0, 0, 0};
    if (nE > 0) {
        const float4* ssrc4 = (const float4*)d_ssrc;
        const float4* se4 = (const float4*)d_se2;
        float4 sd = ((const float4*)d_sdst)[n];
        float4 m, rdn;
        warp_softmax(se4, beg, end, lane, sd, m, rdn);
        for (int c0 = beg; c0 < end; c0 += 32) {
            int nc = min(32, end - c0);
            if (lane < nc) {
                int i = c0 + lane;
                int s = d_srcS[i], e = d_eid[i], et = d_etS[i];
                float4 l = logit4(ssrc4[s], sd, se4[e]);
                float a0 = __expf(l.x - m.x) * rdn.x, a1 = __expf(l.y - m.y) * rdn.y;
                float a2 = __expf(l.z - m.z) * rdn.z, a3 = __expf(l.w - m.w) * rdn.w;
                aSh[wid][lane][0] = dup2(a0); aSh[wid][lane][1] = dup2(a1);
                aSh[wid][lane][2] = dup2(a2); aSh[wid][lane][3] = dup2(a3);
                iSh[wid][lane] = make_int2(s, e);
                atomicAdd(&acctSh[wid][et], a0);
                atomicAdd(&acctSh[wid][22 + et], a1);
                atomicAdd(&acctSh[wid][44 + et], a2);
                atomicAdd(&acctSh[wid][66 + et], a3);
            }
            __syncwarp();
#pragma unroll 2
            for (int j = 0; j < nc; j++) {
                ull b0 = aSh[wid][j][0], b1 = aSh[wid][j][1];
                ull b2 = aSh[wid][j][2], b3 = aSh[wid][j][3];
                int2 se = iSh[wid][j];
                const float4* up = (const float4*)&d_u2[se.x * 256 + lane * 8];
                float4 u0 = up[0], u1 = up[1];
                ull p0 = *(ull*)&u0.x, p1 = *(ull*)&u0.z;
                ull p2 = *(ull*)&u1.x, p3 = *(ull*)&u1.z;
                fma2(axu[0][0], p0, b0); fma2(axu[0][1], p1, b0);
                fma2(axu[0][2], p2, b0); fma2(axu[0][3], p3, b0);
                fma2(axu[1][0], p0, b1); fma2(axu[1][1], p1, b1);
                fma2(axu[1][2], p2, b1); fma2(axu[1][3], p3, b1);
                fma2(axu[2][0], p0, b2); fma2(axu[2][1], p1, b2);
                fma2(axu[2][2], p2, b2); fma2(axu[2][3], p3, b2);
                fma2(axu[3][0], p0, b3); fma2(axu[3][1], p1, b3);
                fma2(axu[3][2], p2, b3); fma2(axu[3][3], p3, b3);
                ull a = *(const ull*)&ea[(size_t)se.y * 64 + lane * 2];
                fma2(av[0], a, b0); fma2(av[1], a, b1);
                fma2(av[2], a, b2); fma2(av[3], a, b3);
            }
            __syncwarp();
        }
    }
    __syncwarp();
    float* v = &d_v2[(size_t)n * K2P];
#pragma unroll
    for (int h = 0; h < 4; h++) {
#pragma unroll
        for (int q = 0; q < 4; q++)
            *(ull*)&v[h * 256 + lane * 8 + q * 2] = axu[h][q];
        *(ull*)&v[1024 + h * 64 + lane * 2] = av[h];
    }
    for (int i = lane; i < 96; i += 32)
        v[1280 + i] = (i < 88) ? acctSh[wid][i] : 0.f;
}

// ---------------- tf32 mma.sync GEMM (shared template for both layers) -------
// MODE 1: K=K1H, LDA=LDA1, A col offset y*K1H, B=[4][216][64] ldb=64, relu+bias
// MODE 2: K=K2P, LDA=K2P, B=[1376][256] col tile y*64, bias+add
template <int K, int MODE>
__global__ void k_gemmTF(const float* __restrict__ A, const float* __restrict__ B,
                         const float* __restrict__ bias, const float* __restrict__ add,
                         float* __restrict__ C) {
    constexpr int LDA = (MODE == 1) ? LDA1 : K2P;
    __shared__ unsigned As[8][136];
    __shared__ unsigned Bs[8][72];
    int y = blockIdx.y;
    int bm = blockIdx.x * 128;
    int colbase = y * 64;
    const float* Ab = A + ((MODE == 1) ? y * K1H : 0);
    const float* Bb = (MODE == 1) ? (B + y * K1H * 64) : (B + colbase);
    const int ldb = (MODE == 1) ? 64 : 256;
    int tid = threadIdx.x;
    int warp = tid >> 5, lane = tid & 31;
    int g = lane >> 2, tig = lane & 3;
    int lrow = tid & 127, lk = (tid >> 7) * 4;
    int brow = tid >> 4, bcol = (tid & 15) * 4;
    int row = bm + lrow;
    float acc[8][4];
#pragma unroll
    for (int nt = 0; nt < 8; nt++)
#pragma unroll
        for (int j = 0; j < 4; j++) acc[nt][j] = 0.f;

    for (int k0 = 0; k0 < K; k0 += 8) {
        float4 avv = make_float4(0, 0, 0, 0);
        if (row < Nn) avv = *(const float4*)&Ab[(size_t)row * LDA + k0 + lk];
        As[lk + 0][lrow] = to_tf32(avv.x);
        As[lk + 1][lrow] = to_tf32(avv.y);
        As[lk + 2][lrow] = to_tf32(avv.z);
        As[lk + 3][lrow] = to_tf32(avv.w);
        if (tid < 128) {
            float4 bv = *(const float4*)&Bb[(size_t)(k0 + brow) * ldb + bcol];
            Bs[brow][bcol + 0] = to_tf32(bv.x);
            Bs[brow][bcol + 1] = to_tf32(bv.y);
            Bs[brow][bcol + 2] = to_tf32(bv.z);
            Bs[brow][bcol + 3] = to_tf32(bv.w);
        }
        __syncthreads();
        unsigned a0 = As[tig][warp * 16 + g];
        unsigned a1 = As[tig][warp * 16 + g + 8];
        unsigned a2 = As[tig + 4][warp * 16 + g];
        unsigned a3 = As[tig + 4][warp * 16 + g + 8];
#pragma unroll
        for (int nt = 0; nt < 8; nt++) {
            unsigned b0 = Bs[tig][nt * 8 + g];
            unsigned b1 = Bs[tig + 4][nt * 8 + g];
            asm volatile(
                "mma.sync.aligned.m16n8k8.row.col.f32.tf32.tf32.f32 "
                "{%0,%1,%2,%3}, {%4,%5,%6,%7}, {%8,%9}, {%0,%1,%2,%3};"
                : "+f"(acc[nt][0]), "+f"(acc[nt][1]), "+f"(acc[nt][2]), "+f"(acc[nt][3])
                : "r"(a0), "r"(a1), "r"(a2), "r"(a3), "r"(b0), "r"(b1));
        }
        __syncthreads();
    }
#pragma unroll
    for (int nt = 0; nt < 8; nt++) {
        int r0 = bm + warp * 16 + g, r1 = r0 + 8;
        int cA = colbase + nt * 8 + 2 * tig, cB = cA + 1;
        float bA = bias[cA], bB = bias[cB];
        if (r0 < Nn) {
            float vA = acc[nt][0] + bA, vB = acc[nt][1] + bB;
            if (MODE == 1) { vA = fmaxf(vA, 0.f); vB = fmaxf(vB, 0.f); }
            else { vA += add[r0 * 256 + cA]; vB += add[r0 * 256 + cB]; }
            C[r0 * 256 + cA] = vA;
            C[r0 * 256 + cB] = vB;
        }
        if (r1 < Nn) {
            float vA = acc[nt][2] + bA, vB = acc[nt][3] + bB;
            if (MODE == 1) { vA = fmaxf(vA, 0.f); vB = fmaxf(vB, 0.f); }
            else { vA += add[r1 * 256 + cA]; vB += add[r1 * 256 + cB]; }
            C[r1 * 256 + cA] = vA;
            C[r1 * 256 + cB] = vB;
        }
    }
}

// ---------------- launch ----------------
extern "C" void kernel_launch(void* const* d_in, const int* in_sizes, int n_in,
                              void* d_out, int out_size) {
    const float* x    = (const float*)d_in[0];
    const void*  ei   = d_in[1];
    const void*  ntp  = d_in[2];
    const float* ea   = (const float*)d_in[3];
    const void*  etp  = d_in[4];
    const float* W1   = (const float*)d_in[5];
    const float* b1   = (const float*)d_in[6];
    const float* We1  = (const float*)d_in[7];
    const float* nte1 = (const float*)d_in[8];
    const float* ete1 = (const float*)d_in[9];
    const float* as1  = (const float*)d_in[10];
    const float* ad1  = (const float*)d_in[11];
    const float* ag1  = (const float*)d_in[12];
    const float* res1 = (const float*)d_in[13];
    const float* W2   = (const float*)d_in[14];
    const float* b2   = (const float*)d_in[15];
    const float* We2  = (const float*)d_in[16];
    const float* nte2 = (const float*)d_in[17];
    const float* ete2 = (const float*)d_in[18];
    const float* as2  = (const float*)d_in[19];
    const float* ad2  = (const float*)d_in[20];
    const float* ag2  = (const float*)d_in[21];
    float* out = (float*)d_out;

    k_pre<<<PRE_TOT, 256>>>(ei, ntp, etp, W1, as1, ad1, We1, ag1, ete1,
                            W2, as2, ad2, We2, ag2, ete2, res1);
    k_scan<<<1, 1024>>>();
    k_mid<<<MID_TOT, 256>>>(ea, x, nte1);
    k_attn1<<<Nn / 8, 256>>>(ea, x);

    float* h1;  cudaGetSymbolAddress((void**)&h1, d_h1);
    float* v1;  cudaGetSymbolAddress((void**)&v1, d_v1);
    float* w1h; cudaGetSymbolAddress((void**)&w1h, d_W1h);
    float* v2;  cudaGetSymbolAddress((void**)&v2, d_v2);
    float* w2c; cudaGetSymbolAddress((void**)&w2c, d_W2cat);
    dim3 g((Nn + 127) / 128, 4);
    k_gemmTF<K1H, 1><<<g, 256>>>(v1, w1h, b1, nullptr, h1);
    k_ns2<<<(Nn * 32 + 255) / 256, 256>>>(nte2);
    k_attn2<<<Nn / 8, 256>>>(ea);
    k_gemmTF<K2P, 2><<<g, 256>>>(v2, w2c, b2, h1, out);
}

// round 14
// speedup vs baseline: 1.5709x; 1.0486x over previous
#include <cuda_runtime.h>
#include <math.h>

#define Nn 10000
#define Ee 320000
#define K1H 216          // per-head K for layer-1 GEMM
#define LDA1 (4 * K1H)   // 864
#define K2P 1376

// ---------------- static scratch ----------------
__device__ int   d_src[Ee], d_dst[Ee], d_et[Ee], d_nt[Nn];
__device__ int   d_deg[Nn], d_off[Nn + 1], d_cur[Nn];
__device__ int   d_eid[Ee], d_srcS[Ee], d_etS[Ee];
__device__ float d_se1[Ee * 4], d_se2[Ee * 4];
__device__ float d_ssrc[Nn * 4], d_sdst[Nn * 4];
__device__ float d_u1[Nn * 64], d_u2[Nn * 256], d_h1[Nn * 256];
__device__ float d_v1[(size_t)Nn * LDA1], d_v2[(size_t)Nn * K2P];
__device__ float d_wsrc1[256], d_wdst1[256], d_wae1[256], d_etd1[22 * 4];
__device__ float d_wsrc2[1024], d_wdst2[1024], d_wae2[256], d_etd2[22 * 4];
__device__ float d_W1h[4 * K1H * 64], d_W2cat[K2P * 256];

typedef unsigned long long ull;

__device__ __forceinline__ float lrelu(float v) { return v > 0.f ? v : 0.2f * v; }
__device__ __forceinline__ int ldidx(const void* p, long long i, int is64) {
    return is64 ? (int)((const long long*)p)[i] : ((const int*)p)[i];
}
__device__ __forceinline__ ull dup2(float x) {
    ull r;
    asm("mov.b64 %0, {%1, %1};" : "=l"(r) : "r"(__float_as_uint(x)));
    return r;
}
__device__ __forceinline__ void fma2(ull& d, ull a, ull b) {
    asm("fma.rn.f32x2 %0, %1, %2, %0;" : "+l"(d) : "l"(a), "l"(b));
}
__device__ __forceinline__ unsigned to_tf32(float x) {
    unsigned r;
    asm("cvt.rna.tf32.f32 %0, %1;" : "=r"(r) : "f"(x));
    return r;
}
__device__ __forceinline__ float4 logit4(float4 ss, float4 sd, float4 se) {
    float4 l;
    l.x = lrelu(ss.x + sd.x + se.x); l.y = lrelu(ss.y + sd.y + se.y);
    l.z = lrelu(ss.z + sd.z + se.z); l.w = lrelu(ss.w + sd.w + se.w);
    return l;
}
__device__ __forceinline__ float4 warpMax4(float4 v) {
#pragma unroll
    for (int o = 16; o > 0; o >>= 1) {
        v.x = fmaxf(v.x, __shfl_xor_sync(0xffffffffu, v.x, o));
        v.y = fmaxf(v.y, __shfl_xor_sync(0xffffffffu, v.y, o));
        v.z = fmaxf(v.z, __shfl_xor_sync(0xffffffffu, v.z, o));
        v.w = fmaxf(v.w, __shfl_xor_sync(0xffffffffu, v.w, o));
    }
    return v;
}
__device__ __forceinline__ float4 warpSum4(float4 v) {
#pragma unroll
    for (int o = 16; o > 0; o >>= 1) {
        v.x += __shfl_xor_sync(0xffffffffu, v.x, o);
        v.y += __shfl_xor_sync(0xffffffffu, v.y, o);
        v.z += __shfl_xor_sync(0xffffffffu, v.z, o);
        v.w += __shfl_xor_sync(0xffffffffu, v.w, o);
    }
    return v;
}
__device__ __forceinline__ int block_is64(const unsigned int* w) {
    int t = threadIdx.x;
    int bad = 0;
    if (t < 128) bad = (w[2 * (t * 39) + 1] != 0u);
    return __syncthreads_or(bad) ? 0 : 1;
}
__device__ __forceinline__ float wdot(const float* A, const float* B, int len, int lane) {
    float s = 0.f;
    for (int c = lane; c < len; c += 32) s += A[c] * B[c];
#pragma unroll
    for (int o = 16; o > 0; o >>= 1) s += __shfl_xor_sync(0xffffffffu, s, o);
    return s;
}

// ---------------- K1: fused preprocessing ----------------
#define PRE_CONV 1250
#define PRE_PW1  (PRE_CONV + 216)
#define PRE_PW2  (PRE_PW1 + 1376)
#define PRE_TOT  (PRE_PW2 + 406)

__global__ void k_pre(const void* ei, const void* ntp, const void* etp,
                      const float* W1, const float* as1, const float* ad1,
                      const float* We1, const float* ag1, const float* etb1,
                      const float* W2, const float* as2, const float* ad2,
                      const float* We2, const float* ag2, const float* etb2,
                      const float* res1) {
    int b = blockIdx.x, t = threadIdx.x;
    if (b < PRE_CONV) {
        int is64 = block_is64((const unsigned int*)ntp);
        int e = b * 256 + t;
        if (e < Ee) {
            int s = ldidx(ei, e, is64);
            int d2 = ldidx(ei, (long long)Ee + e, is64);
            d_src[e] = s; d_dst[e] = d2; d_et[e] = ldidx(etp, e, is64);
            atomicAdd(&d_deg[d2], 1);
        }
        if (b < 40) { int i = b * 256 + t; if (i < Nn) d_nt[i] = ldidx(ntp, i, is64); }
    } else if (b < PRE_PW1) {
        int j = (b - PRE_CONV) * 256 + t;
        int c = j & 63, hk = j >> 6, h = hk / K1H, k = hk - h * K1H;
        float v = 0.f;
        if (k < 64) v = W1[k * 256 + h * 64 + c];
        else if (k < 128) v = We1[(k - 64) * 256 + h * 64 + c];
        else if (k < 150) v = etb1[(k - 128) * 256 + h * 64 + c];
        else if (k < 214) v = res1[(k - 150) * 256 + h * 64 + c];
        d_W1h[j] = v;
    } else if (b < PRE_PW2) {
        int j = (b - PRE_PW1) * 256 + t;
        int col = j & 255, r = j >> 8;
        float v = 0.f;
        if (r < 1024) { int h = r >> 8, k = r & 255; v = W2[k * 1024 + h * 256 + col] * 0.25f; }
        else if (r < 1280) { int rr = r - 1024, h = rr >> 6, k = rr & 63; v = We2[k * 1024 + h * 256 + col] * 0.25f; }
        else if (r < 1368) { int rr = r - 1280, h = rr / 22, tt = rr % 22; v = etb2[tt * 1024 + h * 256 + col] * 0.25f; }
        d_W2cat[j] = v;
    } else {
        // warp-per-output score-vector dots (coalesced)
        int wo = (b - PRE_PW2) * 8 + (t >> 5);
        int lane = t & 31;
        if (wo < 3248) {
            float s = 0.f;
            float* dst = nullptr;
            if (wo < 256) {
                int h = wo >> 6, k = wo & 63;
                s = wdot(W1 + k * 256 + h * 64, as1 + h * 64, 64, lane);
                dst = &d_wsrc1[wo];
            } else if (wo < 512) {
                int jj = wo - 256, h = jj >> 6, k = jj & 63;
                s = wdot(W1 + k * 256 + h * 64, ad1 + h * 64, 64, lane);
                dst = &d_wdst1[jj];
            } else if (wo < 768) {
                int jj = wo - 512, h = jj >> 6, k = jj & 63;
                s = wdot(We1 + k * 256 + h * 64, ag1 + h * 64, 64, lane);
                dst = &d_wae1[jj];
            } else if (wo < 856) {
                int jj = wo - 768, tt = jj >> 2, h = jj & 3;
                s = wdot(etb1 + tt * 256 + h * 64, ag1 + h * 64, 64, lane);
                dst = &d_etd1[jj];
            } else if (wo < 1880) {
                int jj = wo - 856, h = jj >> 8, k = jj & 255;
                s = wdot(W2 + k * 1024 + h * 256, as2 + h * 256, 256, lane);
                dst = &d_wsrc2[jj];
            } else if (wo < 2904) {
                int jj = wo - 1880, h = jj >> 8, k = jj & 255;
                s = wdot(W2 + k * 1024 + h * 256, ad2 + h * 256, 256, lane);
                dst = &d_wdst2[jj];
            } else if (wo < 3160) {
                int jj = wo - 2904, h = jj >> 6, k = jj & 63;
                s = wdot(We2 + k * 1024 + h * 256, ag2 + h * 256, 256, lane);
                dst = &d_wae2[jj];
            } else {
                int jj = wo - 3160, tt = jj >> 2, h = jj & 3;
                s = wdot(etb2 + tt * 1024 + h * 256, ag2 + h * 256, 256, lane);
                dst = &d_etd2[jj];
            }
            if (lane == 0) *dst = s;
        }
    }
}

// ---------------- K2: scan (+ zero d_deg for replay) ----------------
__global__ void k_scan() {
    __shared__ int wsum[32];
    int t = threadIdx.x, base = t * 10, loc[10], sum = 0;
#pragma unroll
    for (int ii = 0; ii < 10; ii++) {
        int i = base + ii;
        int d = (i < Nn) ? d_deg[i] : 0;
        loc[ii] = d; sum += d;
    }
    int lane = t & 31, w = t >> 5;
    int v = sum;
#pragma unroll
    for (int o = 1; o < 32; o <<= 1) {
        int u = __shfl_up_sync(0xffffffffu, v, o);
        if (lane >= o) v += u;
    }
    if (lane == 31) wsum[w] = v;
    __syncthreads();
    if (w == 0) {
        int s = wsum[lane];
#pragma unroll
        for (int o = 1; o < 32; o <<= 1) {
            int u = __shfl_up_sync(0xffffffffu, s, o);
            if (lane >= o) s += u;
        }
        wsum[lane] = s;
    }
    __syncthreads();
    int run = v - sum + (w ? wsum[w - 1] : 0);
#pragma unroll
    for (int ii = 0; ii < 10; ii++) {
        int i = base + ii;
        if (i < Nn) { d_off[i] = run; d_cur[i] = run; d_deg[i] = 0; run += loc[ii]; }
        else if (i == Nn) d_off[Nn] = run;
    }
}

// ---------------- nscore body ----------------
__device__ __forceinline__ void nscore_one(int gw, int lane, const float* xin,
                                           const float* ntemb, int K,
                                           const float* ws, const float* wd, float* u) {
    int nt = d_nt[gw];
    float ps[4] = {0, 0, 0, 0}, pd[4] = {0, 0, 0, 0};
    for (int k = lane; k < K; k += 32) {
        float v = xin[gw * K + k] + ntemb[nt * K + k];
        u[gw * K + k] = v;
#pragma unroll
        for (int h = 0; h < 4; h++) { ps[h] += v * ws[h * K + k]; pd[h] += v * wd[h * K + k]; }
    }
#pragma unroll
    for (int h = 0; h < 4; h++)
        for (int o = 16; o > 0; o >>= 1) {
            ps[h] += __shfl_xor_sync(0xffffffffu, ps[h], o);
            pd[h] += __shfl_xor_sync(0xffffffffu, pd[h], o);
        }
    if (lane == 0)
#pragma unroll
        for (int h = 0; h < 4; h++) { d_ssrc[gw * 4 + h] = ps[h]; d_sdst[gw * 4 + h] = pd[h]; }
}

// ---------------- K3: fused scatter + nscore1 + edgescore ----------------
#define MID_SCAT 1250
#define MID_NS   (MID_SCAT + 1250)
#define MID_TOT  (MID_NS + 40000)

__global__ void k_mid(const float* __restrict__ ea, const float* __restrict__ x,
                      const float* __restrict__ nte1) {
    int b = blockIdx.x, t = threadIdx.x;
    if (b < MID_SCAT) {
        int e = b * 256 + t;
        if (e < Ee) {
            int p = atomicAdd(&d_cur[d_dst[e]], 1);
            d_eid[p] = e; d_srcS[p] = d_src[e]; d_etS[p] = d_et[e];
        }
    } else if (b < MID_NS) {
        int gw = (b - MID_SCAT) * 8 + (t >> 5);
        if (gw < Nn) nscore_one(gw, t & 31, x, nte1, 64, d_wsrc1, d_wdst1, d_u1);
    } else {
        int e = (b - MID_NS) * 8 + (t >> 5);
        int lane = t & 31;
        float a0 = ea[(size_t)e * 64 + lane];
        float a1 = ea[(size_t)e * 64 + 32 + lane];
        float dd1[4], dd2[4];
#pragma unroll
        for (int h = 0; h < 4; h++) {
            dd1[h] = a0 * d_wae1[h * 64 + lane] + a1 * d_wae1[h * 64 + 32 + lane];
            dd2[h] = a0 * d_wae2[h * 64 + lane] + a1 * d_wae2[h * 64 + 32 + lane];
            for (int o = 16; o > 0; o >>= 1) {
                dd1[h] += __shfl_xor_sync(0xffffffffu, dd1[h], o);
                dd2[h] += __shfl_xor_sync(0xffffffffu, dd2[h], o);
            }
        }
        if (lane == 0) {
            int et = d_et[e];
#pragma unroll
            for (int h = 0; h < 4; h++) {
                d_se1[e * 4 + h] = dd1[h] + d_etd1[et * 4 + h];
                d_se2[e * 4 + h] = dd2[h] + d_etd2[et * 4 + h];
            }
        }
    }
}

// ---- warp softmax stats ----
__device__ __forceinline__ void warp_softmax(const float4* se4, int beg, int end,
                                             int lane, float4 sd, float4& m, float4& rdn) {
    const float4* ssrc4 = (const float4*)d_ssrc;
    float4 mx = make_float4(-1e30f, -1e30f, -1e30f, -1e30f);
    for (int i = beg + lane; i < end; i += 32) {
        float4 l = logit4(ssrc4[d_srcS[i]], sd, se4[d_eid[i]]);
        mx.x = fmaxf(mx.x, l.x); mx.y = fmaxf(mx.y, l.y);
        mx.z = fmaxf(mx.z, l.z); mx.w = fmaxf(mx.w, l.w);
    }
    m = warpMax4(mx);
    float4 sm = make_float4(0, 0, 0, 0);
    for (int i = beg + lane; i < end; i += 32) {
        float4 l = logit4(ssrc4[d_srcS[i]], sd, se4[d_eid[i]]);
        sm.x += __expf(l.x - m.x); sm.y += __expf(l.y - m.y);
        sm.z += __expf(l.z - m.z); sm.w += __expf(l.w - m.w);
    }
    float4 den = warpSum4(sm);
    rdn.x = 1.f / (den.x + 1e-16f); rdn.y = 1.f / (den.y + 1e-16f);
    rdn.z = 1.f / (den.z + 1e-16f); rdn.w = 1.f / (den.w + 1e-16f);
}

// ---------------- K4: warp-per-node layer-1 attention (prefetch pipeline) ----
__global__ void k_attn1(const float* __restrict__ ea, const float* __restrict__ x) {
    int wid = threadIdx.x >> 5, lane = threadIdx.x & 31;
    int n = blockIdx.x * 8 + wid;
    __shared__ ull  aSh[8][32][4];
    __shared__ int2 iSh[8][32];
    __shared__ float acctSh[8][88];
    for (int i = lane; i < 88; i += 32) acctSh[wid][i] = 0.f;
    __syncwarp();
    int beg = d_off[n], end = d_off[n + 1], nE = end - beg;
    ull ax[4] = {0, 0, 0, 0}, av[4] = {0, 0, 0, 0};
    if (nE > 0) {
        const float4* ssrc4 = (const float4*)d_ssrc;
        const float4* se4 = (const float4*)d_se1;
        float4 sd = ((const float4*)d_sdst)[n];
        float4 m, rdn;
        warp_softmax(se4, beg, end, lane, sd, m, rdn);
        for (int c0 = beg; c0 < end; c0 += 32) {
            int nc = min(32, end - c0);
            if (lane < nc) {
                int i = c0 + lane;
                int s = d_srcS[i], e = d_eid[i], et = d_etS[i];
                float4 l = logit4(ssrc4[s], sd, se4[e]);
                float a0 = __expf(l.x - m.x) * rdn.x, a1 = __expf(l.y - m.y) * rdn.y;
                float a2 = __expf(l.z - m.z) * rdn.z, a3 = __expf(l.w - m.w) * rdn.w;
                aSh[wid][lane][0] = dup2(a0); aSh[wid][lane][1] = dup2(a1);
                aSh[wid][lane][2] = dup2(a2); aSh[wid][lane][3] = dup2(a3);
                iSh[wid][lane] = make_int2(s, e);
                atomicAdd(&acctSh[wid][et], a0);
                atomicAdd(&acctSh[wid][22 + et], a1);
                atomicAdd(&acctSh[wid][44 + et], a2);
                atomicAdd(&acctSh[wid][66 + et], a3);
            }
            __syncwarp();
            // software-pipelined gather: load edge j+1 while computing edge j
            int2 seC = iSh[wid][0];
            ull uC = *(const ull*)&d_u1[seC.x * 64 + lane * 2];
            ull aC = *(const ull*)&ea[(size_t)seC.y * 64 + lane * 2];
#pragma unroll 2
            for (int j = 0; j < nc; j++) {
                ull uN = 0, aN = 0;
                if (j + 1 < nc) {
                    int2 seN = iSh[wid][j + 1];
                    uN = *(const ull*)&d_u1[seN.x * 64 + lane * 2];
                    aN = *(const ull*)&ea[(size_t)seN.y * 64 + lane * 2];
                }
                ull b0 = aSh[wid][j][0], b1 = aSh[wid][j][1];
                ull b2 = aSh[wid][j][2], b3 = aSh[wid][j][3];
                fma2(ax[0], uC, b0); fma2(ax[1], uC, b1);
                fma2(ax[2], uC, b2); fma2(ax[3], uC, b3);
                fma2(av[0], aC, b0); fma2(av[1], aC, b1);
                fma2(av[2], aC, b2); fma2(av[3], aC, b3);
                uC = uN; aC = aN;
            }
            __syncwarp();
        }
    }
    __syncwarp();
    float* v = &d_v1[(size_t)n * LDA1];
    int c = lane * 2;
#pragma unroll
    for (int h = 0; h < 4; h++) {
        *(ull*)&v[h * K1H + c] = ax[h];
        *(ull*)&v[h * K1H + 64 + c] = av[h];
        *(ull*)&v[h * K1H + 150 + c] = *(const ull*)&x[n * 64 + c];
    }
    for (int i = lane; i < 88; i += 32) {
        int hh = i / 22, t2 = i % 22;
        v[hh * K1H + 128 + t2] = acctSh[wid][hh * 22 + t2];
    }
    if (lane < 8) v[(lane >> 1) * K1H + 214 + (lane & 1)] = 0.f;
}

// ---------------- K6: nscore layer 2 ----------------
__global__ void k_ns2(const float* __restrict__ nte2) {
    int gw = (blockIdx.x * blockDim.x + threadIdx.x) >> 5;
    if (gw < Nn) nscore_one(gw, threadIdx.x & 31, d_h1, nte2, 256, d_wsrc2, d_wdst2, d_u2);
}

// ---------------- K7: warp-per-node layer-2 attention (prefetch pipeline) ----
__global__ void k_attn2(const float* __restrict__ ea) {
    int wid = threadIdx.x >> 5, lane = threadIdx.x & 31;
    int n = blockIdx.x * 8 + wid;
    __shared__ ull  aSh[8][32][4];
    __shared__ int2 iSh[8][32];
    __shared__ float acctSh[8][88];
    for (int i = lane; i < 88; i += 32) acctSh[wid][i] = 0.f;
    __syncwarp();
    int beg = d_off[n], end = d_off[n + 1], nE = end - beg;
    ull axu[4][4];
#pragma unroll
    for (int h = 0; h < 4; h++)
#pragma unroll
        for (int q = 0; q < 4; q++) axu[h][q] = 0ull;
    ull av[4] = {0, 0, 0, 0};
    if (nE > 0) {
        const float4* ssrc4 = (const float4*)d_ssrc;
        const float4* se4 = (const float4*)d_se2;
        float4 sd = ((const float4*)d_sdst)[n];
        float4 m, rdn;
        warp_softmax(se4, beg, end, lane, sd, m, rdn);
        for (int c0 = beg; c0 < end; c0 += 32) {
            int nc = min(32, end - c0);
            if (lane < nc) {
                int i = c0 + lane;
                int s = d_srcS[i], e = d_eid[i], et = d_etS[i];
                float4 l = logit4(ssrc4[s], sd, se4[e]);
                float a0 = __expf(l.x - m.x) * rdn.x, a1 = __expf(l.y - m.y) * rdn.y;
                float a2 = __expf(l.z - m.z) * rdn.z, a3 = __expf(l.w - m.w) * rdn.w;
                aSh[wid][lane][0] = dup2(a0); aSh[wid][lane][1] = dup2(a1);
                aSh[wid][lane][2] = dup2(a2); aSh[wid][lane][3] = dup2(a3);
                iSh[wid][lane] = make_int2(s, e);
                atomicAdd(&acctSh[wid][et], a0);
                atomicAdd(&acctSh[wid][22 + et], a1);
                atomicAdd(&acctSh[wid][44 + et], a2);
                atomicAdd(&acctSh[wid][66 + et], a3);
            }
            __syncwarp();
            int2 seC = iSh[wid][0];
            const float4* upC = (const float4*)&d_u2[seC.x * 256 + lane * 8];
            float4 u0 = upC[0], u1 = upC[1];
            ull aC = *(const ull*)&ea[(size_t)seC.y * 64 + lane * 2];
#pragma unroll 2
            for (int j = 0; j < nc; j++) {
                float4 n0 = make_float4(0, 0, 0, 0), n1 = make_float4(0, 0, 0, 0);
                ull aN = 0;
                if (j + 1 < nc) {
                    int2 seN = iSh[wid][j + 1];
                    const float4* upN = (const float4*)&d_u2[seN.x * 256 + lane * 8];
                    n0 = upN[0]; n1 = upN[1];
                    aN = *(const ull*)&ea[(size_t)seN.y * 64 + lane * 2];
                }
                ull b0 = aSh[wid][j][0], b1 = aSh[wid][j][1];
                ull b2 = aSh[wid][j][2], b3 = aSh[wid][j][3];
                ull p0 = *(ull*)&u0.x, p1 = *(ull*)&u0.z;
                ull p2 = *(ull*)&u1.x, p3 = *(ull*)&u1.z;
                fma2(axu[0][0], p0, b0); fma2(axu[0][1], p1, b0);
                fma2(axu[0][2], p2, b0); fma2(axu[0][3], p3, b0);
                fma2(axu[1][0], p0, b1); fma2(axu[1][1], p1, b1);
                fma2(axu[1][2], p2, b1); fma2(axu[1][3], p3, b1);
                fma2(axu[2][0], p0, b2); fma2(axu[2][1], p1, b2);
                fma2(axu[2][2], p2, b2); fma2(axu[2][3], p3, b2);
                fma2(axu[3][0], p0, b3); fma2(axu[3][1], p1, b3);
                fma2(axu[3][2], p2, b3); fma2(axu[3][3], p3, b3);
                fma2(av[0], aC, b0); fma2(av[1], aC, b1);
                fma2(av[2], aC, b2); fma2(av[3], aC, b3);
                u0 = n0; u1 = n1; aC = aN;
            }
            __syncwarp();
        }
    }
    __syncwarp();
    float* v = &d_v2[(size_t)n * K2P];
#pragma unroll
    for (int h = 0; h < 4; h++) {
#pragma unroll
        for (int q = 0; q < 4; q++)
            *(ull*)&v[h * 256 + lane * 8 + q * 2] = axu[h][q];
        *(ull*)&v[1024 + h * 64 + lane * 2] = av[h];
    }
    for (int i = lane; i < 96; i += 32)
        v[1280 + i] = (i < 88) ? acctSh[wid][i] : 0.f;
}

// ---------------- tf32 mma.sync GEMM (shared template, R13) ----------------
template <int K, int MODE>
__global__ void k_gemmTF(const float* __restrict__ A, const float* __restrict__ B,
                         const float* __restrict__ bias, const float* __restrict__ add,
                         float* __restrict__ C) {
    constexpr int LDA = (MODE == 1) ? LDA1 : K2P;
    __shared__ unsigned As[8][136];
    __shared__ unsigned Bs[8][72];
    int y = blockIdx.y;
    int bm = blockIdx.x * 128;
    int colbase = y * 64;
    const float* Ab = A + ((MODE == 1) ? y * K1H : 0);
    const float* Bb = (MODE == 1) ? (B + y * K1H * 64) : (B + colbase);
    const int ldb = (MODE == 1) ? 64 : 256;
    int tid = threadIdx.x;
    int warp = tid >> 5, lane = tid & 31;
    int g = lane >> 2, tig = lane & 3;
    int lrow = tid & 127, lk = (tid >> 7) * 4;
    int brow = tid >> 4, bcol = (tid & 15) * 4;
    int row = bm + lrow;
    float acc[8][4];
#pragma unroll
    for (int nt = 0; nt < 8; nt++)
#pragma unroll
        for (int j = 0; j < 4; j++) acc[nt][j] = 0.f;

    for (int k0 = 0; k0 < K; k0 += 8) {
        float4 avv = make_float4(0, 0, 0, 0);
        if (row < Nn) avv = *(const float4*)&Ab[(size_t)row * LDA + k0 + lk];
        As[lk + 0][lrow] = to_tf32(avv.x);
        As[lk + 1][lrow] = to_tf32(avv.y);
        As[lk + 2][lrow] = to_tf32(avv.z);
        As[lk + 3][lrow] = to_tf32(avv.w);
        if (tid < 128) {
            float4 bv = *(const float4*)&Bb[(size_t)(k0 + brow) * ldb + bcol];
            Bs[brow][bcol + 0] = to_tf32(bv.x);
            Bs[brow][bcol + 1] = to_tf32(bv.y);
            Bs[brow][bcol + 2] = to_tf32(bv.z);
            Bs[brow][bcol + 3] = to_tf32(bv.w);
        }
        __syncthreads();
        unsigned a0 = As[tig][warp * 16 + g];
        unsigned a1 = As[tig][warp * 16 + g + 8];
        unsigned a2 = As[tig + 4][warp * 16 + g];
        unsigned a3 = As[tig + 4][warp * 16 + g + 8];
#pragma unroll
        for (int nt = 0; nt < 8; nt++) {
            unsigned b0 = Bs[tig][nt * 8 + g];
            unsigned b1 = Bs[tig + 4][nt * 8 + g];
            asm volatile(
                "mma.sync.aligned.m16n8k8.row.col.f32.tf32.tf32.f32 "
                "{%0,%1,%2,%3}, {%4,%5,%6,%7}, {%8,%9}, {%0,%1,%2,%3};"
                : "+f"(acc[nt][0]), "+f"(acc[nt][1]), "+f"(acc[nt][2]), "+f"(acc[nt][3])
                : "r"(a0), "r"(a1), "r"(a2), "r"(a3), "r"(b0), "r"(b1));
        }
        __syncthreads();
    }
#pragma unroll
    for (int nt = 0; nt < 8; nt++) {
        int r0 = bm + warp * 16 + g, r1 = r0 + 8;
        int cA = colbase + nt * 8 + 2 * tig, cB = cA + 1;
        float bA = bias[cA], bB = bias[cB];
        if (r0 < Nn) {
            float vA = acc[nt][0] + bA, vB = acc[nt][1] + bB;
            if (MODE == 1) { vA = fmaxf(vA, 0.f); vB = fmaxf(vB, 0.f); }
            else { vA += add[r0 * 256 + cA]; vB += add[r0 * 256 + cB]; }
            C[r0 * 256 + cA] = vA;
            C[r0 * 256 + cB] = vB;
        }
        if (r1 < Nn) {
            float vA = acc[nt][2] + bA, vB = acc[nt][3] + bB;
            if (MODE == 1) { vA = fmaxf(vA, 0.f); vB = fmaxf(vB, 0.f); }
            else { vA += add[r1 * 256 + cA]; vB += add[r1 * 256 + cB]; }
            C[r1 * 256 + cA] = vA;
            C[r1 * 256 + cB] = vB;
        }
    }
}

// ---------------- launch ----------------
extern "C" void kernel_launch(void* const* d_in, const int* in_sizes, int n_in,
                              void* d_out, int out_size) {
    const float* x    = (const float*)d_in[0];
    const void*  ei   = d_in[1];
    const void*  ntp  = d_in[2];
    const float* ea   = (const float*)d_in[3];
    const void*  etp  = d_in[4];
    const float* W1   = (const float*)d_in[5];
    const float* b1   = (const float*)d_in[6];
    const float* We1  = (const float*)d_in[7];
    const float* nte1 = (const float*)d_in[8];
    const float* ete1 = (const float*)d_in[9];
    const float* as1  = (const float*)d_in[10];
    const float* ad1  = (const float*)d_in[11];
    const float* ag1  = (const float*)d_in[12];
    const float* res1 = (const float*)d_in[13];
    const float* W2   = (const float*)d_in[14];
    const float* b2   = (const float*)d_in[15];
    const float* We2  = (const float*)d_in[16];
    const float* nte2 = (const float*)d_in[17];
    const float* ete2 = (const float*)d_in[18];
    const float* as2  = (const float*)d_in[19];
    const float* ad2  = (const float*)d_in[20];
    const float* ag2  = (const float*)d_in[21];
    float* out = (float*)d_out;

    k_pre<<<PRE_TOT, 256>>>(ei, ntp, etp, W1, as1, ad1, We1, ag1, ete1,
                            W2, as2, ad2, We2, ag2, ete2, res1);
    k_scan<<<1, 1024>>>();
    k_mid<<<MID_TOT, 256>>>(ea, x, nte1);
    k_attn1<<<Nn / 8, 256>>>(ea, x);

    float* h1;  cudaGetSymbolAddress((void**)&h1, d_h1);
    float* v1;  cudaGetSymbolAddress((void**)&v1, d_v1);
    float* w1h; cudaGetSymbolAddress((void**)&w1h, d_W1h);
    float* v2;  cudaGetSymbolAddress((void**)&v2, d_v2);
    float* w2c; cudaGetSymbolAddress((void**)&w2c, d_W2cat);
    dim3 g((Nn + 127) / 128, 4);
    k_gemmTF<K1H, 1><<<g, 256>>>(v1, w1h, b1, nullptr, h1);
    k_ns2<<<(Nn * 32 + 255) / 256, 256>>>(nte2);
    k_attn2<<<Nn / 8, 256>>>(ea);
    k_gemmTF<K2P, 2><<<g, 256>>>(v2, w2c, b2, h1, out);
}

// round 15
// speedup vs baseline: 1.6217x; 1.0324x over previous
#include <cuda_runtime.h>
#include <math.h>

#define Nn 10000
#define Ee 320000
#define K1H 216          // per-head K for layer-1 GEMM
#define LDA1 (4 * K1H)   // 864
#define K2P 1376

// ---------------- static scratch ----------------
__device__ int   d_src[Ee], d_dst[Ee], d_et[Ee], d_nt[Nn];
__device__ int   d_deg[Nn], d_off[Nn + 1], d_cur[Nn];
__device__ int   d_eid[Ee], d_srcS[Ee], d_etS[Ee];
__device__ float d_se1[Ee * 4], d_se2[Ee * 4];
__device__ float d_ssrc[Nn * 4], d_sdst[Nn * 4];
__device__ float d_u1[Nn * 64], d_u2[Nn * 256], d_h1[Nn * 256];
__device__ float d_v1[(size_t)Nn * LDA1], d_v2[(size_t)Nn * K2P];
__device__ float d_wsrc1[256], d_wdst1[256], d_wae1[256], d_etd1[22 * 4];
__device__ float d_wsrc2[1024], d_wdst2[1024], d_wae2[256], d_etd2[22 * 4];
__device__ float d_W1h[4 * K1H * 64], d_W2cat[K2P * 256];

typedef unsigned long long ull;

__device__ __forceinline__ float lrelu(float v) { return v > 0.f ? v : 0.2f * v; }
__device__ __forceinline__ int ldidx(const void* p, long long i, int is64) {
    return is64 ? (int)((const long long*)p)[i] : ((const int*)p)[i];
}
__device__ __forceinline__ ull dup2(float x) {
    ull r;
    asm("mov.b64 %0, {%1, %1};" : "=l"(r) : "r"(__float_as_uint(x)));
    return r;
}
__device__ __forceinline__ void fma2(ull& d, ull a, ull b) {
    asm("fma.rn.f32x2 %0, %1, %2, %0;" : "+l"(d) : "l"(a), "l"(b));
}
__device__ __forceinline__ unsigned to_tf32(float x) {
    unsigned r;
    asm("cvt.rna.tf32.f32 %0, %1;" : "=r"(r) : "f"(x));
    return r;
}
__device__ __forceinline__ float4 logit4(float4 ss, float4 sd, float4 se) {
    float4 l;
    l.x = lrelu(ss.x + sd.x + se.x); l.y = lrelu(ss.y + sd.y + se.y);
    l.z = lrelu(ss.z + sd.z + se.z); l.w = lrelu(ss.w + sd.w + se.w);
    return l;
}
__device__ __forceinline__ float4 warpMax4(float4 v) {
#pragma unroll
    for (int o = 16; o > 0; o >>= 1) {
        v.x = fmaxf(v.x, __shfl_xor_sync(0xffffffffu, v.x, o));
        v.y = fmaxf(v.y, __shfl_xor_sync(0xffffffffu, v.y, o));
        v.z = fmaxf(v.z, __shfl_xor_sync(0xffffffffu, v.z, o));
        v.w = fmaxf(v.w, __shfl_xor_sync(0xffffffffu, v.w, o));
    }
    return v;
}
__device__ __forceinline__ float4 warpSum4(float4 v) {
#pragma unroll
    for (int o = 16; o > 0; o >>= 1) {
        v.x += __shfl_xor_sync(0xffffffffu, v.x, o);
        v.y += __shfl_xor_sync(0xffffffffu, v.y, o);
        v.z += __shfl_xor_sync(0xffffffffu, v.z, o);
        v.w += __shfl_xor_sync(0xffffffffu, v.w, o);
    }
    return v;
}
__device__ __forceinline__ int block_is64(const unsigned int* w) {
    int t = threadIdx.x;
    int bad = 0;
    if (t < 128) bad = (w[2 * (t * 39) + 1] != 0u);
    return __syncthreads_or(bad) ? 0 : 1;
}
__device__ __forceinline__ float wdot(const float* A, const float* B, int len, int lane) {
    float s = 0.f;
    for (int c = lane; c < len; c += 32) s += A[c] * B[c];
#pragma unroll
    for (int o = 16; o > 0; o >>= 1) s += __shfl_xor_sync(0xffffffffu, s, o);
    return s;
}

// ---------------- K1: fused preprocessing ----------------
#define PRE_CONV 1250
#define PRE_PW1  (PRE_CONV + 216)
#define PRE_PW2  (PRE_PW1 + 1376)
#define PRE_TOT  (PRE_PW2 + 406)

__global__ void k_pre(const void* ei, const void* ntp, const void* etp,
                      const float* W1, const float* as1, const float* ad1,
                      const float* We1, const float* ag1, const float* etb1,
                      const float* W2, const float* as2, const float* ad2,
                      const float* We2, const float* ag2, const float* etb2,
                      const float* res1) {
    int b = blockIdx.x, t = threadIdx.x;
    if (b < PRE_CONV) {
        int is64 = block_is64((const unsigned int*)ntp);
        int e = b * 256 + t;
        if (e < Ee) {
            int s = ldidx(ei, e, is64);
            int d2 = ldidx(ei, (long long)Ee + e, is64);
            d_src[e] = s; d_dst[e] = d2; d_et[e] = ldidx(etp, e, is64);
            atomicAdd(&d_deg[d2], 1);
        }
        if (b < 40) { int i = b * 256 + t; if (i < Nn) d_nt[i] = ldidx(ntp, i, is64); }
    } else if (b < PRE_PW1) {
        int j = (b - PRE_CONV) * 256 + t;
        int c = j & 63, hk = j >> 6, h = hk / K1H, k = hk - h * K1H;
        float v = 0.f;
        if (k < 64) v = W1[k * 256 + h * 64 + c];
        else if (k < 128) v = We1[(k - 64) * 256 + h * 64 + c];
        else if (k < 150) v = etb1[(k - 128) * 256 + h * 64 + c];
        else if (k < 214) v = res1[(k - 150) * 256 + h * 64 + c];
        d_W1h[j] = v;
    } else if (b < PRE_PW2) {
        int j = (b - PRE_PW1) * 256 + t;
        int col = j & 255, r = j >> 8;
        float v = 0.f;
        if (r < 1024) { int h = r >> 8, k = r & 255; v = W2[k * 1024 + h * 256 + col] * 0.25f; }
        else if (r < 1280) { int rr = r - 1024, h = rr >> 6, k = rr & 63; v = We2[k * 1024 + h * 256 + col] * 0.25f; }
        else if (r < 1368) { int rr = r - 1280, h = rr / 22, tt = rr % 22; v = etb2[tt * 1024 + h * 256 + col] * 0.25f; }
        d_W2cat[j] = v;
    } else {
        int wo = (b - PRE_PW2) * 8 + (t >> 5);
        int lane = t & 31;
        if (wo < 3248) {
            float s = 0.f;
            float* dst = nullptr;
            if (wo < 256) {
                int h = wo >> 6, k = wo & 63;
                s = wdot(W1 + k * 256 + h * 64, as1 + h * 64, 64, lane);
                dst = &d_wsrc1[wo];
            } else if (wo < 512) {
                int jj = wo - 256, h = jj >> 6, k = jj & 63;
                s = wdot(W1 + k * 256 + h * 64, ad1 + h * 64, 64, lane);
                dst = &d_wdst1[jj];
            } else if (wo < 768) {
                int jj = wo - 512, h = jj >> 6, k = jj & 63;
                s = wdot(We1 + k * 256 + h * 64, ag1 + h * 64, 64, lane);
                dst = &d_wae1[jj];
            } else if (wo < 856) {
                int jj = wo - 768, tt = jj >> 2, h = jj & 3;
                s = wdot(etb1 + tt * 256 + h * 64, ag1 + h * 64, 64, lane);
                dst = &d_etd1[jj];
            } else if (wo < 1880) {
                int jj = wo - 856, h = jj >> 8, k = jj & 255;
                s = wdot(W2 + k * 1024 + h * 256, as2 + h * 256, 256, lane);
                dst = &d_wsrc2[jj];
            } else if (wo < 2904) {
                int jj = wo - 1880, h = jj >> 8, k = jj & 255;
                s = wdot(W2 + k * 1024 + h * 256, ad2 + h * 256, 256, lane);
                dst = &d_wdst2[jj];
            } else if (wo < 3160) {
                int jj = wo - 2904, h = jj >> 6, k = jj & 63;
                s = wdot(We2 + k * 1024 + h * 256, ag2 + h * 256, 256, lane);
                dst = &d_wae2[jj];
            } else {
                int jj = wo - 3160, tt = jj >> 2, h = jj & 3;
                s = wdot(etb2 + tt * 1024 + h * 256, ag2 + h * 256, 256, lane);
                dst = &d_etd2[jj];
            }
            if (lane == 0) *dst = s;
        }
    }
}

// ---------------- K2: scan (+ zero d_deg for replay) ----------------
__global__ void k_scan() {
    __shared__ int wsum[32];
    int t = threadIdx.x, base = t * 10, loc[10], sum = 0;
#pragma unroll
    for (int ii = 0; ii < 10; ii++) {
        int i = base + ii;
        int d = (i < Nn) ? d_deg[i] : 0;
        loc[ii] = d; sum += d;
    }
    int lane = t & 31, w = t >> 5;
    int v = sum;
#pragma unroll
    for (int o = 1; o < 32; o <<= 1) {
        int u = __shfl_up_sync(0xffffffffu, v, o);
        if (lane >= o) v += u;
    }
    if (lane == 31) wsum[w] = v;
    __syncthreads();
    if (w == 0) {
        int s = wsum[lane];
#pragma unroll
        for (int o = 1; o < 32; o <<= 1) {
            int u = __shfl_up_sync(0xffffffffu, s, o);
            if (lane >= o) s += u;
        }
        wsum[lane] = s;
    }
    __syncthreads();
    int run = v - sum + (w ? wsum[w - 1] : 0);
#pragma unroll
    for (int ii = 0; ii < 10; ii++) {
        int i = base + ii;
        if (i < Nn) { d_off[i] = run; d_cur[i] = run; d_deg[i] = 0; run += loc[ii]; }
        else if (i == Nn) d_off[Nn] = run;
    }
}

// ---------------- nscore body ----------------
__device__ __forceinline__ void nscore_one(int gw, int lane, const float* xin,
                                           const float* ntemb, int K,
                                           const float* ws, const float* wd, float* u) {
    int nt = d_nt[gw];
    float ps[4] = {0, 0, 0, 0}, pd[4] = {0, 0, 0, 0};
    for (int k = lane; k < K; k += 32) {
        float v = xin[gw * K + k] + ntemb[nt * K + k];
        u[gw * K + k] = v;
#pragma unroll
        for (int h = 0; h < 4; h++) { ps[h] += v * ws[h * K + k]; pd[h] += v * wd[h * K + k]; }
    }
#pragma unroll
    for (int h = 0; h < 4; h++)
        for (int o = 16; o > 0; o >>= 1) {
            ps[h] += __shfl_xor_sync(0xffffffffu, ps[h], o);
            pd[h] += __shfl_xor_sync(0xffffffffu, pd[h], o);
        }
    if (lane == 0)
#pragma unroll
        for (int h = 0; h < 4; h++) { d_ssrc[gw * 4 + h] = ps[h]; d_sdst[gw * 4 + h] = pd[h]; }
}

// ---------------- K3: fused scatter + nscore1 + edgescore ----------------
#define MID_SCAT 1250
#define MID_NS   (MID_SCAT + 1250)
#define MID_TOT  (MID_NS + 40000)

__global__ void k_mid(const float* __restrict__ ea, const float* __restrict__ x,
                      const float* __restrict__ nte1) {
    int b = blockIdx.x, t = threadIdx.x;
    if (b < MID_SCAT) {
        int e = b * 256 + t;
        if (e < Ee) {
            int p = atomicAdd(&d_cur[d_dst[e]], 1);
            d_eid[p] = e; d_srcS[p] = d_src[e]; d_etS[p] = d_et[e];
        }
    } else if (b < MID_NS) {
        int gw = (b - MID_SCAT) * 8 + (t >> 5);
        if (gw < Nn) nscore_one(gw, t & 31, x, nte1, 64, d_wsrc1, d_wdst1, d_u1);
    } else {
        int e = (b - MID_NS) * 8 + (t >> 5);
        int lane = t & 31;
        float a0 = ea[(size_t)e * 64 + lane];
        float a1 = ea[(size_t)e * 64 + 32 + lane];
        float dd1[4], dd2[4];
#pragma unroll
        for (int h = 0; h < 4; h++) {
            dd1[h] = a0 * d_wae1[h * 64 + lane] + a1 * d_wae1[h * 64 + 32 + lane];
            dd2[h] = a0 * d_wae2[h * 64 + lane] + a1 * d_wae2[h * 64 + 32 + lane];
            for (int o = 16; o > 0; o >>= 1) {
                dd1[h] += __shfl_xor_sync(0xffffffffu, dd1[h], o);
                dd2[h] += __shfl_xor_sync(0xffffffffu, dd2[h], o);
            }
        }
        if (lane == 0) {
            int et = d_et[e];
#pragma unroll
            for (int h = 0; h < 4; h++) {
                d_se1[e * 4 + h] = dd1[h] + d_etd1[et * 4 + h];
                d_se2[e * 4 + h] = dd2[h] + d_etd2[et * 4 + h];
            }
        }
    }
}

// ---- warp softmax stats ----
__device__ __forceinline__ void warp_softmax(const float4* se4, int beg, int end,
                                             int lane, float4 sd, float4& m, float4& rdn) {
    const float4* ssrc4 = (const float4*)d_ssrc;
    float4 mx = make_float4(-1e30f, -1e30f, -1e30f, -1e30f);
    for (int i = beg + lane; i < end; i += 32) {
        float4 l = logit4(ssrc4[d_srcS[i]], sd, se4[d_eid[i]]);
        mx.x = fmaxf(mx.x, l.x); mx.y = fmaxf(mx.y, l.y);
        mx.z = fmaxf(mx.z, l.z); mx.w = fmaxf(mx.w, l.w);
    }
    m = warpMax4(mx);
    float4 sm = make_float4(0, 0, 0, 0);
    for (int i = beg + lane; i < end; i += 32) {
        float4 l = logit4(ssrc4[d_srcS[i]], sd, se4[d_eid[i]]);
        sm.x += __expf(l.x - m.x); sm.y += __expf(l.y - m.y);
        sm.z += __expf(l.z - m.z); sm.w += __expf(l.w - m.w);
    }
    float4 den = warpSum4(sm);
    rdn.x = 1.f / (den.x + 1e-16f); rdn.y = 1.f / (den.y + 1e-16f);
    rdn.z = 1.f / (den.z + 1e-16f); rdn.w = 1.f / (den.w + 1e-16f);
}

// ---------------- K4: warp-per-node layer-1 attention (R6 body, 4 warps/blk) --
__global__ void k_attn1(const float* __restrict__ ea, const float* __restrict__ x) {
    int wid = threadIdx.x >> 5, lane = threadIdx.x & 31;
    int n = blockIdx.x * 4 + wid;
    __shared__ ull  aSh[4][32][4];
    __shared__ int2 iSh[4][32];
    __shared__ float acctSh[4][88];
    for (int i = lane; i < 88; i += 32) acctSh[wid][i] = 0.f;
    __syncwarp();
    int beg = d_off[n], end = d_off[n + 1], nE = end - beg;
    ull ax[4] = {0, 0, 0, 0}, av[4] = {0, 0, 0, 0};
    if (nE > 0) {
        const float4* ssrc4 = (const float4*)d_ssrc;
        const float4* se4 = (const float4*)d_se1;
        float4 sd = ((const float4*)d_sdst)[n];
        float4 m, rdn;
        warp_softmax(se4, beg, end, lane, sd, m, rdn);
        for (int c0 = beg; c0 < end; c0 += 32) {
            int nc = min(32, end - c0);
            if (lane < nc) {
                int i = c0 + lane;
                int s = d_srcS[i], e = d_eid[i], et = d_etS[i];
                float4 l = logit4(ssrc4[s], sd, se4[e]);
                float a0 = __expf(l.x - m.x) * rdn.x, a1 = __expf(l.y - m.y) * rdn.y;
                float a2 = __expf(l.z - m.z) * rdn.z, a3 = __expf(l.w - m.w) * rdn.w;
                aSh[wid][lane][0] = dup2(a0); aSh[wid][lane][1] = dup2(a1);
                aSh[wid][lane][2] = dup2(a2); aSh[wid][lane][3] = dup2(a3);
                iSh[wid][lane] = make_int2(s, e);
                atomicAdd(&acctSh[wid][et], a0);
                atomicAdd(&acctSh[wid][22 + et], a1);
                atomicAdd(&acctSh[wid][44 + et], a2);
                atomicAdd(&acctSh[wid][66 + et], a3);
            }
            __syncwarp();
#pragma unroll 4
            for (int j = 0; j < nc; j++) {
                ull b0 = aSh[wid][j][0], b1 = aSh[wid][j][1];
                ull b2 = aSh[wid][j][2], b3 = aSh[wid][j][3];
                int2 se = iSh[wid][j];
                ull u = *(const ull*)&d_u1[se.x * 64 + lane * 2];
                ull a = *(const ull*)&ea[(size_t)se.y * 64 + lane * 2];
                fma2(ax[0], u, b0); fma2(ax[1], u, b1);
                fma2(ax[2], u, b2); fma2(ax[3], u, b3);
                fma2(av[0], a, b0); fma2(av[1], a, b1);
                fma2(av[2], a, b2); fma2(av[3], a, b3);
            }
            __syncwarp();
        }
    }
    __syncwarp();
    float* v = &d_v1[(size_t)n * LDA1];
    int c = lane * 2;
#pragma unroll
    for (int h = 0; h < 4; h++) {
        *(ull*)&v[h * K1H + c] = ax[h];
        *(ull*)&v[h * K1H + 64 + c] = av[h];
        *(ull*)&v[h * K1H + 150 + c] = *(const ull*)&x[n * 64 + c];
    }
    for (int i = lane; i < 88; i += 32) {
        int hh = i / 22, t2 = i % 22;
        v[hh * K1H + 128 + t2] = acctSh[wid][hh * 22 + t2];
    }
    if (lane < 8) v[(lane >> 1) * K1H + 214 + (lane & 1)] = 0.f;
}

// ---------------- K6: nscore layer 2 ----------------
__global__ void k_ns2(const float* __restrict__ nte2) {
    int gw = (blockIdx.x * blockDim.x + threadIdx.x) >> 5;
    if (gw < Nn) nscore_one(gw, threadIdx.x & 31, d_h1, nte2, 256, d_wsrc2, d_wdst2, d_u2);
}

// ---------------- K7: layer-2 attention (prefetch, 4 warps/blk) --------------
__global__ void k_attn2(const float* __restrict__ ea) {
    int wid = threadIdx.x >> 5, lane = threadIdx.x & 31;
    int n = blockIdx.x * 4 + wid;
    __shared__ ull  aSh[4][32][4];
    __shared__ int2 iSh[4][32];
    __shared__ float acctSh[4][88];
    for (int i = lane; i < 88; i += 32) acctSh[wid][i] = 0.f;
    __syncwarp();
    int beg = d_off[n], end = d_off[n + 1], nE = end - beg;
    ull axu[4][4];
#pragma unroll
    for (int h = 0; h < 4; h++)
#pragma unroll
        for (int q = 0; q < 4; q++) axu[h][q] = 0ull;
    ull av[4] = {0, 0, 0, 0};
    if (nE > 0) {
        const float4* ssrc4 = (const float4*)d_ssrc;
        const float4* se4 = (const float4*)d_se2;
        float4 sd = ((const float4*)d_sdst)[n];
        float4 m, rdn;
        warp_softmax(se4, beg, end, lane, sd, m, rdn);
        for (int c0 = beg; c0 < end; c0 += 32) {
            int nc = min(32, end - c0);
            if (lane < nc) {
                int i = c0 + lane;
                int s = d_srcS[i], e = d_eid[i], et = d_etS[i];
                float4 l = logit4(ssrc4[s], sd, se4[e]);
                float a0 = __expf(l.x - m.x) * rdn.x, a1 = __expf(l.y - m.y) * rdn.y;
                float a2 = __expf(l.z - m.z) * rdn.z, a3 = __expf(l.w - m.w) * rdn.w;
                aSh[wid][lane][0] = dup2(a0); aSh[wid][lane][1] = dup2(a1);
                aSh[wid][lane][2] = dup2(a2); aSh[wid][lane][3] = dup2(a3);
                iSh[wid][lane] = make_int2(s, e);
                atomicAdd(&acctSh[wid][et], a0);
                atomicAdd(&acctSh[wid][22 + et], a1);
                atomicAdd(&acctSh[wid][44 + et], a2);
                atomicAdd(&acctSh[wid][66 + et], a3);
            }
            __syncwarp();
            int2 seC = iSh[wid][0];
            const float4* upC = (const float4*)&d_u2[seC.x * 256 + lane * 8];
            float4 u0 = upC[0], u1 = upC[1];
            ull aC = *(const ull*)&ea[(size_t)seC.y * 64 + lane * 2];
#pragma unroll 2
            for (int j = 0; j < nc; j++) {
                float4 n0 = make_float4(0, 0, 0, 0), n1 = make_float4(0, 0, 0, 0);
                ull aN = 0;
                if (j + 1 < nc) {
                    int2 seN = iSh[wid][j + 1];
                    const float4* upN = (const float4*)&d_u2[seN.x * 256 + lane * 8];
                    n0 = upN[0]; n1 = upN[1];
                    aN = *(const ull*)&ea[(size_t)seN.y * 64 + lane * 2];
                }
                ull b0 = aSh[wid][j][0], b1 = aSh[wid][j][1];
                ull b2 = aSh[wid][j][2], b3 = aSh[wid][j][3];
                ull p0 = *(ull*)&u0.x, p1 = *(ull*)&u0.z;
                ull p2 = *(ull*)&u1.x, p3 = *(ull*)&u1.z;
                fma2(axu[0][0], p0, b0); fma2(axu[0][1], p1, b0);
                fma2(axu[0][2], p2, b0); fma2(axu[0][3], p3, b0);
                fma2(axu[1][0], p0, b1); fma2(axu[1][1], p1, b1);
                fma2(axu[1][2], p2, b1); fma2(axu[1][3], p3, b1);
                fma2(axu[2][0], p0, b2); fma2(axu[2][1], p1, b2);
                fma2(axu[2][2], p2, b2); fma2(axu[2][3], p3, b2);
                fma2(axu[3][0], p0, b3); fma2(axu[3][1], p1, b3);
                fma2(axu[3][2], p2, b3); fma2(axu[3][3], p3, b3);
                fma2(av[0], aC, b0); fma2(av[1], aC, b1);
                fma2(av[2], aC, b2); fma2(av[3], aC, b3);
                u0 = n0; u1 = n1; aC = aN;
            }
            __syncwarp();
        }
    }
    __syncwarp();
    float* v = &d_v2[(size_t)n * K2P];
#pragma unroll
    for (int h = 0; h < 4; h++) {
#pragma unroll
        for (int q = 0; q < 4; q++)
            *(ull*)&v[h * 256 + lane * 8 + q * 2] = axu[h][q];
        *(ull*)&v[1024 + h * 64 + lane * 2] = av[h];
    }
    for (int i = lane; i < 96; i += 32)
        v[1280 + i] = (i < 88) ? acctSh[wid][i] : 0.f;
}

// ---------------- tf32 mma.sync GEMM (shared template, R13) ----------------
template <int K, int MODE>
__global__ void k_gemmTF(const float* __restrict__ A, const float* __restrict__ B,
                         const float* __restrict__ bias, const float* __restrict__ add,
                         float* __restrict__ C) {
    constexpr int LDA = (MODE == 1) ? LDA1 : K2P;
    __shared__ unsigned As[8][136];
    __shared__ unsigned Bs[8][72];
    int y = blockIdx.y;
    int bm = blockIdx.x * 128;
    int colbase = y * 64;
    const float* Ab = A + ((MODE == 1) ? y * K1H : 0);
    const float* Bb = (MODE == 1) ? (B + y * K1H * 64) : (B + colbase);
    const int ldb = (MODE == 1) ? 64 : 256;
    int tid = threadIdx.x;
    int warp = tid >> 5, lane = tid & 31;
    int g = lane >> 2, tig = lane & 3;
    int lrow = tid & 127, lk = (tid >> 7) * 4;
    int brow = tid >> 4, bcol = (tid & 15) * 4;
    int row = bm + lrow;
    float acc[8][4];
#pragma unroll
    for (int nt = 0; nt < 8; nt++)
#pragma unroll
        for (int j = 0; j < 4; j++) acc[nt][j] = 0.f;

    for (int k0 = 0; k0 < K; k0 += 8) {
        float4 avv = make_float4(0, 0, 0, 0);
        if (row < Nn) avv = *(const float4*)&Ab[(size_t)row * LDA + k0 + lk];
        As[lk + 0][lrow] = to_tf32(avv.x);
        As[lk + 1][lrow] = to_tf32(avv.y);
        As[lk + 2][lrow] = to_tf32(avv.z);
        As[lk + 3][lrow] = to_tf32(avv.w);
        if (tid < 128) {
            float4 bv = *(const float4*)&Bb[(size_t)(k0 + brow) * ldb + bcol];
            Bs[brow][bcol + 0] = to_tf32(bv.x);
            Bs[brow][bcol + 1] = to_tf32(bv.y);
            Bs[brow][bcol + 2] = to_tf32(bv.z);
            Bs[brow][bcol + 3] = to_tf32(bv.w);
        }
        __syncthreads();
        unsigned a0 = As[tig][warp * 16 + g];
        unsigned a1 = As[tig][warp * 16 + g + 8];
        unsigned a2 = As[tig + 4][warp * 16 + g];
        unsigned a3 = As[tig + 4][warp * 16 + g + 8];
#pragma unroll
        for (int nt = 0; nt < 8; nt++) {
            unsigned b0 = Bs[tig][nt * 8 + g];
            unsigned b1 = Bs[tig + 4][nt * 8 + g];
            asm volatile(
                "mma.sync.aligned.m16n8k8.row.col.f32.tf32.tf32.f32 "
                "{%0,%1,%2,%3}, {%4,%5,%6,%7}, {%8,%9}, {%0,%1,%2,%3};"
                : "+f"(acc[nt][0]), "+f"(acc[nt][1]), "+f"(acc[nt][2]), "+f"(acc[nt][3])
                : "r"(a0), "r"(a1), "r"(a2), "r"(a3), "r"(b0), "r"(b1));
        }
        __syncthreads();
    }
#pragma unroll
    for (int nt = 0; nt < 8; nt++) {
        int r0 = bm + warp * 16 + g, r1 = r0 + 8;
        int cA = colbase + nt * 8 + 2 * tig, cB = cA + 1;
        float bA = bias[cA], bB = bias[cB];
        if (r0 < Nn) {
            float vA = acc[nt][0] + bA, vB = acc[nt][1] + bB;
            if (MODE == 1) { vA = fmaxf(vA, 0.f); vB = fmaxf(vB, 0.f); }
            else { vA += add[r0 * 256 + cA]; vB += add[r0 * 256 + cB]; }
            C[r0 * 256 + cA] = vA;
            C[r0 * 256 + cB] = vB;
        }
        if (r1 < Nn) {
            float vA = acc[nt][2] + bA, vB = acc[nt][3] + bB;
            if (MODE == 1) { vA = fmaxf(vA, 0.f); vB = fmaxf(vB, 0.f); }
            else { vA += add[r1 * 256 + cA]; vB += add[r1 * 256 + cB]; }
            C[r1 * 256 + cA] = vA;
            C[r1 * 256 + cB] = vB;
        }
    }
}

// ---------------- launch ----------------
extern "C" void kernel_launch(void* const* d_in, const int* in_sizes, int n_in,
                              void* d_out, int out_size) {
    const float* x    = (const float*)d_in[0];
    const void*  ei   = d_in[1];
    const void*  ntp  = d_in[2];
    const float* ea   = (const float*)d_in[3];
    const void*  etp  = d_in[4];
    const float* W1   = (const float*)d_in[5];
    const float* b1   = (const float*)d_in[6];
    const float* We1  = (const float*)d_in[7];
    const float* nte1 = (const float*)d_in[8];
    const float* ete1 = (const float*)d_in[9];
    const float* as1  = (const float*)d_in[10];
    const float* ad1  = (const float*)d_in[11];
    const float* ag1  = (const float*)d_in[12];
    const float* res1 = (const float*)d_in[13];
    const float* W2   = (const float*)d_in[14];
    const float* b2   = (const float*)d_in[15];
    const float* We2  = (const float*)d_in[16];
    const float* nte2 = (const float*)d_in[17];
    const float* ete2 = (const float*)d_in[18];
    const float* as2  = (const float*)d_in[19];
    const float* ad2  = (const float*)d_in[20];
    const float* ag2  = (const float*)d_in[21];
    float* out = (float*)d_out;

    k_pre<<<PRE_TOT, 256>>>(ei, ntp, etp, W1, as1, ad1, We1, ag1, ete1,
                            W2, as2, ad2, We2, ag2, ete2, res1);
    k_scan<<<1, 1024>>>();
    k_mid<<<MID_TOT, 256>>>(ea, x, nte1);
    k_attn1<<<Nn / 4, 128>>>(ea, x);

    float* h1;  cudaGetSymbolAddress((void**)&h1, d_h1);
    float* v1;  cudaGetSymbolAddress((void**)&v1, d_v1);
    float* w1h; cudaGetSymbolAddress((void**)&w1h, d_W1h);
    float* v2;  cudaGetSymbolAddress((void**)&v2, d_v2);
    float* w2c; cudaGetSymbolAddress((void**)&w2c, d_W2cat);
    dim3 g((Nn + 127) / 128, 4);
    k_gemmTF<K1H, 1><<<g, 256>>>(v1, w1h, b1, nullptr, h1);
    k_ns2<<<(Nn * 32 + 255) / 256, 256>>>(nte2);
    k_attn2<<<Nn / 4, 128>>>(ea);
    k_gemmTF<K2P, 2><<<g, 256>>>(v2, w2c, b2, h1, out);
}

// round 16
// speedup vs baseline: 1.7613x; 1.0861x over previous
#include <cuda_runtime.h>
#include <math.h>

#define Nn 10000
#define Ee 320000
#define K1H 216          // per-head K for layer-1 GEMM
#define LDA1 (4 * K1H)   // 864
#define K2P 1376

// ---------------- static scratch ----------------
__device__ int   d_src[Ee], d_dst[Ee], d_et[Ee], d_nt[Nn];
__device__ int   d_deg[Nn], d_off[Nn + 1], d_cur[Nn];
__device__ int   d_eid[Ee], d_srcS[Ee], d_etS[Ee];
__device__ float d_se1[Ee * 4], d_se2[Ee * 4];
__device__ float d_ssrc[Nn * 4], d_sdst[Nn * 4];
__device__ float d_u1[Nn * 64], d_u2[Nn * 256], d_h1[Nn * 256];
__device__ float d_v1[(size_t)Nn * LDA1], d_v2[(size_t)Nn * K2P];
__device__ float d_wsrc1[256], d_wdst1[256], d_wae1[256], d_etd1[22 * 4];
__device__ float d_wsrc2[1024], d_wdst2[1024], d_wae2[256], d_etd2[22 * 4];
__device__ float d_W1h[4 * K1H * 64], d_W2cat[K2P * 256];

typedef unsigned long long ull;

__device__ __forceinline__ float lrelu(float v) { return v > 0.f ? v : 0.2f * v; }
__device__ __forceinline__ int ldidx(const void* p, long long i, int is64) {
    return is64 ? (int)((const long long*)p)[i] : ((const int*)p)[i];
}
__device__ __forceinline__ ull dup2(float x) {
    ull r;
    asm("mov.b64 %0, {%1, %1};" : "=l"(r) : "r"(__float_as_uint(x)));
    return r;
}
__device__ __forceinline__ void fma2(ull& d, ull a, ull b) {
    asm("fma.rn.f32x2 %0, %1, %2, %0;" : "+l"(d) : "l"(a), "l"(b));
}
__device__ __forceinline__ unsigned to_tf32(float x) {
    unsigned r;
    asm("cvt.rna.tf32.f32 %0, %1;" : "=r"(r) : "f"(x));
    return r;
}
__device__ __forceinline__ float4 logit4(float4 ss, float4 sd, float4 se) {
    float4 l;
    l.x = lrelu(ss.x + sd.x + se.x); l.y = lrelu(ss.y + sd.y + se.y);
    l.z = lrelu(ss.z + sd.z + se.z); l.w = lrelu(ss.w + sd.w + se.w);
    return l;
}
__device__ __forceinline__ float4 warpMax4(float4 v) {
#pragma unroll
    for (int o = 16; o > 0; o >>= 1) {
        v.x = fmaxf(v.x, __shfl_xor_sync(0xffffffffu, v.x, o));
        v.y = fmaxf(v.y, __shfl_xor_sync(0xffffffffu, v.y, o));
        v.z = fmaxf(v.z, __shfl_xor_sync(0xffffffffu, v.z, o));
        v.w = fmaxf(v.w, __shfl_xor_sync(0xffffffffu, v.w, o));
    }
    return v;
}
__device__ __forceinline__ float4 warpSum4(float4 v) {
#pragma unroll
    for (int o = 16; o > 0; o >>= 1) {
        v.x += __shfl_xor_sync(0xffffffffu, v.x, o);
        v.y += __shfl_xor_sync(0xffffffffu, v.y, o);
        v.z += __shfl_xor_sync(0xffffffffu, v.z, o);
        v.w += __shfl_xor_sync(0xffffffffu, v.w, o);
    }
    return v;
}
__device__ __forceinline__ int block_is64(const unsigned int* w) {
    int t = threadIdx.x;
    int bad = 0;
    if (t < 128) bad = (w[2 * (t * 39) + 1] != 0u);
    return __syncthreads_or(bad) ? 0 : 1;
}
__device__ __forceinline__ float wdot(const float* A, const float* B, int len, int lane) {
    float s = 0.f;
    for (int c = lane; c < len; c += 32) s += A[c] * B[c];
#pragma unroll
    for (int o = 16; o > 0; o >>= 1) s += __shfl_xor_sync(0xffffffffu, s, o);
    return s;
}
__device__ __forceinline__ float dot8(float4 a0, float4 a1, float4 b0, float4 b1) {
    return a0.x * b0.x + a0.y * b0.y + a0.z * b0.z + a0.w * b0.w +
           a1.x * b1.x + a1.y * b1.y + a1.z * b1.z + a1.w * b1.w;
}

// ---------------- K1: fused preprocessing ----------------
#define PRE_CONV 1250
#define PRE_PW1  (PRE_CONV + 216)
#define PRE_PW2  (PRE_PW1 + 1376)
#define PRE_TOT  (PRE_PW2 + 406)

__global__ void k_pre(const void* ei, const void* ntp, const void* etp,
                      const float* W1, const float* as1, const float* ad1,
                      const float* We1, const float* ag1, const float* etb1,
                      const float* W2, const float* as2, const float* ad2,
                      const float* We2, const float* ag2, const float* etb2,
                      const float* res1) {
    int b = blockIdx.x, t = threadIdx.x;
    if (b < PRE_CONV) {
        int is64 = block_is64((const unsigned int*)ntp);
        int e = b * 256 + t;
        if (e < Ee) {
            int s = ldidx(ei, e, is64);
            int d2 = ldidx(ei, (long long)Ee + e, is64);
            d_src[e] = s; d_dst[e] = d2; d_et[e] = ldidx(etp, e, is64);
            atomicAdd(&d_deg[d2], 1);
        }
        if (b < 40) { int i = b * 256 + t; if (i < Nn) d_nt[i] = ldidx(ntp, i, is64); }
    } else if (b < PRE_PW1) {
        int j = (b - PRE_CONV) * 256 + t;
        int c = j & 63, hk = j >> 6, h = hk / K1H, k = hk - h * K1H;
        float v = 0.f;
        if (k < 64) v = W1[k * 256 + h * 64 + c];
        else if (k < 128) v = We1[(k - 64) * 256 + h * 64 + c];
        else if (k < 150) v = etb1[(k - 128) * 256 + h * 64 + c];
        else if (k < 214) v = res1[(k - 150) * 256 + h * 64 + c];
        d_W1h[j] = v;
    } else if (b < PRE_PW2) {
        int j = (b - PRE_PW1) * 256 + t;
        int col = j & 255, r = j >> 8;
        float v = 0.f;
        if (r < 1024) { int h = r >> 8, k = r & 255; v = W2[k * 1024 + h * 256 + col] * 0.25f; }
        else if (r < 1280) { int rr = r - 1024, h = rr >> 6, k = rr & 63; v = We2[k * 1024 + h * 256 + col] * 0.25f; }
        else if (r < 1368) { int rr = r - 1280, h = rr / 22, tt = rr % 22; v = etb2[tt * 1024 + h * 256 + col] * 0.25f; }
        d_W2cat[j] = v;
    } else {
        int wo = (b - PRE_PW2) * 8 + (t >> 5);
        int lane = t & 31;
        if (wo < 3248) {
            float s = 0.f;
            float* dst = nullptr;
            if (wo < 256) {
                int h = wo >> 6, k = wo & 63;
                s = wdot(W1 + k * 256 + h * 64, as1 + h * 64, 64, lane);
                dst = &d_wsrc1[wo];
            } else if (wo < 512) {
                int jj = wo - 256, h = jj >> 6, k = jj & 63;
                s = wdot(W1 + k * 256 + h * 64, ad1 + h * 64, 64, lane);
                dst = &d_wdst1[jj];
            } else if (wo < 768) {
                int jj = wo - 512, h = jj >> 6, k = jj & 63;
                s = wdot(We1 + k * 256 + h * 64, ag1 + h * 64, 64, lane);
                dst = &d_wae1[jj];
            } else if (wo < 856) {
                int jj = wo - 768, tt = jj >> 2, h = jj & 3;
                s = wdot(etb1 + tt * 256 + h * 64, ag1 + h * 64, 64, lane);
                dst = &d_etd1[jj];
            } else if (wo < 1880) {
                int jj = wo - 856, h = jj >> 8, k = jj & 255;
                s = wdot(W2 + k * 1024 + h * 256, as2 + h * 256, 256, lane);
                dst = &d_wsrc2[jj];
            } else if (wo < 2904) {
                int jj = wo - 1880, h = jj >> 8, k = jj & 255;
                s = wdot(W2 + k * 1024 + h * 256, ad2 + h * 256, 256, lane);
                dst = &d_wdst2[jj];
            } else if (wo < 3160) {
                int jj = wo - 2904, h = jj >> 6, k = jj & 63;
                s = wdot(We2 + k * 1024 + h * 256, ag2 + h * 256, 256, lane);
                dst = &d_wae2[jj];
            } else {
                int jj = wo - 3160, tt = jj >> 2, h = jj & 3;
                s = wdot(etb2 + tt * 1024 + h * 256, ag2 + h * 256, 256, lane);
                dst = &d_etd2[jj];
            }
            if (lane == 0) *dst = s;
        }
    }
}

// ---------------- K2: scan (+ zero d_deg for replay) ----------------
__global__ void k_scan() {
    __shared__ int wsum[32];
    int t = threadIdx.x, base = t * 10, loc[10], sum = 0;
#pragma unroll
    for (int ii = 0; ii < 10; ii++) {
        int i = base + ii;
        int d = (i < Nn) ? d_deg[i] : 0;
        loc[ii] = d; sum += d;
    }
    int lane = t & 31, w = t >> 5;
    int v = sum;
#pragma unroll
    for (int o = 1; o < 32; o <<= 1) {
        int u = __shfl_up_sync(0xffffffffu, v, o);
        if (lane >= o) v += u;
    }
    if (lane == 31) wsum[w] = v;
    __syncthreads();
    if (w == 0) {
        int s = wsum[lane];
#pragma unroll
        for (int o = 1; o < 32; o <<= 1) {
            int u = __shfl_up_sync(0xffffffffu, s, o);
            if (lane >= o) s += u;
        }
        wsum[lane] = s;
    }
    __syncthreads();
    int run = v - sum + (w ? wsum[w - 1] : 0);
#pragma unroll
    for (int ii = 0; ii < 10; ii++) {
        int i = base + ii;
        if (i < Nn) { d_off[i] = run; d_cur[i] = run; d_deg[i] = 0; run += loc[ii]; }
        else if (i == Nn) d_off[Nn] = run;
    }
}

// ---------------- nscore body ----------------
__device__ __forceinline__ void nscore_one(int gw, int lane, const float* xin,
                                           const float* ntemb, int K,
                                           const float* ws, const float* wd, float* u) {
    int nt = d_nt[gw];
    float ps[4] = {0, 0, 0, 0}, pd[4] = {0, 0, 0, 0};
    for (int k = lane; k < K; k += 32) {
        float v = xin[gw * K + k] + ntemb[nt * K + k];
        u[gw * K + k] = v;
#pragma unroll
        for (int h = 0; h < 4; h++) { ps[h] += v * ws[h * K + k]; pd[h] += v * wd[h * K + k]; }
    }
#pragma unroll
    for (int h = 0; h < 4; h++)
        for (int o = 16; o > 0; o >>= 1) {
            ps[h] += __shfl_xor_sync(0xffffffffu, ps[h], o);
            pd[h] += __shfl_xor_sync(0xffffffffu, pd[h], o);
        }
    if (lane == 0)
#pragma unroll
        for (int h = 0; h < 4; h++) { d_ssrc[gw * 4 + h] = ps[h]; d_sdst[gw * 4 + h] = pd[h]; }
}

// ---------------- K3: fused scatter + nscore1 + edgescore(8-lane groups) -----
#define MID_SCAT 1250
#define MID_NS   (MID_SCAT + 1250)
#define MID_TOT  (MID_NS + 10000)   // edgescore: 32 edges per block

__global__ void k_mid(const float* __restrict__ ea, const float* __restrict__ x,
                      const float* __restrict__ nte1) {
    int b = blockIdx.x, t = threadIdx.x;
    if (b < MID_SCAT) {
        int e = b * 256 + t;
        if (e < Ee) {
            int p = atomicAdd(&d_cur[d_dst[e]], 1);
            d_eid[p] = e; d_srcS[p] = d_src[e]; d_etS[p] = d_et[e];
        }
    } else if (b < MID_NS) {
        int gw = (b - MID_SCAT) * 8 + (t >> 5);
        if (gw < Nn) nscore_one(gw, t & 31, x, nte1, 64, d_wsrc1, d_wdst1, d_u1);
    } else {
        // 8 lanes per edge; 4 edges per warp; 32 edges per block
        int lane = t & 31;
        int sub = lane & 7;                       // slice within edge row
        int e = (b - MID_NS) * 32 + (t >> 3);     // edge id (original order)
        const float4* row = (const float4*)&ea[(size_t)e * 64 + sub * 8];
        float4 r0 = row[0], r1 = row[1];
        float dd[8];
#pragma unroll
        for (int h = 0; h < 4; h++) {
            const float4* w1p = (const float4*)&d_wae1[h * 64 + sub * 8];
            dd[h] = dot8(r0, r1, w1p[0], w1p[1]);
            const float4* w2p = (const float4*)&d_wae2[h * 64 + sub * 8];
            dd[4 + h] = dot8(r0, r1, w2p[0], w2p[1]);
        }
#pragma unroll
        for (int o = 4; o >= 1; o >>= 1)
#pragma unroll
            for (int i = 0; i < 8; i++)
                dd[i] += __shfl_xor_sync(0xffffffffu, dd[i], o);
        // lanes 0-3 of each group write se1 heads, lanes 4-7 write se2 heads
        int et = d_et[e];
        if (sub < 4) d_se1[e * 4 + sub] = dd[sub] + d_etd1[et * 4 + sub];
        else d_se2[e * 4 + (sub - 4)] = dd[sub] + d_etd2[et * 4 + (sub - 4)];
    }
}

// ---- warp softmax stats ----
__device__ __forceinline__ void warp_softmax(const float4* se4, int beg, int end,
                                             int lane, float4 sd, float4& m, float4& rdn) {
    const float4* ssrc4 = (const float4*)d_ssrc;
    float4 mx = make_float4(-1e30f, -1e30f, -1e30f, -1e30f);
    for (int i = beg + lane; i < end; i += 32) {
        float4 l = logit4(ssrc4[d_srcS[i]], sd, se4[d_eid[i]]);
        mx.x = fmaxf(mx.x, l.x); mx.y = fmaxf(mx.y, l.y);
        mx.z = fmaxf(mx.z, l.z); mx.w = fmaxf(mx.w, l.w);
    }
    m = warpMax4(mx);
    float4 sm = make_float4(0, 0, 0, 0);
    for (int i = beg + lane; i < end; i += 32) {
        float4 l = logit4(ssrc4[d_srcS[i]], sd, se4[d_eid[i]]);
        sm.x += __expf(l.x - m.x); sm.y += __expf(l.y - m.y);
        sm.z += __expf(l.z - m.z); sm.w += __expf(l.w - m.w);
    }
    float4 den = warpSum4(sm);
    rdn.x = 1.f / (den.x + 1e-16f); rdn.y = 1.f / (den.y + 1e-16f);
    rdn.z = 1.f / (den.z + 1e-16f); rdn.w = 1.f / (den.w + 1e-16f);
}

// ---------------- K4: warp-per-node layer-1 attention (R6 body, 4 warps/blk) --
__global__ void k_attn1(const float* __restrict__ ea, const float* __restrict__ x) {
    int wid = threadIdx.x >> 5, lane = threadIdx.x & 31;
    int n = blockIdx.x * 4 + wid;
    __shared__ ull  aSh[4][32][4];
    __shared__ int2 iSh[4][32];
    __shared__ float acctSh[4][88];
    for (int i = lane; i < 88; i += 32) acctSh[wid][i] = 0.f;
    __syncwarp();
    int beg = d_off[n], end = d_off[n + 1], nE = end - beg;
    ull ax[4] = {0, 0, 0, 0}, av[4] = {0, 0, 0, 0};
    if (nE > 0) {
        const float4* ssrc4 = (const float4*)d_ssrc;
        const float4* se4 = (const float4*)d_se1;
        float4 sd = ((const float4*)d_sdst)[n];
        float4 m, rdn;
        warp_softmax(se4, beg, end, lane, sd, m, rdn);
        for (int c0 = beg; c0 < end; c0 += 32) {
            int nc = min(32, end - c0);
            if (lane < nc) {
                int i = c0 + lane;
                int s = d_srcS[i], e = d_eid[i], et = d_etS[i];
                float4 l = logit4(ssrc4[s], sd, se4[e]);
                float a0 = __expf(l.x - m.x) * rdn.x, a1 = __expf(l.y - m.y) * rdn.y;
                float a2 = __expf(l.z - m.z) * rdn.z, a3 = __expf(l.w - m.w) * rdn.w;
                aSh[wid][lane][0] = dup2(a0); aSh[wid][lane][1] = dup2(a1);
                aSh[wid][lane][2] = dup2(a2); aSh[wid][lane][3] = dup2(a3);
                iSh[wid][lane] = make_int2(s, e);
                atomicAdd(&acctSh[wid][et], a0);
                atomicAdd(&acctSh[wid][22 + et], a1);
                atomicAdd(&acctSh[wid][44 + et], a2);
                atomicAdd(&acctSh[wid][66 + et], a3);
            }
            __syncwarp();
#pragma unroll 4
            for (int j = 0; j < nc; j++) {
                ull b0 = aSh[wid][j][0], b1 = aSh[wid][j][1];
                ull b2 = aSh[wid][j][2], b3 = aSh[wid][j][3];
                int2 se = iSh[wid][j];
                ull u = *(const ull*)&d_u1[se.x * 64 + lane * 2];
                ull a = *(const ull*)&ea[(size_t)se.y * 64 + lane * 2];
                fma2(ax[0], u, b0); fma2(ax[1], u, b1);
                fma2(ax[2], u, b2); fma2(ax[3], u, b3);
                fma2(av[0], a, b0); fma2(av[1], a, b1);
                fma2(av[2], a, b2); fma2(av[3], a, b3);
            }
            __syncwarp();
        }
    }
    __syncwarp();
    float* v = &d_v1[(size_t)n * LDA1];
    int c = lane * 2;
#pragma unroll
    for (int h = 0; h < 4; h++) {
        *(ull*)&v[h * K1H + c] = ax[h];
        *(ull*)&v[h * K1H + 64 + c] = av[h];
        *(ull*)&v[h * K1H + 150 + c] = *(const ull*)&x[n * 64 + c];
    }
    for (int i = lane; i < 88; i += 32) {
        int hh = i / 22, t2 = i % 22;
        v[hh * K1H + 128 + t2] = acctSh[wid][hh * 22 + t2];
    }
    if (lane < 8) v[(lane >> 1) * K1H + 214 + (lane & 1)] = 0.f;
}

// ---------------- K6: nscore layer 2 ----------------
__global__ void k_ns2(const float* __restrict__ nte2) {
    int gw = (blockIdx.x * blockDim.x + threadIdx.x) >> 5;
    if (gw < Nn) nscore_one(gw, threadIdx.x & 31, d_h1, nte2, 256, d_wsrc2, d_wdst2, d_u2);
}

// ---------------- K7: layer-2 attention (prefetch, 4 warps/blk) --------------
__global__ void k_attn2(const float* __restrict__ ea) {
    int wid = threadIdx.x >> 5, lane = threadIdx.x & 31;
    int n = blockIdx.x * 4 + wid;
    __shared__ ull  aSh[4][32][4];
    __shared__ int2 iSh[4][32];
    __shared__ float acctSh[4][88];
    for (int i = lane; i < 88; i += 32) acctSh[wid][i] = 0.f;
    __syncwarp();
    int beg = d_off[n], end = d_off[n + 1], nE = end - beg;
    ull axu[4][4];
#pragma unroll
    for (int h = 0; h < 4; h++)
#pragma unroll
        for (int q = 0; q < 4; q++) axu[h][q] = 0ull;
    ull av[4] = {0, 0, 0, 0};
    if (nE > 0) {
        const float4* ssrc4 = (const float4*)d_ssrc;
        const float4* se4 = (const float4*)d_se2;
        float4 sd = ((const float4*)d_sdst)[n];
        float4 m, rdn;
        warp_softmax(se4, beg, end, lane, sd, m, rdn);
        for (int c0 = beg; c0 < end; c0 += 32) {
            int nc = min(32, end - c0);
            if (lane < nc) {
                int i = c0 + lane;
                int s = d_srcS[i], e = d_eid[i], et = d_etS[i];
                float4 l = logit4(ssrc4[s], sd, se4[e]);
                float a0 = __expf(l.x - m.x) * rdn.x, a1 = __expf(l.y - m.y) * rdn.y;
                float a2 = __expf(l.z - m.z) * rdn.z, a3 = __expf(l.w - m.w) * rdn.w;
                aSh[wid][lane][0] = dup2(a0); aSh[wid][lane][1] = dup2(a1);
                aSh[wid][lane][2] = dup2(a2); aSh[wid][lane][3] = dup2(a3);
                iSh[wid][lane] = make_int2(s, e);
                atomicAdd(&acctSh[wid][et], a0);
                atomicAdd(&acctSh[wid][22 + et], a1);
                atomicAdd(&acctSh[wid][44 + et], a2);
                atomicAdd(&acctSh[wid][66 + et], a3);
            }
            __syncwarp();
            int2 seC = iSh[wid][0];
            const float4* upC = (const float4*)&d_u2[seC.x * 256 + lane * 8];
            float4 u0 = upC[0], u1 = upC[1];
            ull aC = *(const ull*)&ea[(size_t)seC.y * 64 + lane * 2];
#pragma unroll 2
            for (int j = 0; j < nc; j++) {
                float4 n0 = make_float4(0, 0, 0, 0), n1 = make_float4(0, 0, 0, 0);
                ull aN = 0;
                if (j + 1 < nc) {
                    int2 seN = iSh[wid][j + 1];
                    const float4* upN = (const float4*)&d_u2[seN.x * 256 + lane * 8];
                    n0 = upN[0]; n1 = upN[1];
                    aN = *(const ull*)&ea[(size_t)seN.y * 64 + lane * 2];
                }
                ull b0 = aSh[wid][j][0], b1 = aSh[wid][j][1];
                ull b2 = aSh[wid][j][2], b3 = aSh[wid][j][3];
                ull p0 = *(ull*)&u0.x, p1 = *(ull*)&u0.z;
                ull p2 = *(ull*)&u1.x, p3 = *(ull*)&u1.z;
                fma2(axu[0][0], p0, b0); fma2(axu[0][1], p1, b0);
                fma2(axu[0][2], p2, b0); fma2(axu[0][3], p3, b0);
                fma2(axu[1][0], p0, b1); fma2(axu[1][1], p1, b1);
                fma2(axu[1][2], p2, b1); fma2(axu[1][3], p3, b1);
                fma2(axu[2][0], p0, b2); fma2(axu[2][1], p1, b2);
                fma2(axu[2][2], p2, b2); fma2(axu[2][3], p3, b2);
                fma2(axu[3][0], p0, b3); fma2(axu[3][1], p1, b3);
                fma2(axu[3][2], p2, b3); fma2(axu[3][3], p3, b3);
                fma2(av[0], aC, b0); fma2(av[1], aC, b1);
                fma2(av[2], aC, b2); fma2(av[3], aC, b3);
                u0 = n0; u1 = n1; aC = aN;
            }
            __syncwarp();
        }
    }
    __syncwarp();
    float* v = &d_v2[(size_t)n * K2P];
#pragma unroll
    for (int h = 0; h < 4; h++) {
#pragma unroll
        for (int q = 0; q < 4; q++)
            *(ull*)&v[h * 256 + lane * 8 + q * 2] = axu[h][q];
        *(ull*)&v[1024 + h * 64 + lane * 2] = av[h];
    }
    for (int i = lane; i < 96; i += 32)
        v[1280 + i] = (i < 88) ? acctSh[wid][i] : 0.f;
}

// ---------------- tf32 mma.sync GEMM (shared template, R13) ----------------
template <int K, int MODE>
__global__ void k_gemmTF(const float* __restrict__ A, const float* __restrict__ B,
                         const float* __restrict__ bias, const float* __restrict__ add,
                         float* __restrict__ C) {
    constexpr int LDA = (MODE == 1) ? LDA1 : K2P;
    __shared__ unsigned As[8][136];
    __shared__ unsigned Bs[8][72];
    int y = blockIdx.y;
    int bm = blockIdx.x * 128;
    int colbase = y * 64;
    const float* Ab = A + ((MODE == 1) ? y * K1H : 0);
    const float* Bb = (MODE == 1) ? (B + y * K1H * 64) : (B + colbase);
    const int ldb = (MODE == 1) ? 64 : 256;
    int tid = threadIdx.x;
    int warp = tid >> 5, lane = tid & 31;
    int g = lane >> 2, tig = lane & 3;
    int lrow = tid & 127, lk = (tid >> 7) * 4;
    int brow = tid >> 4, bcol = (tid & 15) * 4;
    int row = bm + lrow;
    float acc[8][4];
#pragma unroll
    for (int nt = 0; nt < 8; nt++)
#pragma unroll
        for (int j = 0; j < 4; j++) acc[nt][j] = 0.f;

    for (int k0 = 0; k0 < K; k0 += 8) {
        float4 avv = make_float4(0, 0, 0, 0);
        if (row < Nn) avv = *(const float4*)&Ab[(size_t)row * LDA + k0 + lk];
        As[lk + 0][lrow] = to_tf32(avv.x);
        As[lk + 1][lrow] = to_tf32(avv.y);
        As[lk + 2][lrow] = to_tf32(avv.z);
        As[lk + 3][lrow] = to_tf32(avv.w);
        if (tid < 128) {
            float4 bv = *(const float4*)&Bb[(size_t)(k0 + brow) * ldb + bcol];
            Bs[brow][bcol + 0] = to_tf32(bv.x);
            Bs[brow][bcol + 1] = to_tf32(bv.y);
            Bs[brow][bcol + 2] = to_tf32(bv.z);
            Bs[brow][bcol + 3] = to_tf32(bv.w);
        }
        __syncthreads();
        unsigned a0 = As[tig][warp * 16 + g];
        unsigned a1 = As[tig][warp * 16 + g + 8];
        unsigned a2 = As[tig + 4][warp * 16 + g];
        unsigned a3 = As[tig + 4][warp * 16 + g + 8];
#pragma unroll
        for (int nt = 0; nt < 8; nt++) {
            unsigned b0 = Bs[tig][nt * 8 + g];
            unsigned b1 = Bs[tig + 4][nt * 8 + g];
            asm volatile(
                "mma.sync.aligned.m16n8k8.row.col.f32.tf32.tf32.f32 "
                "{%0,%1,%2,%3}, {%4,%5,%6,%7}, {%8,%9}, {%0,%1,%2,%3};"
                : "+f"(acc[nt][0]), "+f"(acc[nt][1]), "+f"(acc[nt][2]), "+f"(acc[nt][3])
                : "r"(a0), "r"(a1), "r"(a2), "r"(a3), "r"(b0), "r"(b1));
        }
        __syncthreads();
    }
#pragma unroll
    for (int nt = 0; nt < 8; nt++) {
        int r0 = bm + warp * 16 + g, r1 = r0 + 8;
        int cA = colbase + nt * 8 + 2 * tig, cB = cA + 1;
        float bA = bias[cA], bB = bias[cB];
        if (r0 < Nn) {
            float vA = acc[nt][0] + bA, vB = acc[nt][1] + bB;
            if (MODE == 1) { vA = fmaxf(vA, 0.f); vB = fmaxf(vB, 0.f); }
            else { vA += add[r0 * 256 + cA]; vB += add[r0 * 256 + cB]; }
            C[r0 * 256 + cA] = vA;
            C[r0 * 256 + cB] = vB;
        }
        if (r1 < Nn) {
            float vA = acc[nt][2] + bA, vB = acc[nt][3] + bB;
            if (MODE == 1) { vA = fmaxf(vA, 0.f); vB = fmaxf(vB, 0.f); }
            else { vA += add[r1 * 256 + cA]; vB += add[r1 * 256 + cB]; }
            C[r1 * 256 + cA] = vA;
            C[r1 * 256 + cB] = vB;
        }
    }
}

// ---------------- launch ----------------
extern "C" void kernel_launch(void* const* d_in, const int* in_sizes, int n_in,
                              void* d_out, int out_size) {
    const float* x    = (const float*)d_in[0];
    const void*  ei   = d_in[1];
    const void*  ntp  = d_in[2];
    const float* ea   = (const float*)d_in[3];
    const void*  etp  = d_in[4];
    const float* W1   = (const float*)d_in[5];
    const float* b1   = (const float*)d_in[6];
    const float* We1  = (const float*)d_in[7];
    const float* nte1 = (const float*)d_in[8];
    const float* ete1 = (const float*)d_in[9];
    const float* as1  = (const float*)d_in[10];
    const float* ad1  = (const float*)d_in[11];
    const float* ag1  = (const float*)d_in[12];
    const float* res1 = (const float*)d_in[13];
    const float* W2   = (const float*)d_in[14];
    const float* b2   = (const float*)d_in[15];
    const float* We2  = (const float*)d_in[16];
    const float* nte2 = (const float*)d_in[17];
    const float* ete2 = (const float*)d_in[18];
    const float* as2  = (const float*)d_in[19];
    const float* ad2  = (const float*)d_in[20];
    const float* ag2  = (const float*)d_in[21];
    float* out = (float*)d_out;

    k_pre<<<PRE_TOT, 256>>>(ei, ntp, etp, W1, as1, ad1, We1, ag1, ete1,
                            W2, as2, ad2, We2, ag2, ete2, res1);
    k_scan<<<1, 1024>>>();
    k_mid<<<MID_TOT, 256>>>(ea, x, nte1);
    k_attn1<<<Nn / 4, 128>>>(ea, x);

    float* h1;  cudaGetSymbolAddress((void**)&h1, d_h1);
    float* v1;  cudaGetSymbolAddress((void**)&v1, d_v1);
    float* w1h; cudaGetSymbolAddress((void**)&w1h, d_W1h);
    float* v2;  cudaGetSymbolAddress((void**)&v2, d_v2);
    float* w2c; cudaGetSymbolAddress((void**)&w2c, d_W2cat);
    dim3 g((Nn + 127) / 128, 4);
    k_gemmTF<K1H, 1><<<g, 256>>>(v1, w1h, b1, nullptr, h1);
    k_ns2<<<(Nn * 32 + 255) / 256, 256>>>(nte2);
    k_attn2<<<Nn / 4, 128>>>(ea);
    k_gemmTF<K2P, 2><<<g, 256>>>(v2, w2c, b2, h1, out);
}

// round 17
// speedup vs baseline: 1.7824x; 1.0120x over previous
#include <cuda_runtime.h>
#include <math.h>

#define Nn 10000
#define Ee 320000
#define K1H 216          // per-head K for layer-1 GEMM
#define LDA1 (4 * K1H)   // 864
#define K2P 1376

// ---------------- static scratch ----------------
__device__ int   d_src[Ee], d_dst[Ee], d_et[Ee], d_nt[Nn];
__device__ int   d_deg[Nn], d_off[Nn + 1], d_cur[Nn];
__device__ int   d_eid[Ee], d_srcS[Ee], d_etS[Ee];
__device__ float d_se1[Ee * 4], d_se2[Ee * 4];
__device__ float d_ssrc[Nn * 4], d_sdst[Nn * 4];
__device__ float d_ssrc2[Nn * 4], d_sdst2[Nn * 4];
__device__ float d_u1[Nn * 64], d_u2[Nn * 256], d_h1[Nn * 256];
__device__ float d_v1[(size_t)Nn * LDA1], d_v2[(size_t)Nn * K2P];
__device__ float d_wsrc1[256], d_wdst1[256], d_wae1[256], d_etd1[22 * 4];
__device__ float d_wsrc2[1024], d_wdst2[1024], d_wae2[256], d_etd2[22 * 4];
__device__ float d_W1h[4 * K1H * 64], d_W2cat[K2P * 256];

typedef unsigned long long ull;

__device__ __forceinline__ float lrelu(float v) { return v > 0.f ? v : 0.2f * v; }
__device__ __forceinline__ int ldidx(const void* p, long long i, int is64) {
    return is64 ? (int)((const long long*)p)[i] : ((const int*)p)[i];
}
__device__ __forceinline__ ull dup2(float x) {
    ull r;
    asm("mov.b64 %0, {%1, %1};" : "=l"(r) : "r"(__float_as_uint(x)));
    return r;
}
__device__ __forceinline__ void fma2(ull& d, ull a, ull b) {
    asm("fma.rn.f32x2 %0, %1, %2, %0;" : "+l"(d) : "l"(a), "l"(b));
}
__device__ __forceinline__ unsigned to_tf32(float x) {
    unsigned r;
    asm("cvt.rna.tf32.f32 %0, %1;" : "=r"(r) : "f"(x));
    return r;
}
__device__ __forceinline__ float4 logit4(float4 ss, float4 sd, float4 se) {
    float4 l;
    l.x = lrelu(ss.x + sd.x + se.x); l.y = lrelu(ss.y + sd.y + se.y);
    l.z = lrelu(ss.z + sd.z + se.z); l.w = lrelu(ss.w + sd.w + se.w);
    return l;
}
__device__ __forceinline__ float4 warpMax4(float4 v) {
#pragma unroll
    for (int o = 16; o > 0; o >>= 1) {
        v.x = fmaxf(v.x, __shfl_xor_sync(0xffffffffu, v.x, o));
        v.y = fmaxf(v.y, __shfl_xor_sync(0xffffffffu, v.y, o));
        v.z = fmaxf(v.z, __shfl_xor_sync(0xffffffffu, v.z, o));
        v.w = fmaxf(v.w, __shfl_xor_sync(0xffffffffu, v.w, o));
    }
    return v;
}
__device__ __forceinline__ float4 warpSum4(float4 v) {
#pragma unroll
    for (int o = 16; o > 0; o >>= 1) {
        v.x += __shfl_xor_sync(0xffffffffu, v.x, o);
        v.y += __shfl_xor_sync(0xffffffffu, v.y, o);
        v.z += __shfl_xor_sync(0xffffffffu, v.z, o);
        v.w += __shfl_xor_sync(0xffffffffu, v.w, o);
    }
    return v;
}
__device__ __forceinline__ int block_is64(const unsigned int* w) {
    int t = threadIdx.x;
    int bad = 0;
    if (t < 128) bad = (w[2 * (t * 39) + 1] != 0u);
    return __syncthreads_or(bad) ? 0 : 1;
}
__device__ __forceinline__ float wdot(const float* A, const float* B, int len, int lane) {
    float s = 0.f;
    for (int c = lane; c < len; c += 32) s += A[c] * B[c];
#pragma unroll
    for (int o = 16; o > 0; o >>= 1) s += __shfl_xor_sync(0xffffffffu, s, o);
    return s;
}
__device__ __forceinline__ float dot8(float4 a0, float4 a1, float4 b0, float4 b1) {
    return a0.x * b0.x + a0.y * b0.y + a0.z * b0.z + a0.w * b0.w +
           a1.x * b1.x + a1.y * b1.y + a1.z * b1.z + a1.w * b1.w;
}

// ---------------- K1: fused preprocessing ----------------
#define PRE_CONV 1250
#define PRE_PW1  (PRE_CONV + 216)
#define PRE_PW2  (PRE_PW1 + 1376)
#define PRE_TOT  (PRE_PW2 + 406)

__global__ void k_pre(const void* ei, const void* ntp, const void* etp,
                      const float* W1, const float* as1, const float* ad1,
                      const float* We1, const float* ag1, const float* etb1,
                      const float* W2, const float* as2, const float* ad2,
                      const float* We2, const float* ag2, const float* etb2,
                      const float* res1) {
    int b = blockIdx.x, t = threadIdx.x;
    if (b < PRE_CONV) {
        int is64 = block_is64((const unsigned int*)ntp);
        int e = b * 256 + t;
        if (e < Ee) {
            int s = ldidx(ei, e, is64);
            int d2 = ldidx(ei, (long long)Ee + e, is64);
            d_src[e] = s; d_dst[e] = d2; d_et[e] = ldidx(etp, e, is64);
            atomicAdd(&d_deg[d2], 1);
        }
        if (b < 40) { int i = b * 256 + t; if (i < Nn) d_nt[i] = ldidx(ntp, i, is64); }
    } else if (b < PRE_PW1) {
        int j = (b - PRE_CONV) * 256 + t;
        int c = j & 63, hk = j >> 6, h = hk / K1H, k = hk - h * K1H;
        float v = 0.f;
        if (k < 64) v = W1[k * 256 + h * 64 + c];
        else if (k < 128) v = We1[(k - 64) * 256 + h * 64 + c];
        else if (k < 150) v = etb1[(k - 128) * 256 + h * 64 + c];
        else if (k < 214) v = res1[(k - 150) * 256 + h * 64 + c];
        d_W1h[j] = v;
    } else if (b < PRE_PW2) {
        int j = (b - PRE_PW1) * 256 + t;
        int col = j & 255, r = j >> 8;
        float v = 0.f;
        if (r < 1024) { int h = r >> 8, k = r & 255; v = W2[k * 1024 + h * 256 + col] * 0.25f; }
        else if (r < 1280) { int rr = r - 1024, h = rr >> 6, k = rr & 63; v = We2[k * 1024 + h * 256 + col] * 0.25f; }
        else if (r < 1368) { int rr = r - 1280, h = rr / 22, tt = rr % 22; v = etb2[tt * 1024 + h * 256 + col] * 0.25f; }
        d_W2cat[j] = v;
    } else {
        int wo = (b - PRE_PW2) * 8 + (t >> 5);
        int lane = t & 31;
        if (wo < 3248) {
            float s = 0.f;
            float* dst = nullptr;
            if (wo < 256) {
                int h = wo >> 6, k = wo & 63;
                s = wdot(W1 + k * 256 + h * 64, as1 + h * 64, 64, lane);
                dst = &d_wsrc1[wo];
            } else if (wo < 512) {
                int jj = wo - 256, h = jj >> 6, k = jj & 63;
                s = wdot(W1 + k * 256 + h * 64, ad1 + h * 64, 64, lane);
                dst = &d_wdst1[jj];
            } else if (wo < 768) {
                int jj = wo - 512, h = jj >> 6, k = jj & 63;
                s = wdot(We1 + k * 256 + h * 64, ag1 + h * 64, 64, lane);
                dst = &d_wae1[jj];
            } else if (wo < 856) {
                int jj = wo - 768, tt = jj >> 2, h = jj & 3;
                s = wdot(etb1 + tt * 256 + h * 64, ag1 + h * 64, 64, lane);
                dst = &d_etd1[jj];
            } else if (wo < 1880) {
                int jj = wo - 856, h = jj >> 8, k = jj & 255;
                s = wdot(W2 + k * 1024 + h * 256, as2 + h * 256, 256, lane);
                dst = &d_wsrc2[jj];
            } else if (wo < 2904) {
                int jj = wo - 1880, h = jj >> 8, k = jj & 255;
                s = wdot(W2 + k * 1024 + h * 256, ad2 + h * 256, 256, lane);
                dst = &d_wdst2[jj];
            } else if (wo < 3160) {
                int jj = wo - 2904, h = jj >> 6, k = jj & 63;
                s = wdot(We2 + k * 1024 + h * 256, ag2 + h * 256, 256, lane);
                dst = &d_wae2[jj];
            } else {
                int jj = wo - 3160, tt = jj >> 2, h = jj & 3;
                s = wdot(etb2 + tt * 1024 + h * 256, ag2 + h * 256, 256, lane);
                dst = &d_etd2[jj];
            }
            if (lane == 0) *dst = s;
        }
    }
}

// ---------------- K2: scan (+ zero d_deg for replay) ----------------
__global__ void k_scan() {
    __shared__ int wsum[32];
    int t = threadIdx.x, base = t * 10, loc[10], sum = 0;
#pragma unroll
    for (int ii = 0; ii < 10; ii++) {
        int i = base + ii;
        int d = (i < Nn) ? d_deg[i] : 0;
        loc[ii] = d; sum += d;
    }
    int lane = t & 31, w = t >> 5;
    int v = sum;
#pragma unroll
    for (int o = 1; o < 32; o <<= 1) {
        int u = __shfl_up_sync(0xffffffffu, v, o);
        if (lane >= o) v += u;
    }
    if (lane == 31) wsum[w] = v;
    __syncthreads();
    if (w == 0) {
        int s = wsum[lane];
#pragma unroll
        for (int o = 1; o < 32; o <<= 1) {
            int u = __shfl_up_sync(0xffffffffu, s, o);
            if (lane >= o) s += u;
        }
        wsum[lane] = s;
    }
    __syncthreads();
    int run = v - sum + (w ? wsum[w - 1] : 0);
#pragma unroll
    for (int ii = 0; ii < 10; ii++) {
        int i = base + ii;
        if (i < Nn) { d_off[i] = run; d_cur[i] = run; d_deg[i] = 0; run += loc[ii]; }
        else if (i == Nn) d_off[Nn] = run;
    }
}

// ---------------- nscore body (layer 1 only) ----------------
__device__ __forceinline__ void nscore_one(int gw, int lane, const float* xin,
                                           const float* ntemb, int K,
                                           const float* ws, const float* wd, float* u) {
    int nt = d_nt[gw];
    float ps[4] = {0, 0, 0, 0}, pd[4] = {0, 0, 0, 0};
    for (int k = lane; k < K; k += 32) {
        float v = xin[gw * K + k] + ntemb[nt * K + k];
        u[gw * K + k] = v;
#pragma unroll
        for (int h = 0; h < 4; h++) { ps[h] += v * ws[h * K + k]; pd[h] += v * wd[h * K + k]; }
    }
#pragma unroll
    for (int h = 0; h < 4; h++)
        for (int o = 16; o > 0; o >>= 1) {
            ps[h] += __shfl_xor_sync(0xffffffffu, ps[h], o);
            pd[h] += __shfl_xor_sync(0xffffffffu, pd[h], o);
        }
    if (lane == 0)
#pragma unroll
        for (int h = 0; h < 4; h++) { d_ssrc[gw * 4 + h] = ps[h]; d_sdst[gw * 4 + h] = pd[h]; }
}

// ---------------- K3: scatter + nscore1 + edgescore + zero ssrc2 -------------
#define MID_SCAT 1250
#define MID_NS   (MID_SCAT + 1250)
#define MID_EDG  (MID_NS + 10000)
#define MID_TOT  (MID_EDG + 157)

__global__ void k_mid(const float* __restrict__ ea, const float* __restrict__ x,
                      const float* __restrict__ nte1) {
    int b = blockIdx.x, t = threadIdx.x;
    if (b < MID_SCAT) {
        int e = b * 256 + t;
        if (e < Ee) {
            int p = atomicAdd(&d_cur[d_dst[e]], 1);
            d_eid[p] = e; d_srcS[p] = d_src[e]; d_etS[p] = d_et[e];
        }
    } else if (b < MID_NS) {
        int gw = (b - MID_SCAT) * 8 + (t >> 5);
        if (gw < Nn) nscore_one(gw, t & 31, x, nte1, 64, d_wsrc1, d_wdst1, d_u1);
    } else if (b < MID_EDG) {
        int lane = t & 31;
        int sub = lane & 7;
        int e = (b - MID_NS) * 32 + (t >> 3);
        const float4* row = (const float4*)&ea[(size_t)e * 64 + sub * 8];
        float4 r0 = row[0], r1 = row[1];
        float dd[8];
#pragma unroll
        for (int h = 0; h < 4; h++) {
            const float4* w1p = (const float4*)&d_wae1[h * 64 + sub * 8];
            dd[h] = dot8(r0, r1, w1p[0], w1p[1]);
            const float4* w2p = (const float4*)&d_wae2[h * 64 + sub * 8];
            dd[4 + h] = dot8(r0, r1, w2p[0], w2p[1]);
        }
#pragma unroll
        for (int o = 4; o >= 1; o >>= 1)
#pragma unroll
            for (int i = 0; i < 8; i++)
                dd[i] += __shfl_xor_sync(0xffffffffu, dd[i], o);
        int et = d_et[e];
        if (sub < 4) d_se1[e * 4 + sub] = dd[sub] + d_etd1[et * 4 + sub];
        else d_se2[e * 4 + (sub - 4)] = dd[sub] + d_etd2[et * 4 + (sub - 4)];
    } else {
        int idx = (b - MID_EDG) * 256 + t;
        if (idx < Nn * 4) { d_ssrc2[idx] = 0.f; d_sdst2[idx] = 0.f; }
    }
}

// ---- warp softmax stats (parameterized node-score buffers) ----
__device__ __forceinline__ void warp_softmax(const float4* ssrc4, const float4* se4,
                                             int beg, int end, int lane, float4 sd,
                                             float4& m, float4& rdn) {
    float4 mx = make_float4(-1e30f, -1e30f, -1e30f, -1e30f);
    for (int i = beg + lane; i < end; i += 32) {
        float4 l = logit4(ssrc4[d_srcS[i]], sd, se4[d_eid[i]]);
        mx.x = fmaxf(mx.x, l.x); mx.y = fmaxf(mx.y, l.y);
        mx.z = fmaxf(mx.z, l.z); mx.w = fmaxf(mx.w, l.w);
    }
    m = warpMax4(mx);
    float4 sm = make_float4(0, 0, 0, 0);
    for (int i = beg + lane; i < end; i += 32) {
        float4 l = logit4(ssrc4[d_srcS[i]], sd, se4[d_eid[i]]);
        sm.x += __expf(l.x - m.x); sm.y += __expf(l.y - m.y);
        sm.z += __expf(l.z - m.z); sm.w += __expf(l.w - m.w);
    }
    float4 den = warpSum4(sm);
    rdn.x = 1.f / (den.x + 1e-16f); rdn.y = 1.f / (den.y + 1e-16f);
    rdn.z = 1.f / (den.z + 1e-16f); rdn.w = 1.f / (den.w + 1e-16f);
}

// ---------------- K4: warp-per-node layer-1 attention ----------------
__global__ void k_attn1(const float* __restrict__ ea, const float* __restrict__ x) {
    int wid = threadIdx.x >> 5, lane = threadIdx.x & 31;
    int n = blockIdx.x * 4 + wid;
    __shared__ ull  aSh[4][32][4];
    __shared__ int2 iSh[4][32];
    __shared__ float acctSh[4][88];
    for (int i = lane; i < 88; i += 32) acctSh[wid][i] = 0.f;
    __syncwarp();
    int beg = d_off[n], end = d_off[n + 1], nE = end - beg;
    ull ax[4] = {0, 0, 0, 0}, av[4] = {0, 0, 0, 0};
    if (nE > 0) {
        const float4* ssrc4 = (const float4*)d_ssrc;
        const float4* se4 = (const float4*)d_se1;
        float4 sd = ((const float4*)d_sdst)[n];
        float4 m, rdn;
        warp_softmax(ssrc4, se4, beg, end, lane, sd, m, rdn);
        for (int c0 = beg; c0 < end; c0 += 32) {
            int nc = min(32, end - c0);
            if (lane < nc) {
                int i = c0 + lane;
                int s = d_srcS[i], e = d_eid[i], et = d_etS[i];
                float4 l = logit4(ssrc4[s], sd, se4[e]);
                float a0 = __expf(l.x - m.x) * rdn.x, a1 = __expf(l.y - m.y) * rdn.y;
                float a2 = __expf(l.z - m.z) * rdn.z, a3 = __expf(l.w - m.w) * rdn.w;
                aSh[wid][lane][0] = dup2(a0); aSh[wid][lane][1] = dup2(a1);
                aSh[wid][lane][2] = dup2(a2); aSh[wid][lane][3] = dup2(a3);
                iSh[wid][lane] = make_int2(s, e);
                atomicAdd(&acctSh[wid][et], a0);
                atomicAdd(&acctSh[wid][22 + et], a1);
                atomicAdd(&acctSh[wid][44 + et], a2);
                atomicAdd(&acctSh[wid][66 + et], a3);
            }
            __syncwarp();
#pragma unroll 4
            for (int j = 0; j < nc; j++) {
                ull b0 = aSh[wid][j][0], b1 = aSh[wid][j][1];
                ull b2 = aSh[wid][j][2], b3 = aSh[wid][j][3];
                int2 se = iSh[wid][j];
                ull u = *(const ull*)&d_u1[se.x * 64 + lane * 2];
                ull a = *(const ull*)&ea[(size_t)se.y * 64 + lane * 2];
                fma2(ax[0], u, b0); fma2(ax[1], u, b1);
                fma2(ax[2], u, b2); fma2(ax[3], u, b3);
                fma2(av[0], a, b0); fma2(av[1], a, b1);
                fma2(av[2], a, b2); fma2(av[3], a, b3);
            }
            __syncwarp();
        }
    }
    __syncwarp();
    float* v = &d_v1[(size_t)n * LDA1];
    int c = lane * 2;
#pragma unroll
    for (int h = 0; h < 4; h++) {
        *(ull*)&v[h * K1H + c] = ax[h];
        *(ull*)&v[h * K1H + 64 + c] = av[h];
        *(ull*)&v[h * K1H + 150 + c] = *(const ull*)&x[n * 64 + c];
    }
    for (int i = lane; i < 88; i += 32) {
        int hh = i / 22, t2 = i % 22;
        v[hh * K1H + 128 + t2] = acctSh[wid][hh * 22 + t2];
    }
    if (lane < 8) v[(lane >> 1) * K1H + 214 + (lane & 1)] = 0.f;
}

// ---------------- K6: layer-2 attention (prefetch, 4 warps/blk) --------------
__global__ void k_attn2(const float* __restrict__ ea) {
    int wid = threadIdx.x >> 5, lane = threadIdx.x & 31;
    int n = blockIdx.x * 4 + wid;
    __shared__ ull  aSh[4][32][4];
    __shared__ int2 iSh[4][32];
    __shared__ float acctSh[4][88];
    for (int i = lane; i < 88; i += 32) acctSh[wid][i] = 0.f;
    __syncwarp();
    int beg = d_off[n], end = d_off[n + 1], nE = end - beg;
    ull axu[4][4];
#pragma unroll
    for (int h = 0; h < 4; h++)
#pragma unroll
        for (int q = 0; q < 4; q++) axu[h][q] = 0ull;
    ull av[4] = {0, 0, 0, 0};
    if (nE > 0) {
        const float4* ssrc4 = (const float4*)d_ssrc2;
        const float4* se4 = (const float4*)d_se2;
        float4 sd = ((const float4*)d_sdst2)[n];
        float4 m, rdn;
        warp_softmax(ssrc4, se4, beg, end, lane, sd, m, rdn);
        for (int c0 = beg; c0 < end; c0 += 32) {
            int nc = min(32, end - c0);
            if (lane < nc) {
                int i = c0 + lane;
                int s = d_srcS[i], e = d_eid[i], et = d_etS[i];
                float4 l = logit4(ssrc4[s], sd, se4[e]);
                float a0 = __expf(l.x - m.x) * rdn.x, a1 = __expf(l.y - m.y) * rdn.y;
                float a2 = __expf(l.z - m.z) * rdn.z, a3 = __expf(l.w - m.w) * rdn.w;
                aSh[wid][lane][0] = dup2(a0); aSh[wid][lane][1] = dup2(a1);
                aSh[wid][lane][2] = dup2(a2); aSh[wid][lane][3] = dup2(a3);
                iSh[wid][lane] = make_int2(s, e);
                atomicAdd(&acctSh[wid][et], a0);
                atomicAdd(&acctSh[wid][22 + et], a1);
                atomicAdd(&acctSh[wid][44 + et], a2);
                atomicAdd(&acctSh[wid][66 + et], a3);
            }
            __syncwarp();
            int2 seC = iSh[wid][0];
            const float4* upC = (const float4*)&d_u2[seC.x * 256 + lane * 8];
            float4 u0 = upC[0], u1 = upC[1];
            ull aC = *(const ull*)&ea[(size_t)seC.y * 64 + lane * 2];
#pragma unroll 2
            for (int j = 0; j < nc; j++) {
                float4 n0 = make_float4(0, 0, 0, 0), n1 = make_float4(0, 0, 0, 0);
                ull aN = 0;
                if (j + 1 < nc) {
                    int2 seN = iSh[wid][j + 1];
                    const float4* upN = (const float4*)&d_u2[seN.x * 256 + lane * 8];
                    n0 = upN[0]; n1 = upN[1];
                    aN = *(const ull*)&ea[(size_t)seN.y * 64 + lane * 2];
                }
                ull b0 = aSh[wid][j][0], b1 = aSh[wid][j][1];
                ull b2 = aSh[wid][j][2], b3 = aSh[wid][j][3];
                ull p0 = *(ull*)&u0.x, p1 = *(ull*)&u0.z;
                ull p2 = *(ull*)&u1.x, p3 = *(ull*)&u1.z;
                fma2(axu[0][0], p0, b0); fma2(axu[0][1], p1, b0);
                fma2(axu[0][2], p2, b0); fma2(axu[0][3], p3, b0);
                fma2(axu[1][0], p0, b1); fma2(axu[1][1], p1, b1);
                fma2(axu[1][2], p2, b1); fma2(axu[1][3], p3, b1);
                fma2(axu[2][0], p0, b2); fma2(axu[2][1], p1, b2);
                fma2(axu[2][2], p2, b2); fma2(axu[2][3], p3, b2);
                fma2(axu[3][0], p0, b3); fma2(axu[3][1], p1, b3);
                fma2(axu[3][2], p2, b3); fma2(axu[3][3], p3, b3);
                fma2(av[0], aC, b0); fma2(av[1], aC, b1);
                fma2(av[2], aC, b2); fma2(av[3], aC, b3);
                u0 = n0; u1 = n1; aC = aN;
            }
            __syncwarp();
        }
    }
    __syncwarp();
    float* v = &d_v2[(size_t)n * K2P];
#pragma unroll
    for (int h = 0; h < 4; h++) {
#pragma unroll
        for (int q = 0; q < 4; q++)
            *(ull*)&v[h * 256 + lane * 8 + q * 2] = axu[h][q];
        *(ull*)&v[1024 + h * 64 + lane * 2] = av[h];
    }
    for (int i = lane; i < 96; i += 32)
        v[1280 + i] = (i < 88) ? acctSh[wid][i] : 0.f;
}

// ---------------- tf32 mma.sync GEMM ----------------
// MODE 1: layer-1 finalize + fused u2-write + layer-2 node-score partial dots
//         (aux = nte2)
// MODE 2: layer-2 finalize (aux = add term h1)
template <int K, int MODE>
__global__ void k_gemmTF(const float* __restrict__ A, const float* __restrict__ B,
                         const float* __restrict__ bias, const float* __restrict__ aux,
                         float* __restrict__ C) {
    constexpr int LDA = (MODE == 1) ? LDA1 : K2P;
    __shared__ unsigned As[8][136];
    __shared__ unsigned Bs[8][72];
    __shared__ float wsS[4][64], wdS[4][64], ntS[8][64];
    int y = blockIdx.y;
    int bm = blockIdx.x * 128;
    int colbase = y * 64;
    const float* Ab = A + ((MODE == 1) ? y * K1H : 0);
    const float* Bb = (MODE == 1) ? (B + y * K1H * 64) : (B + colbase);
    const int ldb = (MODE == 1) ? 64 : 256;
    int tid = threadIdx.x;
    int warp = tid >> 5, lane = tid & 31;
    int g = lane >> 2, tig = lane & 3;
    int lrow = tid & 127, lk = (tid >> 7) * 4;
    int brow = tid >> 4, bcol = (tid & 15) * 4;
    int row = bm + lrow;
    float acc[8][4];
#pragma unroll
    for (int nt = 0; nt < 8; nt++)
#pragma unroll
        for (int j = 0; j < 4; j++) acc[nt][j] = 0.f;

    if (MODE == 1) {  // stage score weights + nte2 slices for this col block
        if (tid < 256) {
            int h = tid >> 6, c = tid & 63;
            wsS[h][c] = d_wsrc2[h * 256 + colbase + c];
            wdS[h][c] = d_wdst2[h * 256 + colbase + c];
        }
        for (int i = tid; i < 512; i += blockDim.x) {
            int ty2 = i >> 6, c = i & 63;
            ntS[ty2][c] = aux[ty2 * 256 + colbase + c];
        }
    }

    for (int k0 = 0; k0 < K; k0 += 8) {
        float4 avv = make_float4(0, 0, 0, 0);
        if (row < Nn) avv = *(const float4*)&Ab[(size_t)row * LDA + k0 + lk];
        As[lk + 0][lrow] = to_tf32(avv.x);
        As[lk + 1][lrow] = to_tf32(avv.y);
        As[lk + 2][lrow] = to_tf32(avv.z);
        As[lk + 3][lrow] = to_tf32(avv.w);
        if (tid < 128) {
            float4 bv = *(const float4*)&Bb[(size_t)(k0 + brow) * ldb + bcol];
            Bs[brow][bcol + 0] = to_tf32(bv.x);
            Bs[brow][bcol + 1] = to_tf32(bv.y);
            Bs[brow][bcol + 2] = to_tf32(bv.z);
            Bs[brow][bcol + 3] = to_tf32(bv.w);
        }
        __syncthreads();
        unsigned a0 = As[tig][warp * 16 + g];
        unsigned a1 = As[tig][warp * 16 + g + 8];
        unsigned a2 = As[tig + 4][warp * 16 + g];
        unsigned a3 = As[tig + 4][warp * 16 + g + 8];
#pragma unroll
        for (int nt = 0; nt < 8; nt++) {
            unsigned b0 = Bs[tig][nt * 8 + g];
            unsigned b1 = Bs[tig + 4][nt * 8 + g];
            asm volatile(
                "mma.sync.aligned.m16n8k8.row.col.f32.tf32.tf32.f32 "
                "{%0,%1,%2,%3}, {%4,%5,%6,%7}, {%8,%9}, {%0,%1,%2,%3};"
                : "+f"(acc[nt][0]), "+f"(acc[nt][1]), "+f"(acc[nt][2]), "+f"(acc[nt][3])
                : "r"(a0), "r"(a1), "r"(a2), "r"(a3), "r"(b0), "r"(b1));
        }
        __syncthreads();
    }
    if (MODE == 2) {
#pragma unroll
        for (int nt = 0; nt < 8; nt++) {
            int r0 = bm + warp * 16 + g, r1 = r0 + 8;
            int cA = colbase + nt * 8 + 2 * tig, cB = cA + 1;
            float bA = bias[cA], bB = bias[cB];
            if (r0 < Nn) {
                C[r0 * 256 + cA] = acc[nt][0] + bA + aux[r0 * 256 + cA];
                C[r0 * 256 + cB] = acc[nt][1] + bB + aux[r0 * 256 + cB];
            }
            if (r1 < Nn) {
                C[r1 * 256 + cA] = acc[nt][2] + bA + aux[r1 * 256 + cA];
                C[r1 * 256 + cB] = acc[nt][3] + bB + aux[r1 * 256 + cB];
            }
        }
    } else {
        // relu + h1 store + u2 store + layer-2 node-score partial dots
#pragma unroll
        for (int rI = 0; rI < 2; rI++) {
            int r = bm + warp * 16 + g + rI * 8;
            if (r >= Nn) continue;
            int ntp = d_nt[r];
            float ps0 = 0, ps1 = 0, ps2 = 0, ps3 = 0;
            float pd0 = 0, pd1 = 0, pd2 = 0, pd3 = 0;
#pragma unroll
            for (int nt = 0; nt < 8; nt++) {
                int lcA = nt * 8 + 2 * tig, lcB = lcA + 1;
                int cA = colbase + lcA, cB = cA + 1;
                float vA = fmaxf(acc[nt][rI * 2 + 0] + bias[cA], 0.f);
                float vB = fmaxf(acc[nt][rI * 2 + 1] + bias[cB], 0.f);
                C[r * 256 + cA] = vA;
                C[r * 256 + cB] = vB;
                float uA = vA + ntS[ntp][lcA];
                float uB = vB + ntS[ntp][lcB];
                d_u2[r * 256 + cA] = uA;
                d_u2[r * 256 + cB] = uB;
                ps0 += uA * wsS[0][lcA] + uB * wsS[0][lcB];
                ps1 += uA * wsS[1][lcA] + uB * wsS[1][lcB];
                ps2 += uA * wsS[2][lcA] + uB * wsS[2][lcB];
                ps3 += uA * wsS[3][lcA] + uB * wsS[3][lcB];
                pd0 += uA * wdS[0][lcA] + uB * wdS[0][lcB];
                pd1 += uA * wdS[1][lcA] + uB * wdS[1][lcB];
                pd2 += uA * wdS[2][lcA] + uB * wdS[2][lcB];
                pd3 += uA * wdS[3][lcA] + uB * wdS[3][lcB];
            }
#pragma unroll
            for (int o = 1; o <= 2; o <<= 1) {
                ps0 += __shfl_xor_sync(0xffffffffu, ps0, o);
                ps1 += __shfl_xor_sync(0xffffffffu, ps1, o);
                ps2 += __shfl_xor_sync(0xffffffffu, ps2, o);
                ps3 += __shfl_xor_sync(0xffffffffu, ps3, o);
                pd0 += __shfl_xor_sync(0xffffffffu, pd0, o);
                pd1 += __shfl_xor_sync(0xffffffffu, pd1, o);
                pd2 += __shfl_xor_sync(0xffffffffu, pd2, o);
                pd3 += __shfl_xor_sync(0xffffffffu, pd3, o);
            }
            if (tig == 0) {
                atomicAdd(&d_ssrc2[r * 4 + 0], ps0);
                atomicAdd(&d_ssrc2[r * 4 + 1], ps1);
                atomicAdd(&d_ssrc2[r * 4 + 2], ps2);
                atomicAdd(&d_ssrc2[r * 4 + 3], ps3);
                atomicAdd(&d_sdst2[r * 4 + 0], pd0);
                atomicAdd(&d_sdst2[r * 4 + 1], pd1);
                atomicAdd(&d_sdst2[r * 4 + 2], pd2);
                atomicAdd(&d_sdst2[r * 4 + 3], pd3);
            }
        }
    }
}

// ---------------- launch ----------------
extern "C" void kernel_launch(void* const* d_in, const int* in_sizes, int n_in,
                              void* d_out, int out_size) {
    const float* x    = (const float*)d_in[0];
    const void*  ei   = d_in[1];
    const void*  ntp  = d_in[2];
    const float* ea   = (const float*)d_in[3];
    const void*  etp  = d_in[4];
    const float* W1   = (const float*)d_in[5];
    const float* b1   = (const float*)d_in[6];
    const float* We1  = (const float*)d_in[7];
    const float* nte1 = (const float*)d_in[8];
    const float* ete1 = (const float*)d_in[9];
    const float* as1  = (const float*)d_in[10];
    const float* ad1  = (const float*)d_in[11];
    const float* ag1  = (const float*)d_in[12];
    const float* res1 = (const float*)d_in[13];
    const float* W2   = (const float*)d_in[14];
    const float* b2   = (const float*)d_in[15];
    const float* We2  = (const float*)d_in[16];
    const float* nte2 = (const float*)d_in[17];
    const float* ete2 = (const float*)d_in[18];
    const float* as2  = (const float*)d_in[19];
    const float* ad2  = (const float*)d_in[20];
    const float* ag2  = (const float*)d_in[21];
    float* out = (float*)d_out;

    k_pre<<<PRE_TOT, 256>>>(ei, ntp, etp, W1, as1, ad1, We1, ag1, ete1,
                            W2, as2, ad2, We2, ag2, ete2, res1);
    k_scan<<<1, 1024>>>();
    k_mid<<<MID_TOT, 256>>>(ea, x, nte1);
    k_attn1<<<Nn / 4, 128>>>(ea, x);

    float* h1;  cudaGetSymbolAddress((void**)&h1, d_h1);
    float* v1;  cudaGetSymbolAddress((void**)&v1, d_v1);
    float* w1h; cudaGetSymbolAddress((void**)&w1h, d_W1h);
    float* v2;  cudaGetSymbolAddress((void**)&v2, d_v2);
    float* w2c; cudaGetSymbolAddress((void**)&w2c, d_W2cat);
    dim3 g((Nn + 127) / 128, 4);
    k_gemmTF<K1H, 1><<<g, 256>>>(v1, w1h, b1, nte2, h1);
    k_attn2<<<Nn / 4, 128>>>(ea);
    k_gemmTF<K2P, 2><<<g, 256>>>(v2, w2c, b2, h1, out);
}